// round 1
// baseline (speedup 1.0000x reference)
#include <cuda_runtime.h>
#include <math.h>

#define BB 64
#define NN 64
#define HH 128
#define EFD 32
#define DIRD 256
#define LN_EPS 1e-5f
#define CUT 10.0f
#define RBFG 10.0f

// ---------------- device scratch (no runtime allocation) ----------------
static __device__ float g_mask[BB*NN*NN*HH];   // 128 MB
static __device__ float g_ea  [BB*NN*NN];
static __device__ float g_ev  [BB*NN*NN*3];
static __device__ float g_s   [BB*NN*HH];
static __device__ float g_sn  [BB*NN*HH];
static __device__ float g_t   [BB*NN*HH];
static __device__ float g_v   [BB*NN*3*HH];
static __device__ float g_vq  [BB*NN*3*HH];
static __device__ float g_vk  [BB*NN*3*HH];
static __device__ float g_sl  [BB*NN*HH];

__device__ __forceinline__ float silu_f(float x){
    return x * (1.0f / (1.0f + __expf(-x)));
}

// block reduction for 128 threads (4 warps)
__device__ __forceinline__ float blkred128(float v, volatile float* red){
    #pragma unroll
    for (int o = 16; o > 0; o >>= 1) v += __shfl_xor_sync(0xffffffffu, v, o);
    if ((threadIdx.x & 31) == 0) red[threadIdx.x >> 5] = v;
    __syncthreads();
    v = red[0] + red[1] + red[2] + red[3];
    __syncthreads();
    return v;
}

// ---------------- K1: geometry + RBF filter mask ----------------
// grid = B*N (one block per (b,i)), 128 threads
__global__ void k_geom(const int* __restrict__ z, const float* __restrict__ pos,
                       const float* __restrict__ Wef, const float* __restrict__ bef){
    int blk = blockIdx.x;
    int b = blk >> 6, i = blk & 63;
    int t = threadIdx.x;

    __shared__ float pos_s[NN][3];
    __shared__ int   z_s[NN];
    __shared__ float d_s[NN], ea_s[NN];
    __shared__ float ef_s[NN][EFD];
    __shared__ float Wef_s[EFD*HH];
    __shared__ float bef_s[HH];

    for (int r = t; r < EFD*HH; r += 128) Wef_s[r] = Wef[r];
    bef_s[t] = bef[t];
    if (t < NN){
        z_s[t] = z[b*NN + t];
        pos_s[t][0] = pos[(b*NN + t)*3 + 0];
        pos_s[t][1] = pos[(b*NN + t)*3 + 1];
        pos_s[t][2] = pos[(b*NN + t)*3 + 2];
    }
    __syncthreads();

    if (t < NN){
        int j = t;
        float dx = pos_s[j][0] - pos_s[i][0];
        float dy = pos_s[j][1] - pos_s[i][1];
        float dz = pos_s[j][2] - pos_s[i][2];
        float d2 = dx*dx + dy*dy + dz*dz;
        float d  = sqrtf(fmaxf(d2, 1e-12f));
        d_s[j] = d;
        bool pair = (z_s[i] != 0) && (z_s[j] != 0) && (j != i);
        float ea = (pair && d < CUT) ? 0.5f*(cosf(3.14159265358979323846f * d / CUT) + 1.0f) : 0.0f;
        ea_s[j] = ea;
        g_ea[blk*NN + j] = ea;
        float inv = 1.0f / d;
        float ex = pair ? dx*inv : 0.0f;
        float ey = pair ? dy*inv : 0.0f;
        float ez = pair ? dz*inv : 0.0f;
        g_ev[(blk*NN + j)*3 + 0] = ex;
        g_ev[(blk*NN + j)*3 + 1] = ey;
        g_ev[(blk*NN + j)*3 + 2] = ez;
    }
    __syncthreads();

    const float step = CUT / (float)(EFD - 1);
    for (int r = t; r < NN*EFD; r += 128){
        int j = r >> 5, k = r & 31;
        float dd = d_s[j] - step*(float)k;
        ef_s[j][k] = __expf(-RBFG * dd * dd);
    }
    __syncthreads();

    int h = t;
    for (int j = 0; j < NN; j++){
        float acc = bef_s[h];
        #pragma unroll
        for (int k = 0; k < EFD; k++)
            acc = fmaf(ef_s[j][k], Wef_s[k*HH + h], acc);
        g_mask[(blk*NN + j)*HH + h] = silu_f(acc) * ea_s[j];
    }
}

// ---------------- K2a: s = emb[z];  sn = LN(emb2[z]) ----------------
__global__ void k_embed(const int* __restrict__ z, const float* __restrict__ emb_w,
                        const float* __restrict__ emb2_w){
    int a = blockIdx.x, h = threadIdx.x;
    __shared__ float red[4];
    int zi = z[a];
    g_s[a*HH + h] = emb_w[zi*HH + h];
    float x = emb2_w[zi*HH + h];
    float s1 = blkred128(x, red);
    float s2 = blkred128(x*x, red);
    float m = s1 * (1.0f/HH);
    float var = fmaxf(s2 * (1.0f/HH) - m*m, 0.0f);
    g_sn[a*HH + h] = (x - m) * rsqrtf(var + LN_EPS);
}

// ---------------- K2b / K6b: s += mask @ src  (src = sn or sl) ----------------
__global__ void k_gather(int sel){
    int blk = blockIdx.x;              // (b,i)
    int b = blk >> 6;
    int h = threadIdx.x;
    const float* src = sel ? g_sl : g_sn;
    __shared__ float srcs[NN*HH];      // 32 KB
    const float* sb = src + b*NN*HH;
    for (int r = h; r < NN*HH; r += 128) srcs[r] = sb[r];
    __syncthreads();
    const float* mrow = g_mask + blk*NN*HH;
    float acc = 0.0f;
    #pragma unroll 8
    for (int j = 0; j < NN; j++)
        acc = fmaf(mrow[j*HH + h], srcs[j*HH + h], acc);
    g_s[blk*HH + h] += acc;
}

// ---------------- K3 / K6a: dst = silu(LN(s @ W + bias)) ----------------
__global__ void k_lin(const float* __restrict__ W, const float* __restrict__ bias,
                      int dst_sel){
    int a = blockIdx.x, h = threadIdx.x;
    __shared__ float xs[HH];
    __shared__ float red[4];
    xs[h] = g_s[a*HH + h];
    __syncthreads();
    float acc = bias[h];
    #pragma unroll 8
    for (int k = 0; k < HH; k++)
        acc = fmaf(xs[k], W[k*HH + h], acc);
    float s1 = blkred128(acc, red);
    float s2 = blkred128(acc*acc, red);
    float m = s1 * (1.0f/HH);
    float var = fmaxf(s2 * (1.0f/HH) - m*m, 0.0f);
    float y = (acc - m) * rsqrtf(var + LN_EPS);
    float out = silu_f(y);
    if (dst_sel) g_sl[a*HH + h] = out;
    else         g_t [a*HH + h] = out;
}

// ---------------- K4a: v[i,c,h] = sum_j mask*t*ev ----------------
__global__ void k_v(){
    int blk = blockIdx.x;              // (b,i)
    int b = blk >> 6;
    int h = threadIdx.x;
    __shared__ float ts[NN*HH];        // 32 KB
    __shared__ float evl[NN*3];
    const float* tb = g_t + b*NN*HH;
    for (int r = h; r < NN*HH; r += 128) ts[r] = tb[r];
    for (int r = h; r < NN*3; r += 128) evl[r] = g_ev[blk*NN*3 + r];
    __syncthreads();
    const float* mrow = g_mask + blk*NN*HH;
    float a0 = 0.f, a1 = 0.f, a2 = 0.f;
    #pragma unroll 4
    for (int j = 0; j < NN; j++){
        float m = mrow[j*HH + h] * ts[j*HH + h];
        a0 = fmaf(m, evl[j*3+0], a0);
        a1 = fmaf(m, evl[j*3+1], a1);
        a2 = fmaf(m, evl[j*3+2], a2);
    }
    g_v[(blk*3 + 0)*HH + h] = a0;
    g_v[(blk*3 + 1)*HH + h] = a1;
    g_v[(blk*3 + 2)*HH + h] = a2;
}

// ---------------- K4b: vq = v@Wq, vk = v@Wk ----------------
__global__ void k_vqk(const float* __restrict__ Wq, const float* __restrict__ Wk){
    int r = blockIdx.x;                // (b,i,c)  B*N*3 rows
    int h = threadIdx.x;
    __shared__ float vs[HH];
    vs[h] = g_v[r*HH + h];
    __syncthreads();
    float aq = 0.f, ak = 0.f;
    #pragma unroll 8
    for (int k = 0; k < HH; k++){
        float v = vs[k];
        aq = fmaf(v, Wq[k*HH + h], aq);
        ak = fmaf(v, Wk[k*HH + h], ak);
    }
    g_vq[r*HH + h] = aq;
    g_vk[r*HH + h] = ak;
}

// ---------------- K5: fused directional MLP; mask *= dmask ----------------
// grid = B*N*2, 256 threads. Each block: 32 edges (one i, half of j range).
// smem: A[256][33] (dirf^T, then reused as h1^T), Bt[8*256] weight chunk.
__global__ void __launch_bounds__(256) k_dir(const float* __restrict__ Wd1, const float* __restrict__ bd1,
                                             const float* __restrict__ Wd2, const float* __restrict__ bd2){
    int blk = blockIdx.x;
    int jh = blk & 1;
    int i  = (blk >> 1) & 63;
    int b  = blk >> 7;
    int t  = threadIdx.x;
    int base_i = b*NN + i;
    int j0 = jh * 32;

    __shared__ float A  [DIRD*33];     // 33792 B
    __shared__ float Bt [8*DIRD];      //  8192 B
    __shared__ float vi [3*HH];
    __shared__ float vki[3*HH];
    __shared__ float evl[32*3];
    __shared__ float eal[32];
    __shared__ float b1s[DIRD];
    __shared__ float b2s[HH];

    for (int r = t; r < 3*HH; r += 256){
        vi [r] = g_v [base_i*3*HH + r];
        vki[r] = g_vk[base_i*3*HH + r];
    }
    for (int r = t; r < 32*3; r += 256) evl[r] = g_ev[(base_i*NN + j0)*3 + r];
    if (t < 32) eal[t] = g_ea[base_i*NN + j0 + t];
    b1s[t] = bd1[t];
    if (t < HH) b2s[t] = bd2[t];
    __syncthreads();

    // ---- build dirf^T: A[k][e], k in [0,256), e in [0,32) ----
    {
        int k = t;
        if (k < HH){
            float v0 = vi[0*HH+k], v1 = vi[1*HH+k], v2 = vi[2*HH+k];
            #pragma unroll 4
            for (int e = 0; e < 32; e++){
                float d2v = v0*evl[e*3+0] + v1*evl[e*3+1] + v2*evl[e*3+2];
                A[k*33 + e] = d2v * eal[e];
            }
        } else {
            int kk = k - HH;
            float u0 = vki[0*HH+kk], u1 = vki[1*HH+kk], u2 = vki[2*HH+kk];
            for (int e = 0; e < 32; e++){
                int j = j0 + e;
                const float* vq = g_vq + (b*NN + j)*3*HH + kk;
                float d3v = vq[0]*u0 + vq[HH]*u1 + vq[2*HH]*u2;
                A[k*33 + e] = d3v * eal[e];
            }
        }
    }

    // ---- GEMM1: h1[32x256] = silu(A^T @ Wd1 + bd1) ----
    int oc = t & 63;    // cols oc*4 .. +3
    int eg = t >> 6;    // edges eg*8 .. +7
    float acc[8][4];
    #pragma unroll
    for (int e = 0; e < 8; e++)
        #pragma unroll
        for (int c = 0; c < 4; c++) acc[e][c] = 0.f;

    for (int kc = 0; kc < DIRD/8; kc++){
        __syncthreads();
        #pragma unroll
        for (int r = 0; r < 8; r++) Bt[t + r*256] = Wd1[kc*8*DIRD + t + r*256];
        __syncthreads();
        #pragma unroll
        for (int kk = 0; kk < 8; kk++){
            int krow = kc*8 + kk;
            float4 b4 = *(const float4*)&Bt[kk*DIRD + oc*4];
            const float* arow = &A[krow*33 + eg*8];
            #pragma unroll
            for (int e = 0; e < 8; e++){
                float a = arow[e];
                acc[e][0] = fmaf(a, b4.x, acc[e][0]);
                acc[e][1] = fmaf(a, b4.y, acc[e][1]);
                acc[e][2] = fmaf(a, b4.z, acc[e][2]);
                acc[e][3] = fmaf(a, b4.w, acc[e][3]);
            }
        }
    }
    __syncthreads();
    // write h1^T (with silu) into A buffer
    #pragma unroll
    for (int e = 0; e < 8; e++){
        int ee = eg*8 + e;
        #pragma unroll
        for (int c = 0; c < 4; c++){
            int o = oc*4 + c;
            A[o*33 + ee] = silu_f(acc[e][c] + b1s[o]);
        }
    }

    // ---- GEMM2: dmask[32x128] = silu(h1 @ Wd2 + bd2); mask *= dmask ----
    int oc2 = t & 31;   // cols oc2*4 .. +3
    int eg2 = t >> 5;   // edges eg2*4 .. +3
    float acc2[4][4];
    #pragma unroll
    for (int e = 0; e < 4; e++)
        #pragma unroll
        for (int c = 0; c < 4; c++) acc2[e][c] = 0.f;

    for (int kc = 0; kc < DIRD/8; kc++){
        __syncthreads();
        #pragma unroll
        for (int r = 0; r < 4; r++) Bt[t + r*256] = Wd2[kc*8*HH + t + r*256];
        __syncthreads();
        #pragma unroll
        for (int kk = 0; kk < 8; kk++){
            int krow = kc*8 + kk;
            float4 b4 = *(const float4*)&Bt[kk*HH + oc2*4];
            const float* arow = &A[krow*33 + eg2*4];
            #pragma unroll
            for (int e = 0; e < 4; e++){
                float a = arow[e];
                acc2[e][0] = fmaf(a, b4.x, acc2[e][0]);
                acc2[e][1] = fmaf(a, b4.y, acc2[e][1]);
                acc2[e][2] = fmaf(a, b4.z, acc2[e][2]);
                acc2[e][3] = fmaf(a, b4.w, acc2[e][3]);
            }
        }
    }

    #pragma unroll
    for (int e = 0; e < 4; e++){
        int j = j0 + eg2*4 + e;
        int off = (base_i*NN + j)*HH + oc2*4;
        float4 m = *(const float4*)&g_mask[off];
        m.x *= silu_f(acc2[e][0] + b2s[oc2*4 + 0]);
        m.y *= silu_f(acc2[e][1] + b2s[oc2*4 + 1]);
        m.z *= silu_f(acc2[e][2] + b2s[oc2*4 + 2]);
        m.w *= silu_f(acc2[e][3] + b2s[oc2*4 + 3]);
        *(float4*)&g_mask[off] = m;
    }
}

// ---------------- K7: readout ----------------
__global__ void k_out(const int* __restrict__ z, const float* __restrict__ Wo,
                      const float* __restrict__ bo, float* __restrict__ out){
    int b = blockIdx.x, h = threadIdx.x;
    __shared__ float red[4];
    float acc = 0.f;
    for (int i = 0; i < NN; i++)
        if (z[b*NN + i] != 0) acc += g_s[(b*NN + i)*HH + h];
    float part = acc * Wo[h];
    float tot = blkred128(part, red);
    if (h == 0) out[b] = tot + bo[0];
}

// ---------------- launch ----------------
extern "C" void kernel_launch(void* const* d_in, const int* in_sizes, int n_in,
                              void* d_out, int out_size){
    const int*   z      = (const int*)  d_in[0];
    const float* pos    = (const float*)d_in[1];
    const float* emb_w  = (const float*)d_in[2];
    const float* emb2_w = (const float*)d_in[3];
    const float* Wef    = (const float*)d_in[4];
    const float* bef    = (const float*)d_in[5];
    const float* Ws2v   = (const float*)d_in[6];
    const float* bs2v   = (const float*)d_in[7];
    const float* Wq     = (const float*)d_in[8];
    const float* Wk     = (const float*)d_in[9];
    const float* Wd1    = (const float*)d_in[10];
    const float* bd1    = (const float*)d_in[11];
    const float* Wd2    = (const float*)d_in[12];
    const float* bd2    = (const float*)d_in[13];
    const float* Wint   = (const float*)d_in[14];
    const float* bint   = (const float*)d_in[15];
    const float* Wo     = (const float*)d_in[16];
    const float* bo     = (const float*)d_in[17];
    float* out = (float*)d_out;

    k_geom <<<BB*NN, 128>>>(z, pos, Wef, bef);
    k_embed<<<BB*NN, 128>>>(z, emb_w, emb2_w);
    k_gather<<<BB*NN, 128>>>(0);                 // s += mask @ sn
    k_lin  <<<BB*NN, 128>>>(Ws2v, bs2v, 0);      // t = silu(LN(s@Ws2v+b))
    k_v    <<<BB*NN, 128>>>();
    k_vqk  <<<BB*NN*3, 128>>>(Wq, Wk);
    k_dir  <<<BB*NN*2, 256>>>(Wd1, bd1, Wd2, bd2);
    for (int l = 0; l < 3; l++){
        k_lin   <<<BB*NN, 128>>>(Wint + l*HH*HH, bint + l*HH, 1);  // sl
        k_gather<<<BB*NN, 128>>>(1);                                // s += mask @ sl
    }
    k_out<<<BB, 128>>>(z, Wo, bo, out);
}

// round 2
// speedup vs baseline: 1.0334x; 1.0334x over previous
#include <cuda_runtime.h>
#include <math.h>

#define BB 64
#define NN 64
#define HH 128
#define EFD 32
#define DIRD 256
#define LN_EPS 1e-5f
#define CUT 10.0f
#define RBFG 10.0f

// ---------------- device scratch (no runtime allocation) ----------------
static __device__ float g_mask[BB*NN*NN*HH];   // 128 MB
static __device__ float g_ea  [BB*NN*NN];
static __device__ float g_ev  [BB*NN*NN*3];
static __device__ float g_s   [BB*NN*HH];
static __device__ float g_sn  [BB*NN*HH];
static __device__ float g_t   [BB*NN*HH];
static __device__ float g_v   [BB*NN*3*HH];
static __device__ float g_vq  [BB*NN*3*HH];
static __device__ float g_vk  [BB*NN*3*HH];
static __device__ float g_sl  [BB*NN*HH];

__device__ __forceinline__ float silu_f(float x){
    return x * (1.0f / (1.0f + __expf(-x)));
}

// ---- packed f32x2 helpers (Blackwell FFMA2 path, PTX-only) ----
__device__ __forceinline__ unsigned long long pack2s(float a){
    unsigned long long r;
    asm("mov.b64 %0, {%1, %1};" : "=l"(r) : "f"(a));
    return r;
}
__device__ __forceinline__ unsigned long long fma2(unsigned long long a,
                                                   unsigned long long b,
                                                   unsigned long long c){
    unsigned long long d;
    asm("fma.rn.f32x2 %0, %1, %2, %3;" : "=l"(d) : "l"(a), "l"(b), "l"(c));
    return d;
}
__device__ __forceinline__ float2 unpack2(unsigned long long v){
    float2 f;
    asm("mov.b64 {%0, %1}, %2;" : "=f"(f.x), "=f"(f.y) : "l"(v));
    return f;
}

// block reduction for 128 threads (4 warps)
__device__ __forceinline__ float blkred128(float v, volatile float* red){
    #pragma unroll
    for (int o = 16; o > 0; o >>= 1) v += __shfl_xor_sync(0xffffffffu, v, o);
    if ((threadIdx.x & 31) == 0) red[threadIdx.x >> 5] = v;
    __syncthreads();
    v = red[0] + red[1] + red[2] + red[3];
    __syncthreads();
    return v;
}

// ---------------- K1: geometry + RBF filter mask ----------------
__global__ void k_geom(const int* __restrict__ z, const float* __restrict__ pos,
                       const float* __restrict__ Wef, const float* __restrict__ bef){
    int blk = blockIdx.x;
    int b = blk >> 6, i = blk & 63;
    int t = threadIdx.x;

    __shared__ float pos_s[NN][3];
    __shared__ int   z_s[NN];
    __shared__ float d_s[NN], ea_s[NN];
    __shared__ float ef_s[NN][EFD];
    __shared__ float Wef_s[EFD*HH];
    __shared__ float bef_s[HH];

    for (int r = t; r < EFD*HH; r += 128) Wef_s[r] = Wef[r];
    bef_s[t] = bef[t];
    if (t < NN){
        z_s[t] = z[b*NN + t];
        pos_s[t][0] = pos[(b*NN + t)*3 + 0];
        pos_s[t][1] = pos[(b*NN + t)*3 + 1];
        pos_s[t][2] = pos[(b*NN + t)*3 + 2];
    }
    __syncthreads();

    if (t < NN){
        int j = t;
        float dx = pos_s[j][0] - pos_s[i][0];
        float dy = pos_s[j][1] - pos_s[i][1];
        float dz = pos_s[j][2] - pos_s[i][2];
        float d2 = dx*dx + dy*dy + dz*dz;
        float d  = sqrtf(fmaxf(d2, 1e-12f));
        d_s[j] = d;
        bool pair = (z_s[i] != 0) && (z_s[j] != 0) && (j != i);
        float ea = (pair && d < CUT) ? 0.5f*(cosf(3.14159265358979323846f * d / CUT) + 1.0f) : 0.0f;
        ea_s[j] = ea;
        g_ea[blk*NN + j] = ea;
        float inv = 1.0f / d;
        float ex = pair ? dx*inv : 0.0f;
        float ey = pair ? dy*inv : 0.0f;
        float ez = pair ? dz*inv : 0.0f;
        g_ev[(blk*NN + j)*3 + 0] = ex;
        g_ev[(blk*NN + j)*3 + 1] = ey;
        g_ev[(blk*NN + j)*3 + 2] = ez;
    }
    __syncthreads();

    const float step = CUT / (float)(EFD - 1);
    for (int r = t; r < NN*EFD; r += 128){
        int j = r >> 5, k = r & 31;
        float dd = d_s[j] - step*(float)k;
        ef_s[j][k] = __expf(-RBFG * dd * dd);
    }
    __syncthreads();

    int h = t;
    for (int j = 0; j < NN; j++){
        float acc = bef_s[h];
        #pragma unroll
        for (int k = 0; k < EFD; k++)
            acc = fmaf(ef_s[j][k], Wef_s[k*HH + h], acc);
        g_mask[(blk*NN + j)*HH + h] = silu_f(acc) * ea_s[j];
    }
}

// ---------------- K2a: s = emb[z];  sn = LN(emb2[z]) ----------------
__global__ void k_embed(const int* __restrict__ z, const float* __restrict__ emb_w,
                        const float* __restrict__ emb2_w){
    int a = blockIdx.x, h = threadIdx.x;
    __shared__ float red[4];
    int zi = z[a];
    g_s[a*HH + h] = emb_w[zi*HH + h];
    float x = emb2_w[zi*HH + h];
    float s1 = blkred128(x, red);
    float s2 = blkred128(x*x, red);
    float m = s1 * (1.0f/HH);
    float var = fmaxf(s2 * (1.0f/HH) - m*m, 0.0f);
    g_sn[a*HH + h] = (x - m) * rsqrtf(var + LN_EPS);
}

// ---------------- K2b / K6b: s += mask @ src (4 i-rows per block) ----------------
__global__ void k_gather(int sel){
    int blk = blockIdx.x;              // (b, i-group of 4)
    int b  = blk >> 4;
    int i0 = (blk & 15) * 4;
    int h  = threadIdx.x;
    const float* src = sel ? g_sl : g_sn;
    __shared__ float srcs[NN*HH];      // 32 KB
    const float* sb = src + b*NN*HH;
    for (int r = h; r < NN*HH; r += 128) srcs[r] = sb[r];
    __syncthreads();
    const float* m0 = g_mask + ((b*NN + i0)*NN)*HH;
    float a0 = 0.f, a1 = 0.f, a2 = 0.f, a3 = 0.f;
    #pragma unroll 4
    for (int j = 0; j < NN; j++){
        float sv = srcs[j*HH + h];
        a0 = fmaf(m0[(0*NN + j)*HH + h], sv, a0);
        a1 = fmaf(m0[(1*NN + j)*HH + h], sv, a1);
        a2 = fmaf(m0[(2*NN + j)*HH + h], sv, a2);
        a3 = fmaf(m0[(3*NN + j)*HH + h], sv, a3);
    }
    g_s[(b*NN + i0 + 0)*HH + h] += a0;
    g_s[(b*NN + i0 + 1)*HH + h] += a1;
    g_s[(b*NN + i0 + 2)*HH + h] += a2;
    g_s[(b*NN + i0 + 3)*HH + h] += a3;
}

// ---------------- K3 / K6a: dst = silu(LN(s @ W + bias)), 4 atoms per block ----------------
__global__ void k_lin(const float* __restrict__ W, const float* __restrict__ bias,
                      int dst_sel){
    int blk = blockIdx.x;              // 4 atoms
    int h = threadIdx.x;
    __shared__ float xs[4][HH];
    __shared__ float ys[4][HH];
    __shared__ float mm[4], rr[4];
    for (int r = h; r < 4*HH; r += 128) ((float*)xs)[r] = g_s[blk*4*HH + r];
    __syncthreads();
    float bh = bias[h];
    float a0 = bh, a1 = bh, a2 = bh, a3 = bh;
    #pragma unroll 8
    for (int k = 0; k < HH; k++){
        float w = W[k*HH + h];
        a0 = fmaf(xs[0][k], w, a0);
        a1 = fmaf(xs[1][k], w, a1);
        a2 = fmaf(xs[2][k], w, a2);
        a3 = fmaf(xs[3][k], w, a3);
    }
    ys[0][h] = a0; ys[1][h] = a1; ys[2][h] = a2; ys[3][h] = a3;
    __syncthreads();
    {
        int w = h >> 5, l = h & 31;
        float s1 = 0.f, s2 = 0.f;
        #pragma unroll
        for (int c = l; c < HH; c += 32){ float v = ys[w][c]; s1 += v; s2 += v*v; }
        #pragma unroll
        for (int o = 16; o > 0; o >>= 1){
            s1 += __shfl_xor_sync(0xffffffffu, s1, o);
            s2 += __shfl_xor_sync(0xffffffffu, s2, o);
        }
        if (l == 0){
            float m = s1 * (1.0f/HH);
            float var = fmaxf(s2 * (1.0f/HH) - m*m, 0.0f);
            mm[w] = m; rr[w] = rsqrtf(var + LN_EPS);
        }
    }
    __syncthreads();
    float* dst = dst_sel ? g_sl : g_t;
    #pragma unroll
    for (int a = 0; a < 4; a++)
        dst[(blk*4 + a)*HH + h] = silu_f((ys[a][h] - mm[a]) * rr[a]);
}

// ---------------- K4a: v[i,c,h] = sum_j mask*t*ev (4 i-rows per block) ----------------
__global__ void k_v(){
    int blk = blockIdx.x;
    int b  = blk >> 4;
    int i0 = (blk & 15) * 4;
    int h  = threadIdx.x;
    __shared__ float ts[NN*HH];        // 32 KB
    __shared__ float evl[4][NN*3];
    const float* tb = g_t + b*NN*HH;
    for (int r = h; r < NN*HH; r += 128) ts[r] = tb[r];
    for (int r = h; r < 4*NN*3; r += 128) ((float*)evl)[r] = g_ev[(b*NN + i0)*NN*3 + r];
    __syncthreads();
    const float* m0 = g_mask + ((b*NN + i0)*NN)*HH;
    float acc[4][3];
    #pragma unroll
    for (int i = 0; i < 4; i++){ acc[i][0]=0.f; acc[i][1]=0.f; acc[i][2]=0.f; }
    #pragma unroll 2
    for (int j = 0; j < NN; j++){
        float tv = ts[j*HH + h];
        #pragma unroll
        for (int i = 0; i < 4; i++){
            float m = m0[(i*NN + j)*HH + h] * tv;
            acc[i][0] = fmaf(m, evl[i][j*3+0], acc[i][0]);
            acc[i][1] = fmaf(m, evl[i][j*3+1], acc[i][1]);
            acc[i][2] = fmaf(m, evl[i][j*3+2], acc[i][2]);
        }
    }
    #pragma unroll
    for (int i = 0; i < 4; i++){
        int base = (b*NN + i0 + i)*3;
        g_v[(base + 0)*HH + h] = acc[i][0];
        g_v[(base + 1)*HH + h] = acc[i][1];
        g_v[(base + 2)*HH + h] = acc[i][2];
    }
}

// ---------------- K4b: vq = v@Wq, vk = v@Wk (8 rows per block) ----------------
__global__ void k_vqk(const float* __restrict__ Wq, const float* __restrict__ Wk){
    int blk = blockIdx.x;              // 8 rows of (B*N*3)
    int h = threadIdx.x;
    __shared__ float vs[8][HH];
    for (int r = h; r < 8*HH; r += 128) ((float*)vs)[r] = g_v[blk*8*HH + r];
    __syncthreads();
    float aq[8], ak[8];
    #pragma unroll
    for (int r = 0; r < 8; r++){ aq[r] = 0.f; ak[r] = 0.f; }
    #pragma unroll 4
    for (int k = 0; k < HH; k++){
        float wq = Wq[k*HH + h];
        float wk = Wk[k*HH + h];
        #pragma unroll
        for (int r = 0; r < 8; r++){
            float v = vs[r][k];
            aq[r] = fmaf(v, wq, aq[r]);
            ak[r] = fmaf(v, wk, ak[r]);
        }
    }
    #pragma unroll
    for (int r = 0; r < 8; r++){
        g_vq[(blk*8 + r)*HH + h] = aq[r];
        g_vk[(blk*8 + r)*HH + h] = ak[r];
    }
}

// ---------------- K5: fused directional MLP; mask *= dmask (f32x2 GEMMs) ----------------
// grid = B*N*2, 256 threads. Each block: 32 edges (one i, half of j range).
__global__ void __launch_bounds__(256) k_dir(const float* __restrict__ Wd1, const float* __restrict__ bd1,
                                             const float* __restrict__ Wd2, const float* __restrict__ bd2){
    int blk = blockIdx.x;
    int jh = blk & 1;
    int i  = (blk >> 1) & 63;
    int b  = blk >> 7;
    int t  = threadIdx.x;
    int base_i = b*NN + i;
    int j0 = jh * 32;

    __shared__ float A  [DIRD*33];     // 33792 B  (dirf^T, then h1^T)
    __shared__ float Bt [8*DIRD];      //  8192 B  (weight chunk; build-phase scratch)
    __shared__ float b1s[DIRD];
    __shared__ float b2s[HH];

    // build-phase buffers live inside Bt (dead once GEMM weight staging starts)
    float* vi  = Bt;                   // 3*HH
    float* vki = Bt + 3*HH;            // 3*HH
    float* evl = Bt + 6*HH;            // 32*3
    float* eal = Bt + 6*HH + 96;       // 32

    for (int r = t; r < 3*HH; r += 256){
        vi [r] = g_v [base_i*3*HH + r];
        vki[r] = g_vk[base_i*3*HH + r];
    }
    for (int r = t; r < 32*3; r += 256) evl[r] = g_ev[(base_i*NN + j0)*3 + r];
    if (t < 32) eal[t] = g_ea[base_i*NN + j0 + t];
    b1s[t] = bd1[t];
    if (t < HH) b2s[t] = bd2[t];
    __syncthreads();

    // ---- build dirf^T: A[k][e], k in [0,256), e in [0,32) ----
    {
        int k = t;
        if (k < HH){
            float v0 = vi[0*HH+k], v1 = vi[1*HH+k], v2 = vi[2*HH+k];
            #pragma unroll 4
            for (int e = 0; e < 32; e++){
                float d2v = v0*evl[e*3+0] + v1*evl[e*3+1] + v2*evl[e*3+2];
                A[k*33 + e] = d2v * eal[e];
            }
        } else {
            int kk = k - HH;
            float u0 = vki[0*HH+kk], u1 = vki[1*HH+kk], u2 = vki[2*HH+kk];
            for (int e = 0; e < 32; e++){
                int j = j0 + e;
                const float* vq = g_vq + (b*NN + j)*3*HH + kk;
                float d3v = vq[0]*u0 + vq[HH]*u1 + vq[2*HH]*u2;
                A[k*33 + e] = d3v * eal[e];
            }
        }
    }

    // ---- GEMM1: h1[32x256] = silu(A^T @ Wd1 + bd1)  [f32x2] ----
    int oc = t & 63;    // cols oc*4 .. +3
    int eg = t >> 6;    // edges eg*8 .. +7
    unsigned long long acc[8][2];
    #pragma unroll
    for (int e = 0; e < 8; e++){ acc[e][0] = 0ull; acc[e][1] = 0ull; }

    for (int kc = 0; kc < DIRD/8; kc++){
        __syncthreads();
        #pragma unroll
        for (int r = 0; r < 8; r++) Bt[t + r*256] = Wd1[kc*8*DIRD + t + r*256];
        __syncthreads();
        #pragma unroll
        for (int kk = 0; kk < 8; kk++){
            int krow = kc*8 + kk;
            ulonglong2 b2 = *(const ulonglong2*)&Bt[kk*DIRD + oc*4];
            const float* arow = &A[krow*33 + eg*8];
            #pragma unroll
            for (int e = 0; e < 8; e++){
                unsigned long long ap = pack2s(arow[e]);
                acc[e][0] = fma2(ap, b2.x, acc[e][0]);
                acc[e][1] = fma2(ap, b2.y, acc[e][1]);
            }
        }
    }
    __syncthreads();
    // write h1^T (with silu) into A buffer
    #pragma unroll
    for (int e = 0; e < 8; e++){
        int ee = eg*8 + e;
        int o = oc*4;
        float2 p0 = unpack2(acc[e][0]);
        float2 p1 = unpack2(acc[e][1]);
        A[(o+0)*33 + ee] = silu_f(p0.x + b1s[o+0]);
        A[(o+1)*33 + ee] = silu_f(p0.y + b1s[o+1]);
        A[(o+2)*33 + ee] = silu_f(p1.x + b1s[o+2]);
        A[(o+3)*33 + ee] = silu_f(p1.y + b1s[o+3]);
    }

    // ---- GEMM2: dmask[32x128] = silu(h1 @ Wd2 + bd2); mask *= dmask  [f32x2] ----
    int oc2 = t & 31;   // cols oc2*4 .. +3
    int eg2 = t >> 5;   // edges eg2*4 .. +3
    unsigned long long acc2[4][2];
    #pragma unroll
    for (int e = 0; e < 4; e++){ acc2[e][0] = 0ull; acc2[e][1] = 0ull; }

    for (int kc = 0; kc < DIRD/8; kc++){
        __syncthreads();
        #pragma unroll
        for (int r = 0; r < 4; r++) Bt[t + r*256] = Wd2[kc*8*HH + t + r*256];
        __syncthreads();
        #pragma unroll
        for (int kk = 0; kk < 8; kk++){
            int krow = kc*8 + kk;
            ulonglong2 b2 = *(const ulonglong2*)&Bt[kk*HH + oc2*4];
            const float* arow = &A[krow*33 + eg2*4];
            #pragma unroll
            for (int e = 0; e < 4; e++){
                unsigned long long ap = pack2s(arow[e]);
                acc2[e][0] = fma2(ap, b2.x, acc2[e][0]);
                acc2[e][1] = fma2(ap, b2.y, acc2[e][1]);
            }
        }
    }

    #pragma unroll
    for (int e = 0; e < 4; e++){
        int j = j0 + eg2*4 + e;
        int off = (base_i*NN + j)*HH + oc2*4;
        float2 p0 = unpack2(acc2[e][0]);
        float2 p1 = unpack2(acc2[e][1]);
        float4 m = *(const float4*)&g_mask[off];
        m.x *= silu_f(p0.x + b2s[oc2*4 + 0]);
        m.y *= silu_f(p0.y + b2s[oc2*4 + 1]);
        m.z *= silu_f(p1.x + b2s[oc2*4 + 2]);
        m.w *= silu_f(p1.y + b2s[oc2*4 + 3]);
        *(float4*)&g_mask[off] = m;
    }
}

// ---------------- K7: readout ----------------
__global__ void k_out(const int* __restrict__ z, const float* __restrict__ Wo,
                      const float* __restrict__ bo, float* __restrict__ out){
    int b = blockIdx.x, h = threadIdx.x;
    __shared__ float red[4];
    float acc = 0.f;
    for (int i = 0; i < NN; i++)
        if (z[b*NN + i] != 0) acc += g_s[(b*NN + i)*HH + h];
    float part = acc * Wo[h];
    float tot = blkred128(part, red);
    if (h == 0) out[b] = tot + bo[0];
}

// ---------------- launch ----------------
extern "C" void kernel_launch(void* const* d_in, const int* in_sizes, int n_in,
                              void* d_out, int out_size){
    const int*   z      = (const int*)  d_in[0];
    const float* pos    = (const float*)d_in[1];
    const float* emb_w  = (const float*)d_in[2];
    const float* emb2_w = (const float*)d_in[3];
    const float* Wef    = (const float*)d_in[4];
    const float* bef    = (const float*)d_in[5];
    const float* Ws2v   = (const float*)d_in[6];
    const float* bs2v   = (const float*)d_in[7];
    const float* Wq     = (const float*)d_in[8];
    const float* Wk     = (const float*)d_in[9];
    const float* Wd1    = (const float*)d_in[10];
    const float* bd1    = (const float*)d_in[11];
    const float* Wd2    = (const float*)d_in[12];
    const float* bd2    = (const float*)d_in[13];
    const float* Wint   = (const float*)d_in[14];
    const float* bint   = (const float*)d_in[15];
    const float* Wo     = (const float*)d_in[16];
    const float* bo     = (const float*)d_in[17];
    float* out = (float*)d_out;

    k_geom <<<BB*NN, 128>>>(z, pos, Wef, bef);
    k_embed<<<BB*NN, 128>>>(z, emb_w, emb2_w);
    k_gather<<<BB*NN/4, 128>>>(0);               // s += mask @ sn
    k_lin  <<<BB*NN/4, 128>>>(Ws2v, bs2v, 0);    // t = silu(LN(s@Ws2v+b))
    k_v    <<<BB*NN/4, 128>>>();
    k_vqk  <<<BB*NN*3/8, 128>>>(Wq, Wk);
    k_dir  <<<BB*NN*2, 256>>>(Wd1, bd1, Wd2, bd2);
    for (int l = 0; l < 3; l++){
        k_lin   <<<BB*NN/4, 128>>>(Wint + l*HH*HH, bint + l*HH, 1);  // sl
        k_gather<<<BB*NN/4, 128>>>(1);                                // s += mask @ sl
    }
    k_out<<<BB, 128>>>(z, Wo, bo, out);
}

// round 3
// speedup vs baseline: 1.0918x; 1.0565x over previous
#include <cuda_runtime.h>
#include <math.h>

#define BB 64
#define NN 64
#define HH 128
#define EFD 32
#define DIRD 256
#define LN_EPS 1e-5f
#define CUT 10.0f
#define RBFG 10.0f

// ---------------- device scratch (no runtime allocation) ----------------
static __device__ float g_mask[BB*NN*NN*HH];   // 128 MB
static __device__ float g_ea  [BB*NN*NN];
static __device__ float g_ev  [BB*NN*NN*3];
static __device__ float g_s   [BB*NN*HH];
static __device__ float g_sn  [BB*NN*HH];
static __device__ float g_t   [BB*NN*HH];
static __device__ float g_v   [BB*NN*3*HH];
static __device__ float g_vq  [BB*NN*3*HH];
static __device__ float g_vk  [BB*NN*3*HH];
static __device__ float g_sl  [BB*NN*HH];

// ---- MUFU-free fast exp2 / sigmoid / silu (fma+alu pipes only) ----
__device__ __forceinline__ float exp2_poly(float f){
    float p = 1.3333558e-3f;
    p = fmaf(p, f, 9.6181291e-3f);
    p = fmaf(p, f, 5.5504109e-2f);
    p = fmaf(p, f, 2.4022651e-1f);
    p = fmaf(p, f, 6.9314718e-1f);
    p = fmaf(p, f, 1.0f);
    return p;
}
// 2^t for t <= 0 (clamped at -126)
__device__ __forceinline__ float exp2n_f(float t){
    t = fmaxf(t, -126.0f);
    float fn = t + 12582912.0f;       // rint via magic add
    float n  = fn - 12582912.0f;
    float f  = t - n;
    int ni = __float_as_int(fn) - 0x4B400000;
    float scale = __int_as_float((ni + 127) << 23);
    return exp2_poly(f) * scale;
}
__device__ __forceinline__ float silu_f(float x){
    float t = x * (-1.442695041f);    // e^{-x} = 2^t
    t = fminf(fmaxf(t, -126.0f), 126.0f);
    float fn = t + 12582912.0f;
    float n  = fn - 12582912.0f;
    float f  = t - n;
    int ni = __float_as_int(fn) - 0x4B400000;
    float scale = __int_as_float((ni + 127) << 23);
    float e = exp2_poly(f) * scale;   // e^{-x}
    float d = 1.0f + e;
    int id = 0x7EF311C3 - __float_as_int(d);   // fast rcp seed
    float y = __int_as_float(id);
    y = y * fmaf(-d, y, 2.0f);
    y = y * fmaf(-d, y, 2.0f);
    y = y * fmaf(-d, y, 2.0f);
    return x * y;
}

// ---- packed f32x2 helpers (Blackwell FFMA2 path, PTX-only) ----
__device__ __forceinline__ unsigned long long pack2s(float a){
    unsigned long long r;
    asm("mov.b64 %0, {%1, %1};" : "=l"(r) : "f"(a));
    return r;
}
__device__ __forceinline__ unsigned long long fma2(unsigned long long a,
                                                   unsigned long long b,
                                                   unsigned long long c){
    unsigned long long d;
    asm("fma.rn.f32x2 %0, %1, %2, %3;" : "=l"(d) : "l"(a), "l"(b), "l"(c));
    return d;
}
__device__ __forceinline__ float2 unpack2(unsigned long long v){
    float2 f;
    asm("mov.b64 {%0, %1}, %2;" : "=f"(f.x), "=f"(f.y) : "l"(v));
    return f;
}

// block reduction for 128 threads (4 warps)
__device__ __forceinline__ float blkred128(float v, volatile float* red){
    #pragma unroll
    for (int o = 16; o > 0; o >>= 1) v += __shfl_xor_sync(0xffffffffu, v, o);
    if ((threadIdx.x & 31) == 0) red[threadIdx.x >> 5] = v;
    __syncthreads();
    v = red[0] + red[1] + red[2] + red[3];
    __syncthreads();
    return v;
}

// ---------------- K1: geometry + RBF filter mask ----------------
__global__ void k_geom(const int* __restrict__ z, const float* __restrict__ pos,
                       const float* __restrict__ Wef, const float* __restrict__ bef){
    int blk = blockIdx.x;
    int b = blk >> 6, i = blk & 63;
    int t = threadIdx.x;

    __shared__ float pos_s[NN][3];
    __shared__ int   z_s[NN];
    __shared__ float d_s[NN], ea_s[NN];
    __shared__ float ef_s[NN][EFD];
    __shared__ float Wef_s[EFD*HH];
    __shared__ float bef_s[HH];

    for (int r = t; r < EFD*HH; r += 128) Wef_s[r] = Wef[r];
    bef_s[t] = bef[t];
    if (t < NN){
        z_s[t] = z[b*NN + t];
        pos_s[t][0] = pos[(b*NN + t)*3 + 0];
        pos_s[t][1] = pos[(b*NN + t)*3 + 1];
        pos_s[t][2] = pos[(b*NN + t)*3 + 2];
    }
    __syncthreads();

    if (t < NN){
        int j = t;
        float dx = pos_s[j][0] - pos_s[i][0];
        float dy = pos_s[j][1] - pos_s[i][1];
        float dz = pos_s[j][2] - pos_s[i][2];
        float d2 = dx*dx + dy*dy + dz*dz;
        float d  = sqrtf(fmaxf(d2, 1e-12f));
        d_s[j] = d;
        bool pair = (z_s[i] != 0) && (z_s[j] != 0) && (j != i);
        float ea = (pair && d < CUT) ? 0.5f*(cosf(3.14159265358979323846f * d / CUT) + 1.0f) : 0.0f;
        ea_s[j] = ea;
        g_ea[blk*NN + j] = ea;
        float inv = 1.0f / d;
        float ex = pair ? dx*inv : 0.0f;
        float ey = pair ? dy*inv : 0.0f;
        float ez = pair ? dz*inv : 0.0f;
        g_ev[(blk*NN + j)*3 + 0] = ex;
        g_ev[(blk*NN + j)*3 + 1] = ey;
        g_ev[(blk*NN + j)*3 + 2] = ez;
    }
    __syncthreads();

    const float step = CUT / (float)(EFD - 1);
    for (int r = t; r < NN*EFD; r += 128){
        int j = r >> 5, k = r & 31;
        float dd = d_s[j] - step*(float)k;
        ef_s[j][k] = exp2n_f(-14.4269504089f * dd * dd);   // exp(-10*dd^2)
    }
    __syncthreads();

    int h = t;
    for (int j = 0; j < NN; j++){
        float acc = bef_s[h];
        #pragma unroll
        for (int k = 0; k < EFD; k++)
            acc = fmaf(ef_s[j][k], Wef_s[k*HH + h], acc);
        g_mask[(blk*NN + j)*HH + h] = silu_f(acc) * ea_s[j];
    }
}

// ---------------- K2a: s = emb[z];  sn = LN(emb2[z]) ----------------
__global__ void k_embed(const int* __restrict__ z, const float* __restrict__ emb_w,
                        const float* __restrict__ emb2_w){
    int a = blockIdx.x, h = threadIdx.x;
    __shared__ float red[4];
    int zi = z[a];
    g_s[a*HH + h] = emb_w[zi*HH + h];
    float x = emb2_w[zi*HH + h];
    float s1 = blkred128(x, red);
    float s2 = blkred128(x*x, red);
    float m = s1 * (1.0f/HH);
    float var = fmaxf(s2 * (1.0f/HH) - m*m, 0.0f);
    g_sn[a*HH + h] = (x - m) * rsqrtf(var + LN_EPS);
}

// ---------------- K2b / K6b: s += mask @ src (4 i-rows per block) ----------------
__global__ void k_gather(int sel){
    int blk = blockIdx.x;              // (b, i-group of 4)
    int b  = blk >> 4;
    int i0 = (blk & 15) * 4;
    int h  = threadIdx.x;
    const float* src = sel ? g_sl : g_sn;
    __shared__ float srcs[NN*HH];      // 32 KB
    const float* sb = src + b*NN*HH;
    for (int r = h; r < NN*HH; r += 128) srcs[r] = sb[r];
    __syncthreads();
    const float* m0 = g_mask + ((b*NN + i0)*NN)*HH;
    float a0 = 0.f, a1 = 0.f, a2 = 0.f, a3 = 0.f;
    #pragma unroll 4
    for (int j = 0; j < NN; j++){
        float sv = srcs[j*HH + h];
        a0 = fmaf(m0[(0*NN + j)*HH + h], sv, a0);
        a1 = fmaf(m0[(1*NN + j)*HH + h], sv, a1);
        a2 = fmaf(m0[(2*NN + j)*HH + h], sv, a2);
        a3 = fmaf(m0[(3*NN + j)*HH + h], sv, a3);
    }
    g_s[(b*NN + i0 + 0)*HH + h] += a0;
    g_s[(b*NN + i0 + 1)*HH + h] += a1;
    g_s[(b*NN + i0 + 2)*HH + h] += a2;
    g_s[(b*NN + i0 + 3)*HH + h] += a3;
}

// ---------------- K3 / K6a: dst = silu(LN(s @ W + bias)), 4 atoms per block ----------------
__global__ void k_lin(const float* __restrict__ W, const float* __restrict__ bias,
                      int dst_sel){
    int blk = blockIdx.x;              // 4 atoms
    int h = threadIdx.x;
    __shared__ float xs[4][HH];
    __shared__ float ys[4][HH];
    __shared__ float mm[4], rr[4];
    for (int r = h; r < 4*HH; r += 128) ((float*)xs)[r] = g_s[blk*4*HH + r];
    __syncthreads();
    float bh = bias[h];
    float a0 = bh, a1 = bh, a2 = bh, a3 = bh;
    #pragma unroll 8
    for (int k = 0; k < HH; k++){
        float w = W[k*HH + h];
        a0 = fmaf(xs[0][k], w, a0);
        a1 = fmaf(xs[1][k], w, a1);
        a2 = fmaf(xs[2][k], w, a2);
        a3 = fmaf(xs[3][k], w, a3);
    }
    ys[0][h] = a0; ys[1][h] = a1; ys[2][h] = a2; ys[3][h] = a3;
    __syncthreads();
    {
        int w = h >> 5, l = h & 31;
        float s1 = 0.f, s2 = 0.f;
        #pragma unroll
        for (int c = l; c < HH; c += 32){ float v = ys[w][c]; s1 += v; s2 += v*v; }
        #pragma unroll
        for (int o = 16; o > 0; o >>= 1){
            s1 += __shfl_xor_sync(0xffffffffu, s1, o);
            s2 += __shfl_xor_sync(0xffffffffu, s2, o);
        }
        if (l == 0){
            float m = s1 * (1.0f/HH);
            float var = fmaxf(s2 * (1.0f/HH) - m*m, 0.0f);
            mm[w] = m; rr[w] = rsqrtf(var + LN_EPS);
        }
    }
    __syncthreads();
    float* dst = dst_sel ? g_sl : g_t;
    #pragma unroll
    for (int a = 0; a < 4; a++)
        dst[(blk*4 + a)*HH + h] = silu_f((ys[a][h] - mm[a]) * rr[a]);
}

// ---------------- K4a: v[i,c,h] = sum_j mask*t*ev (4 i-rows per block) ----------------
__global__ void k_v(){
    int blk = blockIdx.x;
    int b  = blk >> 4;
    int i0 = (blk & 15) * 4;
    int h  = threadIdx.x;
    __shared__ float ts[NN*HH];        // 32 KB
    __shared__ float evl[4][NN*3];
    const float* tb = g_t + b*NN*HH;
    for (int r = h; r < NN*HH; r += 128) ts[r] = tb[r];
    for (int r = h; r < 4*NN*3; r += 128) ((float*)evl)[r] = g_ev[(b*NN + i0)*NN*3 + r];
    __syncthreads();
    const float* m0 = g_mask + ((b*NN + i0)*NN)*HH;
    float acc[4][3];
    #pragma unroll
    for (int i = 0; i < 4; i++){ acc[i][0]=0.f; acc[i][1]=0.f; acc[i][2]=0.f; }
    #pragma unroll 2
    for (int j = 0; j < NN; j++){
        float tv = ts[j*HH + h];
        #pragma unroll
        for (int i = 0; i < 4; i++){
            float m = m0[(i*NN + j)*HH + h] * tv;
            acc[i][0] = fmaf(m, evl[i][j*3+0], acc[i][0]);
            acc[i][1] = fmaf(m, evl[i][j*3+1], acc[i][1]);
            acc[i][2] = fmaf(m, evl[i][j*3+2], acc[i][2]);
        }
    }
    #pragma unroll
    for (int i = 0; i < 4; i++){
        int base = (b*NN + i0 + i)*3;
        g_v[(base + 0)*HH + h] = acc[i][0];
        g_v[(base + 1)*HH + h] = acc[i][1];
        g_v[(base + 2)*HH + h] = acc[i][2];
    }
}

// ---------------- K4b: vq = v@Wq, vk = v@Wk (8 rows per block) ----------------
__global__ void k_vqk(const float* __restrict__ Wq, const float* __restrict__ Wk){
    int blk = blockIdx.x;              // 8 rows of (B*N*3)
    int h = threadIdx.x;
    __shared__ float vs[8][HH];
    for (int r = h; r < 8*HH; r += 128) ((float*)vs)[r] = g_v[blk*8*HH + r];
    __syncthreads();
    float aq[8], ak[8];
    #pragma unroll
    for (int r = 0; r < 8; r++){ aq[r] = 0.f; ak[r] = 0.f; }
    #pragma unroll 4
    for (int k = 0; k < HH; k++){
        float wq = Wq[k*HH + h];
        float wk = Wk[k*HH + h];
        #pragma unroll
        for (int r = 0; r < 8; r++){
            float v = vs[r][k];
            aq[r] = fmaf(v, wq, aq[r]);
            ak[r] = fmaf(v, wk, ak[r]);
        }
    }
    #pragma unroll
    for (int r = 0; r < 8; r++){
        g_vq[(blk*8 + r)*HH + h] = aq[r];
        g_vk[(blk*8 + r)*HH + h] = ak[r];
    }
}

// ---------------- K5: fused directional MLP; mask *= dmask (f32x2, edge-paired) ----------------
// grid = B*N*2, 256 threads. Each block: 32 edges (one i, half of j range).
__global__ void __launch_bounds__(256) k_dir(const float* __restrict__ Wd1, const float* __restrict__ bd1,
                                             const float* __restrict__ Wd2, const float* __restrict__ bd2){
    int blk = blockIdx.x;
    int jh = blk & 1;
    int i  = (blk >> 1) & 63;
    int b  = blk >> 7;
    int t  = threadIdx.x;
    int base_i = b*NN + i;
    int j0 = jh * 32;

    __shared__ float A  [DIRD*34];     // 34816 B  (dirf^T, then h1^T), stride 34 for 8B align
    __shared__ float Bt [8*DIRD];      //  8192 B  (weight chunk; build-phase scratch)
    __shared__ float b1s[DIRD];
    __shared__ float b2s[HH];

    // build-phase buffers live inside Bt (dead once GEMM weight staging starts)
    float* vi  = Bt;                   // 3*HH
    float* vki = Bt + 3*HH;            // 3*HH
    float* evl = Bt + 6*HH;            // 32*3
    float* eal = Bt + 6*HH + 96;       // 32

    for (int r = t; r < 3*HH; r += 256){
        vi [r] = g_v [base_i*3*HH + r];
        vki[r] = g_vk[base_i*3*HH + r];
    }
    for (int r = t; r < 32*3; r += 256) evl[r] = g_ev[(base_i*NN + j0)*3 + r];
    if (t < 32) eal[t] = g_ea[base_i*NN + j0 + t];
    b1s[t] = bd1[t];
    if (t < HH) b2s[t] = bd2[t];
    __syncthreads();

    // ---- build dirf^T: A[k][e], k in [0,256), e in [0,32) ----
    {
        int k = t;
        if (k < HH){
            float v0 = vi[0*HH+k], v1 = vi[1*HH+k], v2 = vi[2*HH+k];
            #pragma unroll 4
            for (int e = 0; e < 32; e++){
                float d2v = v0*evl[e*3+0] + v1*evl[e*3+1] + v2*evl[e*3+2];
                A[k*34 + e] = d2v * eal[e];
            }
        } else {
            int kk = k - HH;
            float u0 = vki[0*HH+kk], u1 = vki[1*HH+kk], u2 = vki[2*HH+kk];
            for (int e = 0; e < 32; e++){
                int j = j0 + e;
                const float* vq = g_vq + (b*NN + j)*3*HH + kk;
                float d3v = vq[0]*u0 + vq[HH]*u1 + vq[2*HH]*u2;
                A[k*34 + e] = d3v * eal[e];
            }
        }
    }

    // ---- GEMM1: h1[32x256] = silu(A^T @ Wd1 + bd1)  [f32x2, edge pairs] ----
    int oc = t & 63;    // cols oc*4 .. +3
    int eg = t >> 6;    // edges eg*8 .. +7  (4 pairs)
    unsigned long long acc[4][4];
    #pragma unroll
    for (int p = 0; p < 4; p++)
        #pragma unroll
        for (int c = 0; c < 4; c++) acc[p][c] = 0ull;

    for (int kc = 0; kc < DIRD/8; kc++){
        __syncthreads();
        #pragma unroll
        for (int r = 0; r < 8; r++) Bt[t + r*256] = Wd1[kc*8*DIRD + t + r*256];
        __syncthreads();
        #pragma unroll
        for (int kk = 0; kk < 8; kk++){
            int krow = kc*8 + kk;
            float4 b4 = *(const float4*)&Bt[kk*DIRD + oc*4];
            unsigned long long bd0 = pack2s(b4.x), bd1_ = pack2s(b4.y);
            unsigned long long bd2_ = pack2s(b4.z), bd3 = pack2s(b4.w);
            const unsigned long long* ar = (const unsigned long long*)&A[krow*34 + eg*8];
            #pragma unroll
            for (int p = 0; p < 4; p++){
                unsigned long long ap = ar[p];
                acc[p][0] = fma2(ap, bd0,  acc[p][0]);
                acc[p][1] = fma2(ap, bd1_, acc[p][1]);
                acc[p][2] = fma2(ap, bd2_, acc[p][2]);
                acc[p][3] = fma2(ap, bd3,  acc[p][3]);
            }
        }
    }
    __syncthreads();
    // write h1^T (with silu) into A buffer; pairs are adjacent edges -> 8B stores
    #pragma unroll
    for (int p = 0; p < 4; p++){
        #pragma unroll
        for (int c = 0; c < 4; c++){
            int o = oc*4 + c;
            float2 v = unpack2(acc[p][c]);
            float2 w;
            w.x = silu_f(v.x + b1s[o]);
            w.y = silu_f(v.y + b1s[o]);
            *(float2*)&A[o*34 + eg*8 + p*2] = w;
        }
    }

    // ---- GEMM2: dmask[32x128] = silu(h1 @ Wd2 + bd2); mask *= dmask ----
    __syncthreads();
    int oc2 = t & 31;   // cols oc2*4 .. +3
    int eg2 = t >> 5;   // edges eg2*4 .. +3  (2 pairs)
    unsigned long long acc2[2][4];
    #pragma unroll
    for (int p = 0; p < 2; p++)
        #pragma unroll
        for (int c = 0; c < 4; c++) acc2[p][c] = 0ull;

    for (int kc = 0; kc < DIRD/8; kc++){
        __syncthreads();
        #pragma unroll
        for (int r = 0; r < 4; r++) Bt[t + r*256] = Wd2[kc*8*HH + t + r*256];
        __syncthreads();
        #pragma unroll
        for (int kk = 0; kk < 8; kk++){
            int krow = kc*8 + kk;
            float4 b4 = *(const float4*)&Bt[kk*HH + oc2*4];
            unsigned long long bd0 = pack2s(b4.x), bd1_ = pack2s(b4.y);
            unsigned long long bd2_ = pack2s(b4.z), bd3 = pack2s(b4.w);
            const unsigned long long* ar = (const unsigned long long*)&A[krow*34 + eg2*4];
            #pragma unroll
            for (int p = 0; p < 2; p++){
                unsigned long long ap = ar[p];
                acc2[p][0] = fma2(ap, bd0,  acc2[p][0]);
                acc2[p][1] = fma2(ap, bd1_, acc2[p][1]);
                acc2[p][2] = fma2(ap, bd2_, acc2[p][2]);
                acc2[p][3] = fma2(ap, bd3,  acc2[p][3]);
            }
        }
    }

    #pragma unroll
    for (int p = 0; p < 2; p++){
        float2 d0 = unpack2(acc2[p][0]);
        float2 d1 = unpack2(acc2[p][1]);
        float2 d2 = unpack2(acc2[p][2]);
        float2 d3 = unpack2(acc2[p][3]);
        int o = oc2*4;
        int j = j0 + eg2*4 + p*2;
        int off0 = (base_i*NN + j)*HH + o;
        float4 m0 = *(const float4*)&g_mask[off0];
        m0.x *= silu_f(d0.x + b2s[o+0]);
        m0.y *= silu_f(d1.x + b2s[o+1]);
        m0.z *= silu_f(d2.x + b2s[o+2]);
        m0.w *= silu_f(d3.x + b2s[o+3]);
        *(float4*)&g_mask[off0] = m0;
        int off1 = off0 + HH;
        float4 m1 = *(const float4*)&g_mask[off1];
        m1.x *= silu_f(d0.y + b2s[o+0]);
        m1.y *= silu_f(d1.y + b2s[o+1]);
        m1.z *= silu_f(d2.y + b2s[o+2]);
        m1.w *= silu_f(d3.y + b2s[o+3]);
        *(float4*)&g_mask[off1] = m1;
    }
}

// ---------------- K7: readout ----------------
__global__ void k_out(const int* __restrict__ z, const float* __restrict__ Wo,
                      const float* __restrict__ bo, float* __restrict__ out){
    int b = blockIdx.x, h = threadIdx.x;
    __shared__ float red[4];
    float acc = 0.f;
    for (int i = 0; i < NN; i++)
        if (z[b*NN + i] != 0) acc += g_s[(b*NN + i)*HH + h];
    float part = acc * Wo[h];
    float tot = blkred128(part, red);
    if (h == 0) out[b] = tot + bo[0];
}

// ---------------- launch ----------------
extern "C" void kernel_launch(void* const* d_in, const int* in_sizes, int n_in,
                              void* d_out, int out_size){
    const int*   z      = (const int*)  d_in[0];
    const float* pos    = (const float*)d_in[1];
    const float* emb_w  = (const float*)d_in[2];
    const float* emb2_w = (const float*)d_in[3];
    const float* Wef    = (const float*)d_in[4];
    const float* bef    = (const float*)d_in[5];
    const float* Ws2v   = (const float*)d_in[6];
    const float* bs2v   = (const float*)d_in[7];
    const float* Wq     = (const float*)d_in[8];
    const float* Wk     = (const float*)d_in[9];
    const float* Wd1    = (const float*)d_in[10];
    const float* bd1    = (const float*)d_in[11];
    const float* Wd2    = (const float*)d_in[12];
    const float* bd2    = (const float*)d_in[13];
    const float* Wint   = (const float*)d_in[14];
    const float* bint   = (const float*)d_in[15];
    const float* Wo     = (const float*)d_in[16];
    const float* bo     = (const float*)d_in[17];
    float* out = (float*)d_out;

    k_geom <<<BB*NN, 128>>>(z, pos, Wef, bef);
    k_embed<<<BB*NN, 128>>>(z, emb_w, emb2_w);
    k_gather<<<BB*NN/4, 128>>>(0);               // s += mask @ sn
    k_lin  <<<BB*NN/4, 128>>>(Ws2v, bs2v, 0);    // t = silu(LN(s@Ws2v+b))
    k_v    <<<BB*NN/4, 128>>>();
    k_vqk  <<<BB*NN*3/8, 128>>>(Wq, Wk);
    k_dir  <<<BB*NN*2, 256>>>(Wd1, bd1, Wd2, bd2);
    for (int l = 0; l < 3; l++){
        k_lin   <<<BB*NN/4, 128>>>(Wint + l*HH*HH, bint + l*HH, 1);  // sl
        k_gather<<<BB*NN/4, 128>>>(1);                                // s += mask @ sl
    }
    k_out<<<BB, 128>>>(z, Wo, bo, out);
}

// round 4
// speedup vs baseline: 1.2041x; 1.1028x over previous
#include <cuda_runtime.h>
#include <math.h>

#define BB 64
#define NN 64
#define HH 128
#define EFD 32
#define DIRD 256
#define LN_EPS 1e-5f
#define CUT 10.0f
#define RBFG 10.0f
#define AST 260   // smem stride for A (64 x 256 tile): banks (4g+tig) all distinct

// ---------------- device scratch (no runtime allocation) ----------------
static __device__ float g_mask[BB*NN*NN*HH];   // 128 MB
static __device__ float g_ea  [BB*NN*NN];
static __device__ float g_ev  [BB*NN*NN*3];
static __device__ float g_s   [BB*NN*HH];
static __device__ float g_sn  [BB*NN*HH];
static __device__ float g_t   [BB*NN*HH];
static __device__ float g_v   [BB*NN*3*HH];
static __device__ float g_vq  [BB*NN*3*HH];
static __device__ float g_vk  [BB*NN*3*HH];
static __device__ float g_sl  [BB*NN*HH];

// ---- MUFU-free fast exp2 / silu ----
__device__ __forceinline__ float exp2_poly(float f){
    float p = 1.3333558e-3f;
    p = fmaf(p, f, 9.6181291e-3f);
    p = fmaf(p, f, 5.5504109e-2f);
    p = fmaf(p, f, 2.4022651e-1f);
    p = fmaf(p, f, 6.9314718e-1f);
    p = fmaf(p, f, 1.0f);
    return p;
}
__device__ __forceinline__ float exp2n_f(float t){
    t = fmaxf(t, -126.0f);
    float fn = t + 12582912.0f;
    float n  = fn - 12582912.0f;
    float f  = t - n;
    int ni = __float_as_int(fn) - 0x4B400000;
    float scale = __int_as_float((ni + 127) << 23);
    return exp2_poly(f) * scale;
}
__device__ __forceinline__ float silu_f(float x){
    float t = x * (-1.442695041f);
    t = fminf(fmaxf(t, -126.0f), 126.0f);
    float fn = t + 12582912.0f;
    float n  = fn - 12582912.0f;
    float f  = t - n;
    int ni = __float_as_int(fn) - 0x4B400000;
    float scale = __int_as_float((ni + 127) << 23);
    float e = exp2_poly(f) * scale;
    float d = 1.0f + e;
    int id = 0x7EF311C3 - __float_as_int(d);
    float y = __int_as_float(id);
    y = y * fmaf(-d, y, 2.0f);
    y = y * fmaf(-d, y, 2.0f);
    y = y * fmaf(-d, y, 2.0f);
    return x * y;
}

// ---- tf32 helpers ----
__device__ __forceinline__ unsigned tf32of(float x){
    unsigned r;
    asm("cvt.rna.tf32.f32 %0, %1;" : "=r"(r) : "f"(x));
    return r;
}
__device__ __forceinline__ void mma8(float* c, const unsigned* a, unsigned b0, unsigned b1){
    asm("mma.sync.aligned.m16n8k8.row.col.f32.tf32.tf32.f32 "
        "{%0,%1,%2,%3},{%4,%5,%6,%7},{%8,%9},{%0,%1,%2,%3};"
        : "+f"(c[0]), "+f"(c[1]), "+f"(c[2]), "+f"(c[3])
        : "r"(a[0]), "r"(a[1]), "r"(a[2]), "r"(a[3]), "r"(b0), "r"(b1));
}

// block reduction for 128 threads (4 warps)
__device__ __forceinline__ float blkred128(float v, volatile float* red){
    #pragma unroll
    for (int o = 16; o > 0; o >>= 1) v += __shfl_xor_sync(0xffffffffu, v, o);
    if ((threadIdx.x & 31) == 0) red[threadIdx.x >> 5] = v;
    __syncthreads();
    v = red[0] + red[1] + red[2] + red[3];
    __syncthreads();
    return v;
}

// ---------------- K1: geometry + RBF filter mask ----------------
__global__ void k_geom(const int* __restrict__ z, const float* __restrict__ pos,
                       const float* __restrict__ Wef, const float* __restrict__ bef){
    int blk = blockIdx.x;
    int b = blk >> 6, i = blk & 63;
    int t = threadIdx.x;

    __shared__ float pos_s[NN][3];
    __shared__ int   z_s[NN];
    __shared__ float d_s[NN], ea_s[NN];
    __shared__ float ef_s[NN][EFD];
    __shared__ float Wef_s[EFD*HH];
    __shared__ float bef_s[HH];

    for (int r = t; r < EFD*HH; r += 128) Wef_s[r] = Wef[r];
    bef_s[t] = bef[t];
    if (t < NN){
        z_s[t] = z[b*NN + t];
        pos_s[t][0] = pos[(b*NN + t)*3 + 0];
        pos_s[t][1] = pos[(b*NN + t)*3 + 1];
        pos_s[t][2] = pos[(b*NN + t)*3 + 2];
    }
    __syncthreads();

    if (t < NN){
        int j = t;
        float dx = pos_s[j][0] - pos_s[i][0];
        float dy = pos_s[j][1] - pos_s[i][1];
        float dz = pos_s[j][2] - pos_s[i][2];
        float d2 = dx*dx + dy*dy + dz*dz;
        float d  = sqrtf(fmaxf(d2, 1e-12f));
        d_s[j] = d;
        bool pair = (z_s[i] != 0) && (z_s[j] != 0) && (j != i);
        float ea = (pair && d < CUT) ? 0.5f*(cosf(3.14159265358979323846f * d / CUT) + 1.0f) : 0.0f;
        ea_s[j] = ea;
        g_ea[blk*NN + j] = ea;
        float inv = 1.0f / d;
        float ex = pair ? dx*inv : 0.0f;
        float ey = pair ? dy*inv : 0.0f;
        float ez = pair ? dz*inv : 0.0f;
        g_ev[(blk*NN + j)*3 + 0] = ex;
        g_ev[(blk*NN + j)*3 + 1] = ey;
        g_ev[(blk*NN + j)*3 + 2] = ez;
    }
    __syncthreads();

    const float step = CUT / (float)(EFD - 1);
    for (int r = t; r < NN*EFD; r += 128){
        int j = r >> 5, k = r & 31;
        float dd = d_s[j] - step*(float)k;
        ef_s[j][k] = exp2n_f(-14.4269504089f * dd * dd);
    }
    __syncthreads();

    int h = t;
    for (int j = 0; j < NN; j++){
        float acc = bef_s[h];
        #pragma unroll
        for (int k = 0; k < EFD; k++)
            acc = fmaf(ef_s[j][k], Wef_s[k*HH + h], acc);
        g_mask[(blk*NN + j)*HH + h] = silu_f(acc) * ea_s[j];
    }
}

// ---------------- K2a: s = emb[z];  sn = LN(emb2[z]) ----------------
__global__ void k_embed(const int* __restrict__ z, const float* __restrict__ emb_w,
                        const float* __restrict__ emb2_w){
    int a = blockIdx.x, h = threadIdx.x;
    __shared__ float red[4];
    int zi = z[a];
    g_s[a*HH + h] = emb_w[zi*HH + h];
    float x = emb2_w[zi*HH + h];
    float s1 = blkred128(x, red);
    float s2 = blkred128(x*x, red);
    float m = s1 * (1.0f/HH);
    float var = fmaxf(s2 * (1.0f/HH) - m*m, 0.0f);
    g_sn[a*HH + h] = (x - m) * rsqrtf(var + LN_EPS);
}

// ---------------- K2b / K6b: s += mask @ src (4 i-rows per block) ----------------
__global__ void k_gather(int sel){
    int blk = blockIdx.x;
    int b  = blk >> 4;
    int i0 = (blk & 15) * 4;
    int h  = threadIdx.x;
    const float* src = sel ? g_sl : g_sn;
    __shared__ float srcs[NN*HH];
    const float* sb = src + b*NN*HH;
    for (int r = h; r < NN*HH; r += 128) srcs[r] = sb[r];
    __syncthreads();
    const float* m0 = g_mask + ((b*NN + i0)*NN)*HH;
    float a0 = 0.f, a1 = 0.f, a2 = 0.f, a3 = 0.f;
    #pragma unroll 4
    for (int j = 0; j < NN; j++){
        float sv = srcs[j*HH + h];
        a0 = fmaf(m0[(0*NN + j)*HH + h], sv, a0);
        a1 = fmaf(m0[(1*NN + j)*HH + h], sv, a1);
        a2 = fmaf(m0[(2*NN + j)*HH + h], sv, a2);
        a3 = fmaf(m0[(3*NN + j)*HH + h], sv, a3);
    }
    g_s[(b*NN + i0 + 0)*HH + h] += a0;
    g_s[(b*NN + i0 + 1)*HH + h] += a1;
    g_s[(b*NN + i0 + 2)*HH + h] += a2;
    g_s[(b*NN + i0 + 3)*HH + h] += a3;
}

// ---------------- K3 / K6a: dst = silu(LN(s @ W + bias)), 4 atoms per block ----------------
__global__ void k_lin(const float* __restrict__ W, const float* __restrict__ bias,
                      int dst_sel){
    int blk = blockIdx.x;
    int h = threadIdx.x;
    __shared__ float xs[4][HH];
    __shared__ float ys[4][HH];
    __shared__ float mm[4], rr[4];
    for (int r = h; r < 4*HH; r += 128) ((float*)xs)[r] = g_s[blk*4*HH + r];
    __syncthreads();
    float bh = bias[h];
    float a0 = bh, a1 = bh, a2 = bh, a3 = bh;
    #pragma unroll 8
    for (int k = 0; k < HH; k++){
        float w = W[k*HH + h];
        a0 = fmaf(xs[0][k], w, a0);
        a1 = fmaf(xs[1][k], w, a1);
        a2 = fmaf(xs[2][k], w, a2);
        a3 = fmaf(xs[3][k], w, a3);
    }
    ys[0][h] = a0; ys[1][h] = a1; ys[2][h] = a2; ys[3][h] = a3;
    __syncthreads();
    {
        int w = h >> 5, l = h & 31;
        float s1 = 0.f, s2 = 0.f;
        #pragma unroll
        for (int c = l; c < HH; c += 32){ float v = ys[w][c]; s1 += v; s2 += v*v; }
        #pragma unroll
        for (int o = 16; o > 0; o >>= 1){
            s1 += __shfl_xor_sync(0xffffffffu, s1, o);
            s2 += __shfl_xor_sync(0xffffffffu, s2, o);
        }
        if (l == 0){
            float m = s1 * (1.0f/HH);
            float var = fmaxf(s2 * (1.0f/HH) - m*m, 0.0f);
            mm[w] = m; rr[w] = rsqrtf(var + LN_EPS);
        }
    }
    __syncthreads();
    float* dst = dst_sel ? g_sl : g_t;
    #pragma unroll
    for (int a = 0; a < 4; a++)
        dst[(blk*4 + a)*HH + h] = silu_f((ys[a][h] - mm[a]) * rr[a]);
}

// ---------------- K4a: v[i,c,h] = sum_j mask*t*ev (4 i-rows per block) ----------------
__global__ void k_v(){
    int blk = blockIdx.x;
    int b  = blk >> 4;
    int i0 = (blk & 15) * 4;
    int h  = threadIdx.x;
    __shared__ float ts[NN*HH];
    __shared__ float evl[4][NN*3];
    const float* tb = g_t + b*NN*HH;
    for (int r = h; r < NN*HH; r += 128) ts[r] = tb[r];
    for (int r = h; r < 4*NN*3; r += 128) ((float*)evl)[r] = g_ev[(b*NN + i0)*NN*3 + r];
    __syncthreads();
    const float* m0 = g_mask + ((b*NN + i0)*NN)*HH;
    float acc[4][3];
    #pragma unroll
    for (int i = 0; i < 4; i++){ acc[i][0]=0.f; acc[i][1]=0.f; acc[i][2]=0.f; }
    #pragma unroll 2
    for (int j = 0; j < NN; j++){
        float tv = ts[j*HH + h];
        #pragma unroll
        for (int i = 0; i < 4; i++){
            float m = m0[(i*NN + j)*HH + h] * tv;
            acc[i][0] = fmaf(m, evl[i][j*3+0], acc[i][0]);
            acc[i][1] = fmaf(m, evl[i][j*3+1], acc[i][1]);
            acc[i][2] = fmaf(m, evl[i][j*3+2], acc[i][2]);
        }
    }
    #pragma unroll
    for (int i = 0; i < 4; i++){
        int base = (b*NN + i0 + i)*3;
        g_v[(base + 0)*HH + h] = acc[i][0];
        g_v[(base + 1)*HH + h] = acc[i][1];
        g_v[(base + 2)*HH + h] = acc[i][2];
    }
}

// ---------------- K4b: vq = v@Wq, vk = v@Wk (8 rows per block) ----------------
__global__ void k_vqk(const float* __restrict__ Wq, const float* __restrict__ Wk){
    int blk = blockIdx.x;
    int h = threadIdx.x;
    __shared__ float vs[8][HH];
    for (int r = h; r < 8*HH; r += 128) ((float*)vs)[r] = g_v[blk*8*HH + r];
    __syncthreads();
    float aq[8], ak[8];
    #pragma unroll
    for (int r = 0; r < 8; r++){ aq[r] = 0.f; ak[r] = 0.f; }
    #pragma unroll 4
    for (int k = 0; k < HH; k++){
        float wq = Wq[k*HH + h];
        float wk = Wk[k*HH + h];
        #pragma unroll
        for (int r = 0; r < 8; r++){
            float v = vs[r][k];
            aq[r] = fmaf(v, wq, aq[r]);
            ak[r] = fmaf(v, wk, ak[r]);
        }
    }
    #pragma unroll
    for (int r = 0; r < 8; r++){
        g_vq[(blk*8 + r)*HH + h] = aq[r];
        g_vk[(blk*8 + r)*HH + h] = ak[r];
    }
}

// ---------------- K5: directional MLP on tensor cores (3xTF32 mma.sync) ----------------
// One block per (b,i): M = 64 edges, GEMM1 64x256x256, GEMM2 64x128x256.
// 8 warps; warp w -> m-tile (w&3)*16, n-half (w>>2).
// Dynamic smem: A[64*AST] fp32 (dirf, then h1), Bh/Bl[16*264] staged tf32 hi/lo, biases.
__global__ void __launch_bounds__(256, 2) k_dir(const float* __restrict__ Wd1, const float* __restrict__ bd1,
                                                const float* __restrict__ Wd2, const float* __restrict__ bd2){
    extern __shared__ float sm[];
    float* A   = sm;                 // 64*260 = 16640
    float* Bh  = sm + 64*AST;        // 4224
    float* Bl  = Bh + 16*264;        // 4224
    float* b1s = Bl + 16*264;        // 256
    float* b2s = b1s + 256;          // 128

    int t  = threadIdx.x;
    int bi = blockIdx.x;             // b*64 + i
    int bbase = bi & ~63;            // b*64

    // build scratch lives in Bh (dead before first weight stage)
    float* vi  = Bh;                 // 384
    float* vki = Bh + 384;           // 384
    float* evl = Bh + 768;           // 192
    float* eal = Bh + 960;           // 64

    for (int r = t; r < 3*HH; r += 256){
        vi [r] = g_v [bi*3*HH + r];
        vki[r] = g_vk[bi*3*HH + r];
    }
    for (int r = t; r < NN*3; r += 256) evl[r] = g_ev[bi*NN*3 + r];
    if (t < NN) eal[t] = g_ea[bi*NN + t];
    b1s[t] = bd1[t];
    if (t < HH) b2s[t] = bd2[t];
    __syncthreads();

    // ---- build dirf: A[e][k], e in [0,64), k in [0,256) ----
    if (t < HH){
        int k = t;
        float v0 = vi[k], v1 = vi[HH+k], v2 = vi[2*HH+k];
        #pragma unroll 4
        for (int e = 0; e < NN; e++){
            float d2v = v0*evl[e*3+0] + v1*evl[e*3+1] + v2*evl[e*3+2];
            A[e*AST + k] = d2v * eal[e];
        }
    } else {
        int kk = t - HH;
        float u0 = vki[kk], u1 = vki[HH+kk], u2 = vki[2*HH+kk];
        for (int e = 0; e < NN; e++){
            const float* vq = g_vq + (bbase + e)*3*HH + kk;
            float d3v = vq[0]*u0 + vq[HH]*u1 + vq[2*HH]*u2;
            A[e*AST + HH + kk] = d3v * eal[e];
        }
    }
    __syncthreads();

    int lane = t & 31, w = t >> 5;
    int g   = lane >> 2, tig = lane & 3;
    int m0  = (w & 3) * 16;
    int nh  = w >> 2;

    // ---- GEMM1: h1[64x256] = silu(dirf @ Wd1 + b1), 3xTF32 ----
    float acc[16][4];
    #pragma unroll
    for (int nt = 0; nt < 16; nt++){ acc[nt][0]=0.f; acc[nt][1]=0.f; acc[nt][2]=0.f; acc[nt][3]=0.f; }

    for (int ks = 0; ks < 16; ks++){
        __syncthreads();
        #pragma unroll
        for (int r = t; r < 16*256; r += 256){
            int rr = r >> 8, cc = r & 255;
            float wv = Wd1[(ks*16+rr)*256 + cc];
            unsigned hh = tf32of(wv);
            float hf = __uint_as_float(hh);
            Bh[rr*264+cc] = hf;
            Bl[rr*264+cc] = __uint_as_float(tf32of(wv - hf));
        }
        __syncthreads();
        #pragma unroll
        for (int k2 = 0; k2 < 2; k2++){
            int k0 = ks*16 + k2*8;
            int kb = k2*8;
            float af0 = A[(m0+g  )*AST + k0 + tig];
            float af1 = A[(m0+g+8)*AST + k0 + tig];
            float af2 = A[(m0+g  )*AST + k0 + tig + 4];
            float af3 = A[(m0+g+8)*AST + k0 + tig + 4];
            unsigned ah[4], al[4];
            ah[0]=tf32of(af0); al[0]=tf32of(af0-__uint_as_float(ah[0]));
            ah[1]=tf32of(af1); al[1]=tf32of(af1-__uint_as_float(ah[1]));
            ah[2]=tf32of(af2); al[2]=tf32of(af2-__uint_as_float(ah[2]));
            ah[3]=tf32of(af3); al[3]=tf32of(af3-__uint_as_float(ah[3]));
            #pragma unroll
            for (int nt = 0; nt < 16; nt++){
                int n0 = nh*128 + nt*8;
                unsigned bh0 = __float_as_uint(Bh[(kb+tig  )*264 + n0+g]);
                unsigned bh1 = __float_as_uint(Bh[(kb+tig+4)*264 + n0+g]);
                unsigned bl0 = __float_as_uint(Bl[(kb+tig  )*264 + n0+g]);
                unsigned bl1 = __float_as_uint(Bl[(kb+tig+4)*264 + n0+g]);
                mma8(acc[nt], ah, bl0, bl1);
                mma8(acc[nt], al, bh0, bh1);
                mma8(acc[nt], ah, bh0, bh1);
            }
        }
    }
    __syncthreads();
    // write h1 (with silu) back into A
    #pragma unroll
    for (int nt = 0; nt < 16; nt++){
        int n0 = nh*128 + nt*8;
        int c0 = n0 + 2*tig, c1 = c0 + 1;
        A[(m0+g  )*AST + c0] = silu_f(acc[nt][0] + b1s[c0]);
        A[(m0+g  )*AST + c1] = silu_f(acc[nt][1] + b1s[c1]);
        A[(m0+g+8)*AST + c0] = silu_f(acc[nt][2] + b1s[c0]);
        A[(m0+g+8)*AST + c1] = silu_f(acc[nt][3] + b1s[c1]);
    }
    __syncthreads();

    // ---- GEMM2: dmask[64x128] = silu(h1 @ Wd2 + b2), 3xTF32; mask *= dmask ----
    float acc2[8][4];
    #pragma unroll
    for (int nt = 0; nt < 8; nt++){ acc2[nt][0]=0.f; acc2[nt][1]=0.f; acc2[nt][2]=0.f; acc2[nt][3]=0.f; }

    for (int ks = 0; ks < 16; ks++){
        __syncthreads();
        #pragma unroll
        for (int r = t; r < 16*128; r += 256){
            int rr = r >> 7, cc = r & 127;
            float wv = Wd2[(ks*16+rr)*128 + cc];
            unsigned hh = tf32of(wv);
            float hf = __uint_as_float(hh);
            Bh[rr*136+cc] = hf;
            Bl[rr*136+cc] = __uint_as_float(tf32of(wv - hf));
        }
        __syncthreads();
        #pragma unroll
        for (int k2 = 0; k2 < 2; k2++){
            int k0 = ks*16 + k2*8;
            int kb = k2*8;
            float af0 = A[(m0+g  )*AST + k0 + tig];
            float af1 = A[(m0+g+8)*AST + k0 + tig];
            float af2 = A[(m0+g  )*AST + k0 + tig + 4];
            float af3 = A[(m0+g+8)*AST + k0 + tig + 4];
            unsigned ah[4], al[4];
            ah[0]=tf32of(af0); al[0]=tf32of(af0-__uint_as_float(ah[0]));
            ah[1]=tf32of(af1); al[1]=tf32of(af1-__uint_as_float(ah[1]));
            ah[2]=tf32of(af2); al[2]=tf32of(af2-__uint_as_float(ah[2]));
            ah[3]=tf32of(af3); al[3]=tf32of(af3-__uint_as_float(ah[3]));
            #pragma unroll
            for (int nt = 0; nt < 8; nt++){
                int n0 = nh*64 + nt*8;
                unsigned bh0 = __float_as_uint(Bh[(kb+tig  )*136 + n0+g]);
                unsigned bh1 = __float_as_uint(Bh[(kb+tig+4)*136 + n0+g]);
                unsigned bl0 = __float_as_uint(Bl[(kb+tig  )*136 + n0+g]);
                unsigned bl1 = __float_as_uint(Bl[(kb+tig+4)*136 + n0+g]);
                mma8(acc2[nt], ah, bl0, bl1);
                mma8(acc2[nt], al, bh0, bh1);
                mma8(acc2[nt], ah, bh0, bh1);
            }
        }
    }

    // epilogue: mask *= silu(dmask + b2)
    #pragma unroll
    for (int nt = 0; nt < 8; nt++){
        int n0 = nh*64 + nt*8;
        int h0 = n0 + 2*tig, h1i = h0 + 1;
        long r0 = (long)(bi*NN + m0+g  )*HH;
        long r1 = (long)(bi*NN + m0+g+8)*HH;
        g_mask[r0+h0 ] *= silu_f(acc2[nt][0] + b2s[h0 ]);
        g_mask[r0+h1i] *= silu_f(acc2[nt][1] + b2s[h1i]);
        g_mask[r1+h0 ] *= silu_f(acc2[nt][2] + b2s[h0 ]);
        g_mask[r1+h1i] *= silu_f(acc2[nt][3] + b2s[h1i]);
    }
}

// ---------------- K7: readout ----------------
__global__ void k_out(const int* __restrict__ z, const float* __restrict__ Wo,
                      const float* __restrict__ bo, float* __restrict__ out){
    int b = blockIdx.x, h = threadIdx.x;
    __shared__ float red[4];
    float acc = 0.f;
    for (int i = 0; i < NN; i++)
        if (z[b*NN + i] != 0) acc += g_s[(b*NN + i)*HH + h];
    float part = acc * Wo[h];
    float tot = blkred128(part, red);
    if (h == 0) out[b] = tot + bo[0];
}

// ---------------- launch ----------------
#define SMEM_DIR ((64*AST + 2*16*264 + 256 + 128) * sizeof(float))

extern "C" void kernel_launch(void* const* d_in, const int* in_sizes, int n_in,
                              void* d_out, int out_size){
    const int*   z      = (const int*)  d_in[0];
    const float* pos    = (const float*)d_in[1];
    const float* emb_w  = (const float*)d_in[2];
    const float* emb2_w = (const float*)d_in[3];
    const float* Wef    = (const float*)d_in[4];
    const float* bef    = (const float*)d_in[5];
    const float* Ws2v   = (const float*)d_in[6];
    const float* bs2v   = (const float*)d_in[7];
    const float* Wq     = (const float*)d_in[8];
    const float* Wk     = (const float*)d_in[9];
    const float* Wd1    = (const float*)d_in[10];
    const float* bd1    = (const float*)d_in[11];
    const float* Wd2    = (const float*)d_in[12];
    const float* bd2    = (const float*)d_in[13];
    const float* Wint   = (const float*)d_in[14];
    const float* bint   = (const float*)d_in[15];
    const float* Wo     = (const float*)d_in[16];
    const float* bo     = (const float*)d_in[17];
    float* out = (float*)d_out;

    cudaFuncSetAttribute(k_dir, cudaFuncAttributeMaxDynamicSharedMemorySize, (int)SMEM_DIR);

    k_geom <<<BB*NN, 128>>>(z, pos, Wef, bef);
    k_embed<<<BB*NN, 128>>>(z, emb_w, emb2_w);
    k_gather<<<BB*NN/4, 128>>>(0);               // s += mask @ sn
    k_lin  <<<BB*NN/4, 128>>>(Ws2v, bs2v, 0);    // t = silu(LN(s@Ws2v+b))
    k_v    <<<BB*NN/4, 128>>>();
    k_vqk  <<<BB*NN*3/8, 128>>>(Wq, Wk);
    k_dir  <<<BB*NN, 256, SMEM_DIR>>>(Wd1, bd1, Wd2, bd2);
    for (int l = 0; l < 3; l++){
        k_lin   <<<BB*NN/4, 128>>>(Wint + l*HH*HH, bint + l*HH, 1);  // sl
        k_gather<<<BB*NN/4, 128>>>(1);                                // s += mask @ sl
    }
    k_out<<<BB, 128>>>(z, Wo, bo, out);
}

// round 6
// speedup vs baseline: 1.3127x; 1.0902x over previous
#include <cuda_runtime.h>
#include <cuda_bf16.h>
#include <math.h>
#include <stdint.h>

#define BB 64
#define NN 64
#define HH 128
#define EFD 32
#define LN_EPS 1e-5f
#define CUT 10.0f

// ---------------- device scratch (no runtime allocation) ----------------
static __device__ float g_mask[BB*NN*NN*HH];   // 128 MB
static __device__ float g_ea  [BB*NN*NN];
static __device__ float g_ev  [BB*NN*NN*3];
static __device__ float g_s   [BB*NN*HH];
static __device__ float g_sn  [BB*NN*HH];
static __device__ float g_t   [BB*NN*HH];
static __device__ float g_v   [BB*NN*3*HH];
static __device__ float g_vq  [BB*NN*3*HH];
static __device__ float g_vk  [BB*NN*3*HH];
static __device__ float g_sl  [BB*NN*HH];
// pre-split bf16 hi/lo packed weights: [n][kp] -> uint2{hi_pair, lo_pair}
static __device__ uint2 gW1s[256*128];
static __device__ uint2 gW2s[128*128];

// ---- MUFU-free fast exp2 / silu ----
__device__ __forceinline__ float exp2_poly(float f){
    float p = 1.3333558e-3f;
    p = fmaf(p, f, 9.6181291e-3f);
    p = fmaf(p, f, 5.5504109e-2f);
    p = fmaf(p, f, 2.4022651e-1f);
    p = fmaf(p, f, 6.9314718e-1f);
    p = fmaf(p, f, 1.0f);
    return p;
}
__device__ __forceinline__ float exp2n_f(float t){
    t = fmaxf(t, -126.0f);
    float fn = t + 12582912.0f;
    float n  = fn - 12582912.0f;
    float f  = t - n;
    int ni = __float_as_int(fn) - 0x4B400000;
    float scale = __int_as_float((ni + 127) << 23);
    return exp2_poly(f) * scale;
}
__device__ __forceinline__ float silu_f(float x){
    float t = x * (-1.442695041f);
    t = fminf(fmaxf(t, -126.0f), 126.0f);
    float fn = t + 12582912.0f;
    float n  = fn - 12582912.0f;
    float f  = t - n;
    int ni = __float_as_int(fn) - 0x4B400000;
    float scale = __int_as_float((ni + 127) << 23);
    float e = exp2_poly(f) * scale;
    float d = 1.0f + e;
    int id = 0x7EF311C3 - __float_as_int(d);
    float y = __int_as_float(id);
    y = y * fmaf(-d, y, 2.0f);
    y = y * fmaf(-d, y, 2.0f);
    y = y * fmaf(-d, y, 2.0f);
    return x * y;
}

// ---- bf16 2-way split & pack: {low16 = bf16(f0) [k even], high16 = bf16(f1) [k odd]} ----
__device__ __forceinline__ uint2 split_pack(float f0, float f1){
    unsigned hp;
    asm("cvt.rn.bf16x2.f32 %0, %1, %2;" : "=r"(hp) : "f"(f1), "f"(f0));
    float h0 = __uint_as_float(hp << 16);
    float h1 = __uint_as_float(hp & 0xFFFF0000u);
    unsigned lp;
    asm("cvt.rn.bf16x2.f32 %0, %1, %2;" : "=r"(lp) : "f"(f1 - h1), "f"(f0 - h0));
    return make_uint2(hp, lp);
}

// ---- mma.sync bf16 m16n8k16 ----
__device__ __forceinline__ void mma16(float* c, const unsigned* a, unsigned b0, unsigned b1){
    asm("mma.sync.aligned.m16n8k16.row.col.f32.bf16.bf16.f32 "
        "{%0,%1,%2,%3},{%4,%5,%6,%7},{%8,%9},{%0,%1,%2,%3};"
        : "+f"(c[0]), "+f"(c[1]), "+f"(c[2]), "+f"(c[3])
        : "r"(a[0]), "r"(a[1]), "r"(a[2]), "r"(a[3]), "r"(b0), "r"(b1));
}

// block reduction for 128 threads (4 warps)
__device__ __forceinline__ float blkred128(float v, volatile float* red){
    #pragma unroll
    for (int o = 16; o > 0; o >>= 1) v += __shfl_xor_sync(0xffffffffu, v, o);
    if ((threadIdx.x & 31) == 0) red[threadIdx.x >> 5] = v;
    __syncthreads();
    v = red[0] + red[1] + red[2] + red[3];
    __syncthreads();
    return v;
}

// ---------------- K0: pre-split weights into bf16 hi/lo packed pairs ----------------
__global__ void k_wsplit(const float* __restrict__ Wd1, const float* __restrict__ Wd2){
    int n = blockIdx.x, kp = threadIdx.x;   // kp in [0,128)
    if (n < 256){
        float f0 = Wd1[(2*kp  )*256 + n];
        float f1 = Wd1[(2*kp+1)*256 + n];
        gW1s[n*128 + kp] = split_pack(f0, f1);
    } else {
        int n2 = n - 256;
        float f0 = Wd2[(2*kp  )*128 + n2];
        float f1 = Wd2[(2*kp+1)*128 + n2];
        gW2s[n2*128 + kp] = split_pack(f0, f1);
    }
}

// ---------------- K1: geometry + RBF filter mask ----------------
__global__ void k_geom(const int* __restrict__ z, const float* __restrict__ pos,
                       const float* __restrict__ Wef, const float* __restrict__ bef){
    int blk = blockIdx.x;
    int b = blk >> 6, i = blk & 63;
    int t = threadIdx.x;

    __shared__ float pos_s[NN][3];
    __shared__ int   z_s[NN];
    __shared__ float d_s[NN], ea_s[NN];
    __shared__ float ef_s[NN][EFD];
    __shared__ float Wef_s[EFD*HH];
    __shared__ float bef_s[HH];

    for (int r = t; r < EFD*HH; r += 128) Wef_s[r] = Wef[r];
    bef_s[t] = bef[t];
    if (t < NN){
        z_s[t] = z[b*NN + t];
        pos_s[t][0] = pos[(b*NN + t)*3 + 0];
        pos_s[t][1] = pos[(b*NN + t)*3 + 1];
        pos_s[t][2] = pos[(b*NN + t)*3 + 2];
    }
    __syncthreads();

    if (t < NN){
        int j = t;
        float dx = pos_s[j][0] - pos_s[i][0];
        float dy = pos_s[j][1] - pos_s[i][1];
        float dz = pos_s[j][2] - pos_s[i][2];
        float d2 = dx*dx + dy*dy + dz*dz;
        float d  = sqrtf(fmaxf(d2, 1e-12f));
        d_s[j] = d;
        bool pair = (z_s[i] != 0) && (z_s[j] != 0) && (j != i);
        float ea = (pair && d < CUT) ? 0.5f*(cosf(3.14159265358979323846f * d / CUT) + 1.0f) : 0.0f;
        ea_s[j] = ea;
        g_ea[blk*NN + j] = ea;
        float inv = 1.0f / d;
        g_ev[(blk*NN + j)*3 + 0] = pair ? dx*inv : 0.0f;
        g_ev[(blk*NN + j)*3 + 1] = pair ? dy*inv : 0.0f;
        g_ev[(blk*NN + j)*3 + 2] = pair ? dz*inv : 0.0f;
    }
    __syncthreads();

    const float step = CUT / (float)(EFD - 1);
    for (int r = t; r < NN*EFD; r += 128){
        int j = r >> 5, k = r & 31;
        float dd = d_s[j] - step*(float)k;
        ef_s[j][k] = exp2n_f(-14.4269504089f * dd * dd);
    }
    __syncthreads();

    int h = t;
    for (int j = 0; j < NN; j++){
        float acc = bef_s[h];
        #pragma unroll
        for (int k = 0; k < EFD; k++)
            acc = fmaf(ef_s[j][k], Wef_s[k*HH + h], acc);
        g_mask[(blk*NN + j)*HH + h] = silu_f(acc) * ea_s[j];
    }
}

// ---------------- K2a: s = emb[z];  sn = LN(emb2[z]) ----------------
__global__ void k_embed(const int* __restrict__ z, const float* __restrict__ emb_w,
                        const float* __restrict__ emb2_w){
    int a = blockIdx.x, h = threadIdx.x;
    __shared__ float red[4];
    int zi = z[a];
    g_s[a*HH + h] = emb_w[zi*HH + h];
    float x = emb2_w[zi*HH + h];
    float s1 = blkred128(x, red);
    float s2 = blkred128(x*x, red);
    float m = s1 * (1.0f/HH);
    float var = fmaxf(s2 * (1.0f/HH) - m*m, 0.0f);
    g_sn[a*HH + h] = (x - m) * rsqrtf(var + LN_EPS);
}

// ---------------- K2b / K6b: s += mask @ src (4 i-rows per block) ----------------
__global__ void k_gather(int sel){
    int blk = blockIdx.x;
    int b  = blk >> 4;
    int i0 = (blk & 15) * 4;
    int h  = threadIdx.x;
    const float* src = sel ? g_sl : g_sn;
    __shared__ float srcs[NN*HH];
    const float* sb = src + b*NN*HH;
    for (int r = h; r < NN*HH; r += 128) srcs[r] = sb[r];
    __syncthreads();
    const float* m0 = g_mask + ((b*NN + i0)*NN)*HH;
    float a0 = 0.f, a1 = 0.f, a2 = 0.f, a3 = 0.f;
    #pragma unroll 4
    for (int j = 0; j < NN; j++){
        float sv = srcs[j*HH + h];
        a0 = fmaf(m0[(0*NN + j)*HH + h], sv, a0);
        a1 = fmaf(m0[(1*NN + j)*HH + h], sv, a1);
        a2 = fmaf(m0[(2*NN + j)*HH + h], sv, a2);
        a3 = fmaf(m0[(3*NN + j)*HH + h], sv, a3);
    }
    g_s[(b*NN + i0 + 0)*HH + h] += a0;
    g_s[(b*NN + i0 + 1)*HH + h] += a1;
    g_s[(b*NN + i0 + 2)*HH + h] += a2;
    g_s[(b*NN + i0 + 3)*HH + h] += a3;
}

// ---------------- K3 / K6a: dst = silu(LN(s @ W + bias)), 4 atoms per block ----------------
__global__ void k_lin(const float* __restrict__ W, const float* __restrict__ bias,
                      int dst_sel){
    int blk = blockIdx.x;
    int h = threadIdx.x;
    __shared__ float xs[4][HH];
    __shared__ float ys[4][HH];
    __shared__ float mm[4], rr[4];
    for (int r = h; r < 4*HH; r += 128) ((float*)xs)[r] = g_s[blk*4*HH + r];
    __syncthreads();
    float bh = bias[h];
    float a0 = bh, a1 = bh, a2 = bh, a3 = bh;
    #pragma unroll 8
    for (int k = 0; k < HH; k++){
        float w = W[k*HH + h];
        a0 = fmaf(xs[0][k], w, a0);
        a1 = fmaf(xs[1][k], w, a1);
        a2 = fmaf(xs[2][k], w, a2);
        a3 = fmaf(xs[3][k], w, a3);
    }
    ys[0][h] = a0; ys[1][h] = a1; ys[2][h] = a2; ys[3][h] = a3;
    __syncthreads();
    {
        int w = h >> 5, l = h & 31;
        float s1 = 0.f, s2 = 0.f;
        #pragma unroll
        for (int c = l; c < HH; c += 32){ float v = ys[w][c]; s1 += v; s2 += v*v; }
        #pragma unroll
        for (int o = 16; o > 0; o >>= 1){
            s1 += __shfl_xor_sync(0xffffffffu, s1, o);
            s2 += __shfl_xor_sync(0xffffffffu, s2, o);
        }
        if (l == 0){
            float m = s1 * (1.0f/HH);
            float var = fmaxf(s2 * (1.0f/HH) - m*m, 0.0f);
            mm[w] = m; rr[w] = rsqrtf(var + LN_EPS);
        }
    }
    __syncthreads();
    float* dst = dst_sel ? g_sl : g_t;
    #pragma unroll
    for (int a = 0; a < 4; a++)
        dst[(blk*4 + a)*HH + h] = silu_f((ys[a][h] - mm[a]) * rr[a]);
}

// ---------------- K4a: v[i,c,h] = sum_j mask*t*ev (4 i-rows per block) ----------------
__global__ void k_v(){
    int blk = blockIdx.x;
    int b  = blk >> 4;
    int i0 = (blk & 15) * 4;
    int h  = threadIdx.x;
    __shared__ float ts[NN*HH];
    __shared__ float evl[4][NN*3];
    const float* tb = g_t + b*NN*HH;
    for (int r = h; r < NN*HH; r += 128) ts[r] = tb[r];
    for (int r = h; r < 4*NN*3; r += 128) ((float*)evl)[r] = g_ev[(b*NN + i0)*NN*3 + r];
    __syncthreads();
    const float* m0 = g_mask + ((b*NN + i0)*NN)*HH;
    float acc[4][3];
    #pragma unroll
    for (int i = 0; i < 4; i++){ acc[i][0]=0.f; acc[i][1]=0.f; acc[i][2]=0.f; }
    #pragma unroll 2
    for (int j = 0; j < NN; j++){
        float tv = ts[j*HH + h];
        #pragma unroll
        for (int i = 0; i < 4; i++){
            float m = m0[(i*NN + j)*HH + h] * tv;
            acc[i][0] = fmaf(m, evl[i][j*3+0], acc[i][0]);
            acc[i][1] = fmaf(m, evl[i][j*3+1], acc[i][1]);
            acc[i][2] = fmaf(m, evl[i][j*3+2], acc[i][2]);
        }
    }
    #pragma unroll
    for (int i = 0; i < 4; i++){
        int base = (b*NN + i0 + i)*3;
        g_v[(base + 0)*HH + h] = acc[i][0];
        g_v[(base + 1)*HH + h] = acc[i][1];
        g_v[(base + 2)*HH + h] = acc[i][2];
    }
}

// ---------------- K4b: vq = v@Wq, vk = v@Wk (8 rows per block) ----------------
__global__ void k_vqk(const float* __restrict__ Wq, const float* __restrict__ Wk){
    int blk = blockIdx.x;
    int h = threadIdx.x;
    __shared__ float vs[8][HH];
    for (int r = h; r < 8*HH; r += 128) ((float*)vs)[r] = g_v[blk*8*HH + r];
    __syncthreads();
    float aq[8], ak[8];
    #pragma unroll
    for (int r = 0; r < 8; r++){ aq[r] = 0.f; ak[r] = 0.f; }
    #pragma unroll 4
    for (int k = 0; k < HH; k++){
        float wq = Wq[k*HH + h];
        float wk = Wk[k*HH + h];
        #pragma unroll
        for (int r = 0; r < 8; r++){
            float v = vs[r][k];
            aq[r] = fmaf(v, wq, aq[r]);
            ak[r] = fmaf(v, wk, ak[r]);
        }
    }
    #pragma unroll
    for (int r = 0; r < 8; r++){
        g_vq[(blk*8 + r)*HH + h] = aq[r];
        g_vk[(blk*8 + r)*HH + h] = ak[r];
    }
}

// ---------------- K5: directional MLP, mma.sync bf16 hi/lo (3 products) ----------------
// One block per i-pair: M = 128 edges, GEMM1 128x256x256, GEMM2 128x128x256.
// 8 warps as 4(m) x 2(n): warp m-tile 32 rows, n-half 128 (GEMM1) / 64 (GEMM2).
// smem (u32 units): Ahl uint2[128][132] -> 33792 | Bhl uint2[256][36] -> 18432 | floats
#define SMEM_DIR_BYTES (54656*4)
__global__ void __launch_bounds__(256, 1) k_dir(const float* __restrict__ bd1,
                                                const float* __restrict__ bd2){
    extern __shared__ unsigned smu[];
    uint2* Ahl = (uint2*)smu;                    // [e][kp], stride 132
    uint2* Bhl = (uint2*)(smu + 33792);          // [n][kp'], stride 36
    float* b1s = (float*)(smu + 52224);
    float* b2s = (float*)(smu + 52480);
    float* eas = (float*)(smu + 52608);
    float* evs = (float*)(smu + 52736);
    float* vis = (float*)(smu + 53120);
    float* vks = (float*)(smu + 53888);

    int t = threadIdx.x, lane = t & 31, wid = t >> 5;
    int g = lane >> 2, tig = lane & 3;
    int bi0 = blockIdx.x * 2, bbase = bi0 & ~63;

    b1s[t] = bd1[t];
    if (t < 128) b2s[t] = bd2[t];
    if (t < 128) eas[t] = g_ea[bi0*64 + t];
    for (int r = t; r < 384; r += 256) evs[r] = g_ev[bi0*192 + r];
    for (int r = t; r < 768; r += 256){ vis[r] = g_v[bi0*384 + r]; vks[r] = g_vk[bi0*384 + r]; }
    __syncthreads();

    // ---- build dirf -> Ahl (packed bf16 hi/lo pairs) ----
    {
        int kp = t & 127, eh = t >> 7;           // e in [eh*64, eh*64+64)
        if (kp < 64){                            // dir2: h = 2kp, 2kp+1 ; i = eh
            int h0 = 2*kp;
            float va0 = vis[eh*384 + h0],     va1 = vis[eh*384 + 128 + h0],   va2 = vis[eh*384 + 256 + h0];
            float vb0 = vis[eh*384 + h0 + 1], vb1 = vis[eh*384 + 129 + h0],   vb2 = vis[eh*384 + 257 + h0];
            for (int j = 0; j < 64; j++){
                int e = eh*64 + j;
                float ea = eas[e];
                float e0 = evs[e*3], e1 = evs[e*3+1], e2 = evs[e*3+2];
                float f0 = (va0*e0 + va1*e1 + va2*e2) * ea;
                float f1 = (vb0*e0 + vb1*e1 + vb2*e2) * ea;
                Ahl[e*132 + kp] = split_pack(f0, f1);
            }
        } else {                                 // dir3: k = 128 + 2(kp-64), +1
            int kk = 2*(kp - 64);
            float u0 = vks[eh*384 + kk],     u1 = vks[eh*384 + 128 + kk], u2 = vks[eh*384 + 256 + kk];
            float w0 = vks[eh*384 + kk + 1], w1 = vks[eh*384 + 129 + kk], w2 = vks[eh*384 + 257 + kk];
            for (int j = 0; j < 64; j++){
                int e = eh*64 + j;
                float ea = eas[e];
                const float* vq = g_vq + (bbase + j)*384 + kk;
                float2 q0 = *(const float2*)vq;
                float2 q1 = *(const float2*)(vq + 128);
                float2 q2 = *(const float2*)(vq + 256);
                float f0 = (q0.x*u0 + q1.x*u1 + q2.x*u2) * ea;
                float f1 = (q0.y*w0 + q1.y*w1 + q2.y*w2) * ea;
                Ahl[e*132 + kp] = split_pack(f0, f1);
            }
        }
    }
    __syncthreads();

    int m0 = (wid & 3) * 32, nh = wid >> 1 >> 1 >> 1;  // nh = wid>>2? keep explicit below
    nh = wid >> 2;

    // ================= GEMM1: D1[128x256] = dirf @ Wd1 =================
    float acc1[2][16][4];
    #pragma unroll
    for (int ms = 0; ms < 2; ms++)
        #pragma unroll
        for (int nt = 0; nt < 16; nt++)
            #pragma unroll
            for (int q = 0; q < 4; q++) acc1[ms][nt][q] = 0.f;

    for (int c = 0; c < 4; c++){
        for (int r = t; r < 4096; r += 256){     // 256 rows x 16 uint4
            int n = r >> 4, q = r & 15;
            *(uint4*)&Bhl[n*36 + q*2] = *(const uint4*)&gW1s[n*128 + c*32 + q*2];
        }
        __syncthreads();
        #pragma unroll
        for (int ksl = 0; ksl < 4; ksl++){
            int kp0 = c*32 + ksl*8;
            int kb  = ksl*8;
            unsigned ah[2][4], al[2][4];
            #pragma unroll
            for (int ms = 0; ms < 2; ms++){
                int r0 = m0 + ms*16;
                uint2 p0 = Ahl[(r0+g  )*132 + kp0 + tig];
                uint2 p1 = Ahl[(r0+g+8)*132 + kp0 + tig];
                uint2 p2 = Ahl[(r0+g  )*132 + kp0 + tig + 4];
                uint2 p3 = Ahl[(r0+g+8)*132 + kp0 + tig + 4];
                ah[ms][0]=p0.x; al[ms][0]=p0.y; ah[ms][1]=p1.x; al[ms][1]=p1.y;
                ah[ms][2]=p2.x; al[ms][2]=p2.y; ah[ms][3]=p3.x; al[ms][3]=p3.y;
            }
            #pragma unroll
            for (int nt = 0; nt < 16; nt++){
                int n0 = nh*128 + nt*8;
                uint2 bp0 = Bhl[(n0+g)*36 + kb + tig];
                uint2 bp1 = Bhl[(n0+g)*36 + kb + tig + 4];
                #pragma unroll
                for (int ms = 0; ms < 2; ms++){
                    mma16(acc1[ms][nt], ah[ms], bp0.x, bp1.x);
                    mma16(acc1[ms][nt], al[ms], bp0.x, bp1.x);
                    mma16(acc1[ms][nt], ah[ms], bp0.y, bp1.y);
                }
            }
        }
        __syncthreads();
    }

    // ---- epilogue1: h1 = silu(D1 + b1) packed back into Ahl ----
    #pragma unroll
    for (int ms = 0; ms < 2; ms++){
        #pragma unroll
        for (int nt = 0; nt < 16; nt++){
            int n0 = nh*128 + nt*8;
            int c0 = n0 + 2*tig;
            int kph = c0 >> 1;
            int r0 = m0 + ms*16 + g;
            float y0 = silu_f(acc1[ms][nt][0] + b1s[c0]);
            float y1 = silu_f(acc1[ms][nt][1] + b1s[c0+1]);
            Ahl[r0*132 + kph] = split_pack(y0, y1);
            float y2 = silu_f(acc1[ms][nt][2] + b1s[c0]);
            float y3 = silu_f(acc1[ms][nt][3] + b1s[c0+1]);
            Ahl[(r0+8)*132 + kph] = split_pack(y2, y3);
        }
    }
    __syncthreads();

    // ================= GEMM2: D2[128x128] = h1 @ Wd2 =================
    float acc2[2][8][4];
    #pragma unroll
    for (int ms = 0; ms < 2; ms++)
        #pragma unroll
        for (int nt = 0; nt < 8; nt++)
            #pragma unroll
            for (int q = 0; q < 4; q++) acc2[ms][nt][q] = 0.f;

    for (int c = 0; c < 4; c++){
        for (int r = t; r < 2048; r += 256){     // 128 rows x 16 uint4
            int n = r >> 4, q = r & 15;
            *(uint4*)&Bhl[n*36 + q*2] = *(const uint4*)&gW2s[n*128 + c*32 + q*2];
        }
        __syncthreads();
        #pragma unroll
        for (int ksl = 0; ksl < 4; ksl++){
            int kp0 = c*32 + ksl*8;
            int kb  = ksl*8;
            unsigned ah[2][4], al[2][4];
            #pragma unroll
            for (int ms = 0; ms < 2; ms++){
                int r0 = m0 + ms*16;
                uint2 p0 = Ahl[(r0+g  )*132 + kp0 + tig];
                uint2 p1 = Ahl[(r0+g+8)*132 + kp0 + tig];
                uint2 p2 = Ahl[(r0+g  )*132 + kp0 + tig + 4];
                uint2 p3 = Ahl[(r0+g+8)*132 + kp0 + tig + 4];
                ah[ms][0]=p0.x; al[ms][0]=p0.y; ah[ms][1]=p1.x; al[ms][1]=p1.y;
                ah[ms][2]=p2.x; al[ms][2]=p2.y; ah[ms][3]=p3.x; al[ms][3]=p3.y;
            }
            #pragma unroll
            for (int nt = 0; nt < 8; nt++){
                int n0 = nh*64 + nt*8;
                uint2 bp0 = Bhl[(n0+g)*36 + kb + tig];
                uint2 bp1 = Bhl[(n0+g)*36 + kb + tig + 4];
                #pragma unroll
                for (int ms = 0; ms < 2; ms++){
                    mma16(acc2[ms][nt], ah[ms], bp0.x, bp1.x);
                    mma16(acc2[ms][nt], al[ms], bp0.x, bp1.x);
                    mma16(acc2[ms][nt], ah[ms], bp0.y, bp1.y);
                }
            }
        }
        __syncthreads();
    }

    // ---- epilogue2: mask *= silu(D2 + b2) ----
    #pragma unroll
    for (int ms = 0; ms < 2; ms++){
        #pragma unroll
        for (int nt = 0; nt < 8; nt++){
            int n0 = nh*64 + nt*8;
            int c0 = n0 + 2*tig;
            int e0 = m0 + ms*16 + g;
            long base0 = ((long)(bi0*64 + e0))*128 + c0;
            float2 mv = *(float2*)&g_mask[base0];
            mv.x *= silu_f(acc2[ms][nt][0] + b2s[c0]);
            mv.y *= silu_f(acc2[ms][nt][1] + b2s[c0+1]);
            *(float2*)&g_mask[base0] = mv;
            long base1 = base0 + 8L*128;
            float2 mw = *(float2*)&g_mask[base1];
            mw.x *= silu_f(acc2[ms][nt][2] + b2s[c0]);
            mw.y *= silu_f(acc2[ms][nt][3] + b2s[c0+1]);
            *(float2*)&g_mask[base1] = mw;
        }
    }
}

// ---------------- K7: readout ----------------
__global__ void k_out(const int* __restrict__ z, const float* __restrict__ Wo,
                      const float* __restrict__ bo, float* __restrict__ out){
    int b = blockIdx.x, h = threadIdx.x;
    __shared__ float red[4];
    float acc = 0.f;
    for (int i = 0; i < NN; i++)
        if (z[b*NN + i] != 0) acc += g_s[(b*NN + i)*HH + h];
    float part = acc * Wo[h];
    float tot = blkred128(part, red);
    if (h == 0) out[b] = tot + bo[0];
}

// ---------------- launch ----------------
extern "C" void kernel_launch(void* const* d_in, const int* in_sizes, int n_in,
                              void* d_out, int out_size){
    const int*   z      = (const int*)  d_in[0];
    const float* pos    = (const float*)d_in[1];
    const float* emb_w  = (const float*)d_in[2];
    const float* emb2_w = (const float*)d_in[3];
    const float* Wef    = (const float*)d_in[4];
    const float* bef    = (const float*)d_in[5];
    const float* Ws2v   = (const float*)d_in[6];
    const float* bs2v   = (const float*)d_in[7];
    const float* Wq     = (const float*)d_in[8];
    const float* Wk     = (const float*)d_in[9];
    const float* Wd1    = (const float*)d_in[10];
    const float* bd1    = (const float*)d_in[11];
    const float* Wd2    = (const float*)d_in[12];
    const float* bd2    = (const float*)d_in[13];
    const float* Wint   = (const float*)d_in[14];
    const float* bint   = (const float*)d_in[15];
    const float* Wo     = (const float*)d_in[16];
    const float* bo     = (const float*)d_in[17];
    float* out = (float*)d_out;

    cudaFuncSetAttribute(k_dir, cudaFuncAttributeMaxDynamicSharedMemorySize, SMEM_DIR_BYTES);

    k_wsplit<<<384, 128>>>(Wd1, Wd2);
    k_geom <<<BB*NN, 128>>>(z, pos, Wef, bef);
    k_embed<<<BB*NN, 128>>>(z, emb_w, emb2_w);
    k_gather<<<BB*NN/4, 128>>>(0);               // s += mask @ sn
    k_lin  <<<BB*NN/4, 128>>>(Ws2v, bs2v, 0);    // t = silu(LN(s@Ws2v+b))
    k_v    <<<BB*NN/4, 128>>>();
    k_vqk  <<<BB*NN*3/8, 128>>>(Wq, Wk);
    k_dir  <<<BB*NN/2, 256, SMEM_DIR_BYTES>>>(bd1, bd2);
    for (int l = 0; l < 3; l++){
        k_lin   <<<BB*NN/4, 128>>>(Wint + l*HH*HH, bint + l*HH, 1);  // sl
        k_gather<<<BB*NN/4, 128>>>(1);                                // s += mask @ sl
    }
    k_out<<<BB, 128>>>(z, Wo, bo, out);
}

// round 7
// speedup vs baseline: 1.9042x; 1.4506x over previous
#include <cuda_runtime.h>
#include <cuda_bf16.h>
#include <math.h>
#include <stdint.h>

#define BB 64
#define NN 64
#define HH 128
#define EFD 32
#define LN_EPS 1e-5f
#define CUT 10.0f

// ---------------- device scratch (no runtime allocation) ----------------
static __device__ float g_mask[BB*NN*NN*HH];   // 128 MB
static __device__ float g_ea  [BB*NN*NN];
static __device__ float g_ev  [BB*NN*NN*3];
static __device__ float g_s   [BB*NN*HH];
static __device__ float g_sn  [BB*NN*HH];
static __device__ float g_t   [BB*NN*HH];
static __device__ float g_v   [BB*NN*3*HH];
static __device__ float g_vq  [BB*NN*3*HH];
static __device__ float g_vk  [BB*NN*3*HH];
static __device__ float g_sl  [BB*NN*HH];
// fp16-packed weights: [n][kp] -> {f16(k=2kp), f16(k=2kp+1)}; W1 rows k>=128 pre-scaled x64
static __device__ unsigned gW1h[256*128];
static __device__ unsigned gW2h[128*128];

// ---- MUFU-free fast exp2 / silu ----
__device__ __forceinline__ float exp2_poly(float f){
    float p = 1.3333558e-3f;
    p = fmaf(p, f, 9.6181291e-3f);
    p = fmaf(p, f, 5.5504109e-2f);
    p = fmaf(p, f, 2.4022651e-1f);
    p = fmaf(p, f, 6.9314718e-1f);
    p = fmaf(p, f, 1.0f);
    return p;
}
__device__ __forceinline__ float exp2n_f(float t){
    t = fmaxf(t, -126.0f);
    float fn = t + 12582912.0f;
    float n  = fn - 12582912.0f;
    float f  = t - n;
    int ni = __float_as_int(fn) - 0x4B400000;
    float scale = __int_as_float((ni + 127) << 23);
    return exp2_poly(f) * scale;
}
__device__ __forceinline__ float silu_f(float x){
    float t = x * (-1.442695041f);
    t = fminf(fmaxf(t, -126.0f), 126.0f);
    float fn = t + 12582912.0f;
    float n  = fn - 12582912.0f;
    float f  = t - n;
    int ni = __float_as_int(fn) - 0x4B400000;
    float scale = __int_as_float((ni + 127) << 23);
    float e = exp2_poly(f) * scale;
    float d = 1.0f + e;
    int id = 0x7EF311C3 - __float_as_int(d);
    float y = __int_as_float(id);
    y = y * fmaf(-d, y, 2.0f);
    y = y * fmaf(-d, y, 2.0f);
    y = y * fmaf(-d, y, 2.0f);
    return x * y;
}

// ---- fp16 pack: {low16 = f16(f0) [k even], high16 = f16(f1) [k odd]} ----
__device__ __forceinline__ unsigned half_pack(float f0, float f1){
    unsigned p;
    asm("cvt.rn.f16x2.f32 %0, %1, %2;" : "=r"(p) : "f"(f1), "f"(f0));
    return p;
}

// ---- mma.sync fp16 m16n8k16, fp32 accumulate ----
__device__ __forceinline__ void mma16h(float* c, const unsigned* a, unsigned b0, unsigned b1){
    asm("mma.sync.aligned.m16n8k16.row.col.f32.f16.f16.f32 "
        "{%0,%1,%2,%3},{%4,%5,%6,%7},{%8,%9},{%0,%1,%2,%3};"
        : "+f"(c[0]), "+f"(c[1]), "+f"(c[2]), "+f"(c[3])
        : "r"(a[0]), "r"(a[1]), "r"(a[2]), "r"(a[3]), "r"(b0), "r"(b1));
}

// block reduction for 128 threads (4 warps)
__device__ __forceinline__ float blkred128(float v, volatile float* red){
    #pragma unroll
    for (int o = 16; o > 0; o >>= 1) v += __shfl_xor_sync(0xffffffffu, v, o);
    if ((threadIdx.x & 31) == 0) red[threadIdx.x >> 5] = v;
    __syncthreads();
    v = red[0] + red[1] + red[2] + red[3];
    __syncthreads();
    return v;
}

// ---------------- K0: convert weights to packed fp16 ----------------
__global__ void k_whalf(const float* __restrict__ Wd1, const float* __restrict__ Wd2){
    int n = blockIdx.x, kp = threadIdx.x;   // kp in [0,128)
    if (n < 256){
        float s = (kp >= 64) ? 64.0f : 1.0f;   // dir3 rows pre-scaled (dirf scaled 1/64)
        float f0 = Wd1[(2*kp  )*256 + n] * s;
        float f1 = Wd1[(2*kp+1)*256 + n] * s;
        gW1h[n*128 + kp] = half_pack(f0, f1);
    } else {
        int n2 = n - 256;
        float f0 = Wd2[(2*kp  )*128 + n2];
        float f1 = Wd2[(2*kp+1)*128 + n2];
        gW2h[n2*128 + kp] = half_pack(f0, f1);
    }
}

// ---------------- K1: geometry + RBF filter mask ----------------
__global__ void k_geom(const int* __restrict__ z, const float* __restrict__ pos,
                       const float* __restrict__ Wef, const float* __restrict__ bef){
    int blk = blockIdx.x;
    int b = blk >> 6, i = blk & 63;
    int t = threadIdx.x;

    __shared__ float pos_s[NN][3];
    __shared__ int   z_s[NN];
    __shared__ float d_s[NN], ea_s[NN];
    __shared__ float ef_s[NN][EFD];
    __shared__ float Wef_s[EFD*HH];
    __shared__ float bef_s[HH];

    for (int r = t; r < EFD*HH; r += 128) Wef_s[r] = Wef[r];
    bef_s[t] = bef[t];
    if (t < NN){
        z_s[t] = z[b*NN + t];
        pos_s[t][0] = pos[(b*NN + t)*3 + 0];
        pos_s[t][1] = pos[(b*NN + t)*3 + 1];
        pos_s[t][2] = pos[(b*NN + t)*3 + 2];
    }
    __syncthreads();

    if (t < NN){
        int j = t;
        float dx = pos_s[j][0] - pos_s[i][0];
        float dy = pos_s[j][1] - pos_s[i][1];
        float dz = pos_s[j][2] - pos_s[i][2];
        float d2 = dx*dx + dy*dy + dz*dz;
        float d  = sqrtf(fmaxf(d2, 1e-12f));
        d_s[j] = d;
        bool pair = (z_s[i] != 0) && (z_s[j] != 0) && (j != i);
        float ea = (pair && d < CUT) ? 0.5f*(cosf(3.14159265358979323846f * d / CUT) + 1.0f) : 0.0f;
        ea_s[j] = ea;
        g_ea[blk*NN + j] = ea;
        float inv = 1.0f / d;
        g_ev[(blk*NN + j)*3 + 0] = pair ? dx*inv : 0.0f;
        g_ev[(blk*NN + j)*3 + 1] = pair ? dy*inv : 0.0f;
        g_ev[(blk*NN + j)*3 + 2] = pair ? dz*inv : 0.0f;
    }
    __syncthreads();

    const float step = CUT / (float)(EFD - 1);
    for (int r = t; r < NN*EFD; r += 128){
        int j = r >> 5, k = r & 31;
        float dd = d_s[j] - step*(float)k;
        ef_s[j][k] = exp2n_f(-14.4269504089f * dd * dd);
    }
    __syncthreads();

    int h = t;
    for (int j = 0; j < NN; j++){
        float acc = bef_s[h];
        #pragma unroll
        for (int k = 0; k < EFD; k++)
            acc = fmaf(ef_s[j][k], Wef_s[k*HH + h], acc);
        g_mask[(blk*NN + j)*HH + h] = silu_f(acc) * ea_s[j];
    }
}

// ---------------- K2a: s = emb[z];  sn = LN(emb2[z]) ----------------
__global__ void k_embed(const int* __restrict__ z, const float* __restrict__ emb_w,
                        const float* __restrict__ emb2_w){
    int a = blockIdx.x, h = threadIdx.x;
    __shared__ float red[4];
    int zi = z[a];
    g_s[a*HH + h] = emb_w[zi*HH + h];
    float x = emb2_w[zi*HH + h];
    float s1 = blkred128(x, red);
    float s2 = blkred128(x*x, red);
    float m = s1 * (1.0f/HH);
    float var = fmaxf(s2 * (1.0f/HH) - m*m, 0.0f);
    g_sn[a*HH + h] = (x - m) * rsqrtf(var + LN_EPS);
}

// ---------------- K2b / K6b: s += mask @ src (4 i-rows per block) ----------------
__global__ void k_gather(int sel){
    int blk = blockIdx.x;
    int b  = blk >> 4;
    int i0 = (blk & 15) * 4;
    int h  = threadIdx.x;
    const float* src = sel ? g_sl : g_sn;
    __shared__ float srcs[NN*HH];
    const float* sb = src + b*NN*HH;
    for (int r = h; r < NN*HH; r += 128) srcs[r] = sb[r];
    __syncthreads();
    const float* m0 = g_mask + ((b*NN + i0)*NN)*HH;
    float a0 = 0.f, a1 = 0.f, a2 = 0.f, a3 = 0.f;
    #pragma unroll 4
    for (int j = 0; j < NN; j++){
        float sv = srcs[j*HH + h];
        a0 = fmaf(m0[(0*NN + j)*HH + h], sv, a0);
        a1 = fmaf(m0[(1*NN + j)*HH + h], sv, a1);
        a2 = fmaf(m0[(2*NN + j)*HH + h], sv, a2);
        a3 = fmaf(m0[(3*NN + j)*HH + h], sv, a3);
    }
    g_s[(b*NN + i0 + 0)*HH + h] += a0;
    g_s[(b*NN + i0 + 1)*HH + h] += a1;
    g_s[(b*NN + i0 + 2)*HH + h] += a2;
    g_s[(b*NN + i0 + 3)*HH + h] += a3;
}

// ---------------- K3 / K6a: dst = silu(LN(s @ W + bias)), 4 atoms per block ----------------
__global__ void k_lin(const float* __restrict__ W, const float* __restrict__ bias,
                      int dst_sel){
    int blk = blockIdx.x;
    int h = threadIdx.x;
    __shared__ float xs[4][HH];
    __shared__ float ys[4][HH];
    __shared__ float mm[4], rr[4];
    for (int r = h; r < 4*HH; r += 128) ((float*)xs)[r] = g_s[blk*4*HH + r];
    __syncthreads();
    float bh = bias[h];
    float a0 = bh, a1 = bh, a2 = bh, a3 = bh;
    #pragma unroll 8
    for (int k = 0; k < HH; k++){
        float w = W[k*HH + h];
        a0 = fmaf(xs[0][k], w, a0);
        a1 = fmaf(xs[1][k], w, a1);
        a2 = fmaf(xs[2][k], w, a2);
        a3 = fmaf(xs[3][k], w, a3);
    }
    ys[0][h] = a0; ys[1][h] = a1; ys[2][h] = a2; ys[3][h] = a3;
    __syncthreads();
    {
        int w = h >> 5, l = h & 31;
        float s1 = 0.f, s2 = 0.f;
        #pragma unroll
        for (int c = l; c < HH; c += 32){ float v = ys[w][c]; s1 += v; s2 += v*v; }
        #pragma unroll
        for (int o = 16; o > 0; o >>= 1){
            s1 += __shfl_xor_sync(0xffffffffu, s1, o);
            s2 += __shfl_xor_sync(0xffffffffu, s2, o);
        }
        if (l == 0){
            float m = s1 * (1.0f/HH);
            float var = fmaxf(s2 * (1.0f/HH) - m*m, 0.0f);
            mm[w] = m; rr[w] = rsqrtf(var + LN_EPS);
        }
    }
    __syncthreads();
    float* dst = dst_sel ? g_sl : g_t;
    #pragma unroll
    for (int a = 0; a < 4; a++)
        dst[(blk*4 + a)*HH + h] = silu_f((ys[a][h] - mm[a]) * rr[a]);
}

// ---------------- K4a: v[i,c,h] = sum_j mask*t*ev (4 i-rows per block) ----------------
__global__ void k_v(){
    int blk = blockIdx.x;
    int b  = blk >> 4;
    int i0 = (blk & 15) * 4;
    int h  = threadIdx.x;
    __shared__ float ts[NN*HH];
    __shared__ float evl[4][NN*3];
    const float* tb = g_t + b*NN*HH;
    for (int r = h; r < NN*HH; r += 128) ts[r] = tb[r];
    for (int r = h; r < 4*NN*3; r += 128) ((float*)evl)[r] = g_ev[(b*NN + i0)*NN*3 + r];
    __syncthreads();
    const float* m0 = g_mask + ((b*NN + i0)*NN)*HH;
    float acc[4][3];
    #pragma unroll
    for (int i = 0; i < 4; i++){ acc[i][0]=0.f; acc[i][1]=0.f; acc[i][2]=0.f; }
    #pragma unroll 2
    for (int j = 0; j < NN; j++){
        float tv = ts[j*HH + h];
        #pragma unroll
        for (int i = 0; i < 4; i++){
            float m = m0[(i*NN + j)*HH + h] * tv;
            acc[i][0] = fmaf(m, evl[i][j*3+0], acc[i][0]);
            acc[i][1] = fmaf(m, evl[i][j*3+1], acc[i][1]);
            acc[i][2] = fmaf(m, evl[i][j*3+2], acc[i][2]);
        }
    }
    #pragma unroll
    for (int i = 0; i < 4; i++){
        int base = (b*NN + i0 + i)*3;
        g_v[(base + 0)*HH + h] = acc[i][0];
        g_v[(base + 1)*HH + h] = acc[i][1];
        g_v[(base + 2)*HH + h] = acc[i][2];
    }
}

// ---------------- K4b: vq = v@Wq, vk = v@Wk (8 rows per block) ----------------
__global__ void k_vqk(const float* __restrict__ Wq, const float* __restrict__ Wk){
    int blk = blockIdx.x;
    int h = threadIdx.x;
    __shared__ float vs[8][HH];
    for (int r = h; r < 8*HH; r += 128) ((float*)vs)[r] = g_v[blk*8*HH + r];
    __syncthreads();
    float aq[8], ak[8];
    #pragma unroll
    for (int r = 0; r < 8; r++){ aq[r] = 0.f; ak[r] = 0.f; }
    #pragma unroll 4
    for (int k = 0; k < HH; k++){
        float wq = Wq[k*HH + h];
        float wk = Wk[k*HH + h];
        #pragma unroll
        for (int r = 0; r < 8; r++){
            float v = vs[r][k];
            aq[r] = fmaf(v, wq, aq[r]);
            ak[r] = fmaf(v, wk, ak[r]);
        }
    }
    #pragma unroll
    for (int r = 0; r < 8; r++){
        g_vq[(blk*8 + r)*HH + h] = aq[r];
        g_vk[(blk*8 + r)*HH + h] = ak[r];
    }
}

// ---------------- K5: directional MLP, single-product fp16 mma.sync ----------------
// One block per i-pair: M = 128 edges, GEMM1 128x256x256, GEMM2 128x128x256.
// 8 warps as 4(m) x 2(n). smem words: Ah[128][132]=16896 | Bh[256][36]=9216 | b1s 256 | b2s 128
#define SMEM_DIR_BYTES (26496*4)
__global__ void __launch_bounds__(256) k_dir(const float* __restrict__ bd1,
                                             const float* __restrict__ bd2){
    extern __shared__ unsigned smu[];
    unsigned* Ah = smu;                          // [e][kp], stride 132 (fp16 pairs)
    unsigned* Bh = smu + 16896;                  // [n][kp'], stride 36
    float* b1s = (float*)(smu + 26112);
    float* b2s = (float*)(smu + 26368);
    // build-phase scratch overlaps Bh (dead before first staging)
    float* eas = (float*)(Bh);                   // 128
    float* evs = (float*)(Bh + 128);             // 384
    float* vis = (float*)(Bh + 512);             // 768
    float* vks = (float*)(Bh + 1280);            // 768

    int t = threadIdx.x, lane = t & 31, wid = t >> 5;
    int g = lane >> 2, tig = lane & 3;
    int bi0 = blockIdx.x * 2, bbase = bi0 & ~63;

    b1s[t] = bd1[t];
    if (t < 128) b2s[t] = bd2[t];
    if (t < 128) eas[t] = g_ea[bi0*64 + t];
    for (int r = t; r < 384; r += 256) evs[r] = g_ev[bi0*192 + r];
    for (int r = t; r < 768; r += 256){ vis[r] = g_v[bi0*384 + r]; vks[r] = g_vk[bi0*384 + r]; }
    __syncthreads();

    // ---- build dirf -> Ah (fp16 pairs); dir3 half scaled by 1/64 ----
    {
        int kp = t & 127, eh = t >> 7;           // e in [eh*64, eh*64+64)
        if (kp < 64){                            // dir2: h = 2kp, 2kp+1 ; i = eh
            int h0 = 2*kp;
            float va0 = vis[eh*384 + h0],     va1 = vis[eh*384 + 128 + h0], va2 = vis[eh*384 + 256 + h0];
            float vb0 = vis[eh*384 + h0 + 1], vb1 = vis[eh*384 + 129 + h0], vb2 = vis[eh*384 + 257 + h0];
            for (int j = 0; j < 64; j++){
                int e = eh*64 + j;
                float ea = eas[e];
                float e0 = evs[e*3], e1 = evs[e*3+1], e2 = evs[e*3+2];
                float f0 = (va0*e0 + va1*e1 + va2*e2) * ea;
                float f1 = (vb0*e0 + vb1*e1 + vb2*e2) * ea;
                Ah[e*132 + kp] = half_pack(f0, f1);
            }
        } else {                                 // dir3: k = 128 + 2(kp-64), +1; scale 1/64
            int kk = 2*(kp - 64);
            float u0 = vks[eh*384 + kk],     u1 = vks[eh*384 + 128 + kk], u2 = vks[eh*384 + 256 + kk];
            float w0 = vks[eh*384 + kk + 1], w1 = vks[eh*384 + 129 + kk], w2 = vks[eh*384 + 257 + kk];
            for (int j = 0; j < 64; j++){
                int e = eh*64 + j;
                float ea = eas[e] * 0.015625f;   // /64
                const float* vq = g_vq + (bbase + j)*384 + kk;
                float2 q0 = *(const float2*)vq;
                float2 q1 = *(const float2*)(vq + 128);
                float2 q2 = *(const float2*)(vq + 256);
                float f0 = (q0.x*u0 + q1.x*u1 + q2.x*u2) * ea;
                float f1 = (q0.y*w0 + q1.y*w1 + q2.y*w2) * ea;
                Ah[e*132 + kp] = half_pack(f0, f1);
            }
        }
    }
    __syncthreads();

    int m0 = (wid & 3) * 32;
    int nh = wid >> 2;

    // ================= GEMM1: D1[128x256] = dirf @ Wd1 =================
    float acc1[2][16][4];
    #pragma unroll
    for (int ms = 0; ms < 2; ms++)
        #pragma unroll
        for (int nt = 0; nt < 16; nt++)
            #pragma unroll
            for (int q = 0; q < 4; q++) acc1[ms][nt][q] = 0.f;

    for (int c = 0; c < 4; c++){
        for (int r = t; r < 2048; r += 256){     // 256 rows x 8 uint4
            int n = r >> 3, q = r & 7;
            *(uint4*)&Bh[n*36 + q*4] = *(const uint4*)&gW1h[n*128 + c*32 + q*4];
        }
        __syncthreads();
        #pragma unroll
        for (int ksl = 0; ksl < 4; ksl++){
            int kp0 = c*32 + ksl*8;
            int kb  = ksl*8;
            unsigned ah[2][4];
            #pragma unroll
            for (int ms = 0; ms < 2; ms++){
                int r0 = m0 + ms*16;
                ah[ms][0] = Ah[(r0+g  )*132 + kp0 + tig];
                ah[ms][1] = Ah[(r0+g+8)*132 + kp0 + tig];
                ah[ms][2] = Ah[(r0+g  )*132 + kp0 + tig + 4];
                ah[ms][3] = Ah[(r0+g+8)*132 + kp0 + tig + 4];
            }
            #pragma unroll
            for (int nt = 0; nt < 16; nt++){
                int n0 = nh*128 + nt*8;
                unsigned b0 = Bh[(n0+g)*36 + kb + tig];
                unsigned b1 = Bh[(n0+g)*36 + kb + tig + 4];
                mma16h(acc1[0][nt], ah[0], b0, b1);
                mma16h(acc1[1][nt], ah[1], b0, b1);
            }
        }
        __syncthreads();
    }

    // ---- epilogue1: h1 = silu(D1 + b1) packed back into Ah ----
    #pragma unroll
    for (int ms = 0; ms < 2; ms++){
        #pragma unroll
        for (int nt = 0; nt < 16; nt++){
            int n0 = nh*128 + nt*8;
            int c0 = n0 + 2*tig;
            int kph = c0 >> 1;
            int r0 = m0 + ms*16 + g;
            float y0 = silu_f(acc1[ms][nt][0] + b1s[c0]);
            float y1 = silu_f(acc1[ms][nt][1] + b1s[c0+1]);
            Ah[r0*132 + kph] = half_pack(y0, y1);
            float y2 = silu_f(acc1[ms][nt][2] + b1s[c0]);
            float y3 = silu_f(acc1[ms][nt][3] + b1s[c0+1]);
            Ah[(r0+8)*132 + kph] = half_pack(y2, y3);
        }
    }
    __syncthreads();

    // ================= GEMM2: D2[128x128] = h1 @ Wd2 =================
    float acc2[2][8][4];
    #pragma unroll
    for (int ms = 0; ms < 2; ms++)
        #pragma unroll
        for (int nt = 0; nt < 8; nt++)
            #pragma unroll
            for (int q = 0; q < 4; q++) acc2[ms][nt][q] = 0.f;

    for (int c = 0; c < 4; c++){
        for (int r = t; r < 1024; r += 256){     // 128 rows x 8 uint4
            int n = r >> 3, q = r & 7;
            *(uint4*)&Bh[n*36 + q*4] = *(const uint4*)&gW2h[n*128 + c*32 + q*4];
        }
        __syncthreads();
        #pragma unroll
        for (int ksl = 0; ksl < 4; ksl++){
            int kp0 = c*32 + ksl*8;
            int kb  = ksl*8;
            unsigned ah[2][4];
            #pragma unroll
            for (int ms = 0; ms < 2; ms++){
                int r0 = m0 + ms*16;
                ah[ms][0] = Ah[(r0+g  )*132 + kp0 + tig];
                ah[ms][1] = Ah[(r0+g+8)*132 + kp0 + tig];
                ah[ms][2] = Ah[(r0+g  )*132 + kp0 + tig + 4];
                ah[ms][3] = Ah[(r0+g+8)*132 + kp0 + tig + 4];
            }
            #pragma unroll
            for (int nt = 0; nt < 8; nt++){
                int n0 = nh*64 + nt*8;
                unsigned b0 = Bh[(n0+g)*36 + kb + tig];
                unsigned b1 = Bh[(n0+g)*36 + kb + tig + 4];
                mma16h(acc2[0][nt], ah[0], b0, b1);
                mma16h(acc2[1][nt], ah[1], b0, b1);
            }
        }
        __syncthreads();
    }

    // ---- epilogue2: mask *= silu(D2 + b2) ----
    #pragma unroll
    for (int ms = 0; ms < 2; ms++){
        #pragma unroll
        for (int nt = 0; nt < 8; nt++){
            int n0 = nh*64 + nt*8;
            int c0 = n0 + 2*tig;
            int e0 = m0 + ms*16 + g;
            long base0 = ((long)(bi0*64 + e0))*128 + c0;
            float2 mv = *(float2*)&g_mask[base0];
            mv.x *= silu_f(acc2[ms][nt][0] + b2s[c0]);
            mv.y *= silu_f(acc2[ms][nt][1] + b2s[c0+1]);
            *(float2*)&g_mask[base0] = mv;
            long base1 = base0 + 8L*128;
            float2 mw = *(float2*)&g_mask[base1];
            mw.x *= silu_f(acc2[ms][nt][2] + b2s[c0]);
            mw.y *= silu_f(acc2[ms][nt][3] + b2s[c0+1]);
            *(float2*)&g_mask[base1] = mw;
        }
    }
}

// ---------------- K7: readout ----------------
__global__ void k_out(const int* __restrict__ z, const float* __restrict__ Wo,
                      const float* __restrict__ bo, float* __restrict__ out){
    int b = blockIdx.x, h = threadIdx.x;
    __shared__ float red[4];
    float acc = 0.f;
    for (int i = 0; i < NN; i++)
        if (z[b*NN + i] != 0) acc += g_s[(b*NN + i)*HH + h];
    float part = acc * Wo[h];
    float tot = blkred128(part, red);
    if (h == 0) out[b] = tot + bo[0];
}

// ---------------- launch ----------------
extern "C" void kernel_launch(void* const* d_in, const int* in_sizes, int n_in,
                              void* d_out, int out_size){
    const int*   z      = (const int*)  d_in[0];
    const float* pos    = (const float*)d_in[1];
    const float* emb_w  = (const float*)d_in[2];
    const float* emb2_w = (const float*)d_in[3];
    const float* Wef    = (const float*)d_in[4];
    const float* bef    = (const float*)d_in[5];
    const float* Ws2v   = (const float*)d_in[6];
    const float* bs2v   = (const float*)d_in[7];
    const float* Wq     = (const float*)d_in[8];
    const float* Wk     = (const float*)d_in[9];
    const float* Wd1    = (const float*)d_in[10];
    const float* bd1    = (const float*)d_in[11];
    const float* Wd2    = (const float*)d_in[12];
    const float* bd2    = (const float*)d_in[13];
    const float* Wint   = (const float*)d_in[14];
    const float* bint   = (const float*)d_in[15];
    const float* Wo     = (const float*)d_in[16];
    const float* bo     = (const float*)d_in[17];
    float* out = (float*)d_out;

    cudaFuncSetAttribute(k_dir, cudaFuncAttributeMaxDynamicSharedMemorySize, SMEM_DIR_BYTES);

    k_whalf<<<384, 128>>>(Wd1, Wd2);
    k_geom <<<BB*NN, 128>>>(z, pos, Wef, bef);
    k_embed<<<BB*NN, 128>>>(z, emb_w, emb2_w);
    k_gather<<<BB*NN/4, 128>>>(0);               // s += mask @ sn
    k_lin  <<<BB*NN/4, 128>>>(Ws2v, bs2v, 0);    // t = silu(LN(s@Ws2v+b))
    k_v    <<<BB*NN/4, 128>>>();
    k_vqk  <<<BB*NN*3/8, 128>>>(Wq, Wk);
    k_dir  <<<BB*NN/2, 256, SMEM_DIR_BYTES>>>(bd1, bd2);
    for (int l = 0; l < 3; l++){
        k_lin   <<<BB*NN/4, 128>>>(Wint + l*HH*HH, bint + l*HH, 1);  // sl
        k_gather<<<BB*NN/4, 128>>>(1);                                // s += mask @ sl
    }
    k_out<<<BB, 128>>>(z, Wo, bo, out);
}

// round 8
// speedup vs baseline: 2.3965x; 1.2585x over previous
#include <cuda_runtime.h>
#include <cuda_fp16.h>
#include <math.h>
#include <stdint.h>

#define BB 64
#define NN 64
#define HH 128
#define EFD 32
#define LN_EPS 1e-5f
#define CUT 10.0f

// ---------------- device scratch (no runtime allocation) ----------------
static __device__ __half g_maskh[BB*NN*NN*HH]; // 64 MB fp16 mask
static __device__ float g_ea  [BB*NN*NN];
static __device__ float g_ev  [BB*NN*NN*3];
static __device__ float g_s   [BB*NN*HH];
static __device__ float g_sn  [BB*NN*HH];
static __device__ float g_t   [BB*NN*HH];
static __device__ float g_v   [BB*NN*3*HH];
static __device__ float g_vq  [BB*NN*3*HH];
static __device__ float g_vk  [BB*NN*3*HH];
static __device__ float g_sl  [BB*NN*HH];
static __device__ float g_P   [BB*NN*3*256];   // P_i = V_i @ Wd1[0:128] (dir2 low-rank path)
// fp16-packed weights: gW1h3 = Wd1 dir3 rows (128..255) pre-scaled x64: [n][kp<64]
static __device__ unsigned gW1h3[256*64];
static __device__ unsigned gW2h [128*128];

// ---- MUFU-free fast exp2 / silu ----
__device__ __forceinline__ float exp2_poly(float f){
    float p = 1.3333558e-3f;
    p = fmaf(p, f, 9.6181291e-3f);
    p = fmaf(p, f, 5.5504109e-2f);
    p = fmaf(p, f, 2.4022651e-1f);
    p = fmaf(p, f, 6.9314718e-1f);
    p = fmaf(p, f, 1.0f);
    return p;
}
__device__ __forceinline__ float exp2n_f(float t){
    t = fmaxf(t, -126.0f);
    float fn = t + 12582912.0f;
    float n  = fn - 12582912.0f;
    float f  = t - n;
    int ni = __float_as_int(fn) - 0x4B400000;
    float scale = __int_as_float((ni + 127) << 23);
    return exp2_poly(f) * scale;
}
__device__ __forceinline__ float silu_f(float x){
    float t = x * (-1.442695041f);
    t = fminf(fmaxf(t, -126.0f), 126.0f);
    float fn = t + 12582912.0f;
    float n  = fn - 12582912.0f;
    float f  = t - n;
    int ni = __float_as_int(fn) - 0x4B400000;
    float scale = __int_as_float((ni + 127) << 23);
    float e = exp2_poly(f) * scale;
    float d = 1.0f + e;
    int id = 0x7EF311C3 - __float_as_int(d);
    float y = __int_as_float(id);
    y = y * fmaf(-d, y, 2.0f);
    y = y * fmaf(-d, y, 2.0f);
    y = y * fmaf(-d, y, 2.0f);
    return x * y;
}

// ---- fp16 pack: {low16 = f16(f0), high16 = f16(f1)} ----
__device__ __forceinline__ unsigned half_pack(float f0, float f1){
    unsigned p;
    asm("cvt.rn.f16x2.f32 %0, %1, %2;" : "=r"(p) : "f"(f1), "f"(f0));
    return p;
}

// ---- mma.sync fp16 m16n8k16, fp32 accumulate ----
__device__ __forceinline__ void mma16h(float* c, const unsigned* a, unsigned b0, unsigned b1){
    asm("mma.sync.aligned.m16n8k16.row.col.f32.f16.f16.f32 "
        "{%0,%1,%2,%3},{%4,%5,%6,%7},{%8,%9},{%0,%1,%2,%3};"
        : "+f"(c[0]), "+f"(c[1]), "+f"(c[2]), "+f"(c[3])
        : "r"(a[0]), "r"(a[1]), "r"(a[2]), "r"(a[3]), "r"(b0), "r"(b1));
}

// block reduction for 128 threads (4 warps)
__device__ __forceinline__ float blkred128(float v, volatile float* red){
    #pragma unroll
    for (int o = 16; o > 0; o >>= 1) v += __shfl_xor_sync(0xffffffffu, v, o);
    if ((threadIdx.x & 31) == 0) red[threadIdx.x >> 5] = v;
    __syncthreads();
    v = red[0] + red[1] + red[2] + red[3];
    __syncthreads();
    return v;
}

// ---------------- K0: convert weights to packed fp16 ----------------
__global__ void k_whalf(const float* __restrict__ Wd1, const float* __restrict__ Wd2){
    int n = blockIdx.x, kp = threadIdx.x;
    if (n < 256){
        if (kp < 64){   // dir3 rows of Wd1, pre-scaled x64
            float f0 = Wd1[(128 + 2*kp    )*256 + n] * 64.0f;
            float f1 = Wd1[(128 + 2*kp + 1)*256 + n] * 64.0f;
            gW1h3[n*64 + kp] = half_pack(f0, f1);
        }
    } else {
        int n2 = n - 256;
        float f0 = Wd2[(2*kp  )*128 + n2];
        float f1 = Wd2[(2*kp+1)*128 + n2];
        gW2h[n2*128 + kp] = half_pack(f0, f1);
    }
}

// ---------------- K0b: P_i = V_i @ Wd1[0:128]  (3 x 256 per atom, fp32) ----------------
__global__ void k_p(const float* __restrict__ Wd1){
    int bi = blockIdx.x, n = threadIdx.x;      // 256 threads = n
    __shared__ float vs[3*HH];
    for (int r = n; r < 3*HH; r += 256) vs[r] = g_v[bi*3*HH + r];
    __syncthreads();
    float p0 = 0.f, p1 = 0.f, p2 = 0.f;
    #pragma unroll 4
    for (int k = 0; k < HH; k++){
        float w = Wd1[k*256 + n];
        p0 = fmaf(vs[k],        w, p0);
        p1 = fmaf(vs[HH + k],   w, p1);
        p2 = fmaf(vs[2*HH + k], w, p2);
    }
    g_P[bi*768 + n]       = p0;
    g_P[bi*768 + 256 + n] = p1;
    g_P[bi*768 + 512 + n] = p2;
}

// ---------------- K1: geometry + RBF filter mask (fp16 out) ----------------
__global__ void k_geom(const int* __restrict__ z, const float* __restrict__ pos,
                       const float* __restrict__ Wef, const float* __restrict__ bef){
    int blk = blockIdx.x;
    int b = blk >> 6, i = blk & 63;
    int t = threadIdx.x;

    __shared__ float pos_s[NN][3];
    __shared__ int   z_s[NN];
    __shared__ float d_s[NN], ea_s[NN];
    __shared__ float ef_s[NN][EFD];
    __shared__ float Wef_s[EFD*HH];
    __shared__ float bef_s[HH];

    for (int r = t; r < EFD*HH; r += 128) Wef_s[r] = Wef[r];
    bef_s[t] = bef[t];
    if (t < NN){
        z_s[t] = z[b*NN + t];
        pos_s[t][0] = pos[(b*NN + t)*3 + 0];
        pos_s[t][1] = pos[(b*NN + t)*3 + 1];
        pos_s[t][2] = pos[(b*NN + t)*3 + 2];
    }
    __syncthreads();

    if (t < NN){
        int j = t;
        float dx = pos_s[j][0] - pos_s[i][0];
        float dy = pos_s[j][1] - pos_s[i][1];
        float dz = pos_s[j][2] - pos_s[i][2];
        float d2 = dx*dx + dy*dy + dz*dz;
        float d  = sqrtf(fmaxf(d2, 1e-12f));
        d_s[j] = d;
        bool pair = (z_s[i] != 0) && (z_s[j] != 0) && (j != i);
        float ea = (pair && d < CUT) ? 0.5f*(cosf(3.14159265358979323846f * d / CUT) + 1.0f) : 0.0f;
        ea_s[j] = ea;
        g_ea[blk*NN + j] = ea;
        float inv = 1.0f / d;
        g_ev[(blk*NN + j)*3 + 0] = pair ? dx*inv : 0.0f;
        g_ev[(blk*NN + j)*3 + 1] = pair ? dy*inv : 0.0f;
        g_ev[(blk*NN + j)*3 + 2] = pair ? dz*inv : 0.0f;
    }
    __syncthreads();

    const float step = CUT / (float)(EFD - 1);
    for (int r = t; r < NN*EFD; r += 128){
        int j = r >> 5, k = r & 31;
        float dd = d_s[j] - step*(float)k;
        ef_s[j][k] = exp2n_f(-14.4269504089f * dd * dd);
    }
    __syncthreads();

    int h = t;
    for (int j = 0; j < NN; j++){
        float acc = bef_s[h];
        #pragma unroll
        for (int k = 0; k < EFD; k++)
            acc = fmaf(ef_s[j][k], Wef_s[k*HH + h], acc);
        g_maskh[(size_t)(blk*NN + j)*HH + h] = __float2half(silu_f(acc) * ea_s[j]);
    }
}

// ---------------- K2a: s = emb[z];  sn = LN(emb2[z]) ----------------
__global__ void k_embed(const int* __restrict__ z, const float* __restrict__ emb_w,
                        const float* __restrict__ emb2_w){
    int a = blockIdx.x, h = threadIdx.x;
    __shared__ float red[4];
    int zi = z[a];
    g_s[a*HH + h] = emb_w[zi*HH + h];
    float x = emb2_w[zi*HH + h];
    float s1 = blkred128(x, red);
    float s2 = blkred128(x*x, red);
    float m = s1 * (1.0f/HH);
    float var = fmaxf(s2 * (1.0f/HH) - m*m, 0.0f);
    g_sn[a*HH + h] = (x - m) * rsqrtf(var + LN_EPS);
}

// ---------------- K2b / K6b: s += mask @ src (8 i-rows per block, fp16 mask) ----------------
__global__ void k_gather(int sel){
    int blk = blockIdx.x;              // (b, i-group of 8)
    int b  = blk >> 3;
    int i0 = (blk & 7) * 8;
    int t  = threadIdx.x;
    int h  = t & 127, rh = t >> 7;     // rh in {0,1}: rows rh*4 .. rh*4+3
    const float* src = sel ? g_sl : g_sn;
    __shared__ float srcs[NN*HH];
    const float* sb = src + b*NN*HH;
    for (int r = t; r < NN*HH; r += 256) srcs[r] = sb[r];
    __syncthreads();
    const __half* m0 = g_maskh + (size_t)((b*NN + i0 + rh*4)*NN)*HH;
    float a0 = 0.f, a1 = 0.f, a2 = 0.f, a3 = 0.f;
    #pragma unroll 4
    for (int j = 0; j < NN; j++){
        float sv = srcs[j*HH + h];
        a0 = fmaf(__half2float(m0[(size_t)(0*NN + j)*HH + h]), sv, a0);
        a1 = fmaf(__half2float(m0[(size_t)(1*NN + j)*HH + h]), sv, a1);
        a2 = fmaf(__half2float(m0[(size_t)(2*NN + j)*HH + h]), sv, a2);
        a3 = fmaf(__half2float(m0[(size_t)(3*NN + j)*HH + h]), sv, a3);
    }
    int base = b*NN + i0 + rh*4;
    g_s[(base + 0)*HH + h] += a0;
    g_s[(base + 1)*HH + h] += a1;
    g_s[(base + 2)*HH + h] += a2;
    g_s[(base + 3)*HH + h] += a3;
}

// ---------------- K3 / K6a: dst = silu(LN(s @ W + bias)), 4 atoms per block ----------------
__global__ void k_lin(const float* __restrict__ W, const float* __restrict__ bias,
                      int dst_sel){
    int blk = blockIdx.x;
    int h = threadIdx.x;
    __shared__ float xs[4][HH];
    __shared__ float ys[4][HH];
    __shared__ float mm[4], rr[4];
    for (int r = h; r < 4*HH; r += 128) ((float*)xs)[r] = g_s[blk*4*HH + r];
    __syncthreads();
    float bh = bias[h];
    float a0 = bh, a1 = bh, a2 = bh, a3 = bh;
    #pragma unroll 8
    for (int k = 0; k < HH; k++){
        float w = W[k*HH + h];
        a0 = fmaf(xs[0][k], w, a0);
        a1 = fmaf(xs[1][k], w, a1);
        a2 = fmaf(xs[2][k], w, a2);
        a3 = fmaf(xs[3][k], w, a3);
    }
    ys[0][h] = a0; ys[1][h] = a1; ys[2][h] = a2; ys[3][h] = a3;
    __syncthreads();
    {
        int w = h >> 5, l = h & 31;
        float s1 = 0.f, s2 = 0.f;
        #pragma unroll
        for (int c = l; c < HH; c += 32){ float v = ys[w][c]; s1 += v; s2 += v*v; }
        #pragma unroll
        for (int o = 16; o > 0; o >>= 1){
            s1 += __shfl_xor_sync(0xffffffffu, s1, o);
            s2 += __shfl_xor_sync(0xffffffffu, s2, o);
        }
        if (l == 0){
            float m = s1 * (1.0f/HH);
            float var = fmaxf(s2 * (1.0f/HH) - m*m, 0.0f);
            mm[w] = m; rr[w] = rsqrtf(var + LN_EPS);
        }
    }
    __syncthreads();
    float* dst = dst_sel ? g_sl : g_t;
    #pragma unroll
    for (int a = 0; a < 4; a++)
        dst[(blk*4 + a)*HH + h] = silu_f((ys[a][h] - mm[a]) * rr[a]);
}

// ---------------- K4a: v[i,c,h] = sum_j mask*t*ev (4 i-rows per block, fp16 mask) ----------------
__global__ void k_v(){
    int blk = blockIdx.x;
    int b  = blk >> 4;
    int i0 = (blk & 15) * 4;
    int h  = threadIdx.x;
    __shared__ float ts[NN*HH];
    __shared__ float evl[4][NN*3];
    const float* tb = g_t + b*NN*HH;
    for (int r = h; r < NN*HH; r += 128) ts[r] = tb[r];
    for (int r = h; r < 4*NN*3; r += 128) ((float*)evl)[r] = g_ev[(b*NN + i0)*NN*3 + r];
    __syncthreads();
    const __half* m0 = g_maskh + (size_t)((b*NN + i0)*NN)*HH;
    float acc[4][3];
    #pragma unroll
    for (int i = 0; i < 4; i++){ acc[i][0]=0.f; acc[i][1]=0.f; acc[i][2]=0.f; }
    #pragma unroll 2
    for (int j = 0; j < NN; j++){
        float tv = ts[j*HH + h];
        #pragma unroll
        for (int i = 0; i < 4; i++){
            float m = __half2float(m0[(size_t)(i*NN + j)*HH + h]) * tv;
            acc[i][0] = fmaf(m, evl[i][j*3+0], acc[i][0]);
            acc[i][1] = fmaf(m, evl[i][j*3+1], acc[i][1]);
            acc[i][2] = fmaf(m, evl[i][j*3+2], acc[i][2]);
        }
    }
    #pragma unroll
    for (int i = 0; i < 4; i++){
        int base = (b*NN + i0 + i)*3;
        g_v[(base + 0)*HH + h] = acc[i][0];
        g_v[(base + 1)*HH + h] = acc[i][1];
        g_v[(base + 2)*HH + h] = acc[i][2];
    }
}

// ---------------- K4b: vq = v@Wq, vk = v@Wk (8 rows per block) ----------------
__global__ void k_vqk(const float* __restrict__ Wq, const float* __restrict__ Wk){
    int blk = blockIdx.x;
    int h = threadIdx.x;
    __shared__ float vs[8][HH];
    for (int r = h; r < 8*HH; r += 128) ((float*)vs)[r] = g_v[blk*8*HH + r];
    __syncthreads();
    float aq[8], ak[8];
    #pragma unroll
    for (int r = 0; r < 8; r++){ aq[r] = 0.f; ak[r] = 0.f; }
    #pragma unroll 4
    for (int k = 0; k < HH; k++){
        float wq = Wq[k*HH + h];
        float wk = Wk[k*HH + h];
        #pragma unroll
        for (int r = 0; r < 8; r++){
            float v = vs[r][k];
            aq[r] = fmaf(v, wq, aq[r]);
            ak[r] = fmaf(v, wk, ak[r]);
        }
    }
    #pragma unroll
    for (int r = 0; r < 8; r++){
        g_vq[(blk*8 + r)*HH + h] = aq[r];
        g_vk[(blk*8 + r)*HH + h] = ak[r];
    }
}

// ---------------- K5: directional MLP ----------------
// GEMM1 dir3-half on fp16 mma (K=128); dir2 contribution injected via fp32 low-rank init.
// One block per i-pair: M = 128 edges. 8 warps as 4(m) x 2(n).
// smem words: Ah[128][132]=16896 | Bh 9216 | b1s 256 | b2s 128
#define SMEM_DIR_BYTES (26496*4)
__global__ void __launch_bounds__(256) k_dir(const float* __restrict__ bd1,
                                             const float* __restrict__ bd2){
    extern __shared__ unsigned smu[];
    unsigned* Ah = smu;                          // [e][kp], stride 132 (fp16 pairs)
    unsigned* Bh = smu + 16896;                  // staging [n][kp'], stride 36
    float* b1s = (float*)(smu + 26112);
    float* b2s = (float*)(smu + 26368);
    // pre-GEMM scratch overlaps Bh (dead before first staging)
    float* eas = (float*)(Bh);                   // 128
    float* evs = (float*)(Bh + 128);             // 384
    float* vks = (float*)(Bh + 512);             // 768
    float* Ps  = (float*)(Bh + 1280);            // 1536 (2 x 3 x 256)

    int t = threadIdx.x, lane = t & 31, wid = t >> 5;
    int g = lane >> 2, tig = lane & 3;
    int bi0 = blockIdx.x * 2, bbase = bi0 & ~63;

    b1s[t] = bd1[t];
    if (t < 128) b2s[t] = bd2[t];
    if (t < 128) eas[t] = g_ea[bi0*64 + t];
    for (int r = t; r < 384;  r += 256) evs[r] = g_ev[bi0*192 + r];
    for (int r = t; r < 768;  r += 256) vks[r] = g_vk[bi0*384 + r];
    for (int r = t; r < 1536; r += 256) Ps [r] = g_P [bi0*768 + r];
    __syncthreads();

    // ---- build dir3 (scaled 1/64) -> Ah kp 0..63 ----
    {
        int kp3 = t & 63, eh = t >> 6;           // eh: i = eh&1, j-half = eh>>1
        int i  = eh & 1, jh = eh >> 1;
        int kk = 2*kp3;
        float u0 = vks[i*384 + kk],     u1 = vks[i*384 + 128 + kk], u2 = vks[i*384 + 256 + kk];
        float w0 = vks[i*384 + kk + 1], w1 = vks[i*384 + 129 + kk], w2 = vks[i*384 + 257 + kk];
        for (int jj = 0; jj < 32; jj++){
            int j = jh*32 + jj;
            int e = i*64 + j;
            float ea = eas[e] * 0.015625f;       // /64
            const float* vq = g_vq + (bbase + j)*384 + kk;
            float2 q0 = *(const float2*)vq;
            float2 q1 = *(const float2*)(vq + 128);
            float2 q2 = *(const float2*)(vq + 256);
            float f0 = (q0.x*u0 + q1.x*u1 + q2.x*u2) * ea;
            float f1 = (q0.y*w0 + q1.y*w1 + q2.y*w2) * ea;
            Ah[e*132 + kp3] = half_pack(f0, f1);
        }
    }

    int m0 = (wid & 3) * 32;
    int nh = wid >> 2;

    // ---- init acc1 with dir2 low-rank contribution: ea[e] * (ev[e] . P_i[:, n]) ----
    float acc1[2][16][4];
    #pragma unroll
    for (int ms = 0; ms < 2; ms++){
        int ea_r = m0 + ms*16 + g;
        int eb_r = ea_r + 8;
        int ia = ea_r >> 6, ib = eb_r >> 6;
        float ca0 = evs[ea_r*3], ca1 = evs[ea_r*3+1], ca2 = evs[ea_r*3+2];
        float cb0 = evs[eb_r*3], cb1 = evs[eb_r*3+1], cb2 = evs[eb_r*3+2];
        float wa = eas[ea_r], wb = eas[eb_r];
        const float* Pa = Ps + ia*768;
        const float* Pb = Ps + ib*768;
        #pragma unroll
        for (int nt = 0; nt < 16; nt++){
            int c0 = nh*128 + nt*8 + 2*tig;
            acc1[ms][nt][0] = wa * (ca0*Pa[c0]     + ca1*Pa[256+c0]     + ca2*Pa[512+c0]);
            acc1[ms][nt][1] = wa * (ca0*Pa[c0+1]   + ca1*Pa[256+c0+1]   + ca2*Pa[512+c0+1]);
            acc1[ms][nt][2] = wb * (cb0*Pb[c0]     + cb1*Pb[256+c0]     + cb2*Pb[512+c0]);
            acc1[ms][nt][3] = wb * (cb0*Pb[c0+1]   + cb1*Pb[256+c0+1]   + cb2*Pb[512+c0+1]);
        }
    }
    __syncthreads();

    // ================= GEMM1 (dir3 half): K=128, 2 staged chunks =================
    for (int c = 0; c < 2; c++){
        for (int r = t; r < 2048; r += 256){     // 256 n x 8 uint4
            int n = r >> 3, q = r & 7;
            *(uint4*)&Bh[n*36 + q*4] = *(const uint4*)&gW1h3[n*64 + c*32 + q*4];
        }
        __syncthreads();
        #pragma unroll
        for (int ksl = 0; ksl < 4; ksl++){
            int kp0 = c*32 + ksl*8;
            int kb  = ksl*8;
            unsigned ah[2][4];
            #pragma unroll
            for (int ms = 0; ms < 2; ms++){
                int r0 = m0 + ms*16;
                ah[ms][0] = Ah[(r0+g  )*132 + kp0 + tig];
                ah[ms][1] = Ah[(r0+g+8)*132 + kp0 + tig];
                ah[ms][2] = Ah[(r0+g  )*132 + kp0 + tig + 4];
                ah[ms][3] = Ah[(r0+g+8)*132 + kp0 + tig + 4];
            }
            #pragma unroll
            for (int nt = 0; nt < 16; nt++){
                int n0 = nh*128 + nt*8;
                unsigned b0 = Bh[(n0+g)*36 + kb + tig];
                unsigned b1 = Bh[(n0+g)*36 + kb + tig + 4];
                mma16h(acc1[0][nt], ah[0], b0, b1);
                mma16h(acc1[1][nt], ah[1], b0, b1);
            }
        }
        __syncthreads();
    }

    // ---- epilogue1: h1 = silu(D1 + b1) packed back into Ah (kp 0..127) ----
    #pragma unroll
    for (int ms = 0; ms < 2; ms++){
        #pragma unroll
        for (int nt = 0; nt < 16; nt++){
            int n0 = nh*128 + nt*8;
            int c0 = n0 + 2*tig;
            int kph = c0 >> 1;
            int r0 = m0 + ms*16 + g;
            float y0 = silu_f(acc1[ms][nt][0] + b1s[c0]);
            float y1 = silu_f(acc1[ms][nt][1] + b1s[c0+1]);
            Ah[r0*132 + kph] = half_pack(y0, y1);
            float y2 = silu_f(acc1[ms][nt][2] + b1s[c0]);
            float y3 = silu_f(acc1[ms][nt][3] + b1s[c0+1]);
            Ah[(r0+8)*132 + kph] = half_pack(y2, y3);
        }
    }
    __syncthreads();

    // ================= GEMM2: D2[128x128] = h1 @ Wd2, K=256 =================
    float acc2[2][8][4];
    #pragma unroll
    for (int ms = 0; ms < 2; ms++)
        #pragma unroll
        for (int nt = 0; nt < 8; nt++)
            #pragma unroll
            for (int q = 0; q < 4; q++) acc2[ms][nt][q] = 0.f;

    for (int c = 0; c < 4; c++){
        for (int r = t; r < 1024; r += 256){     // 128 n x 8 uint4
            int n = r >> 3, q = r & 7;
            *(uint4*)&Bh[n*36 + q*4] = *(const uint4*)&gW2h[n*128 + c*32 + q*4];
        }
        __syncthreads();
        #pragma unroll
        for (int ksl = 0; ksl < 4; ksl++){
            int kp0 = c*32 + ksl*8;
            int kb  = ksl*8;
            unsigned ah[2][4];
            #pragma unroll
            for (int ms = 0; ms < 2; ms++){
                int r0 = m0 + ms*16;
                ah[ms][0] = Ah[(r0+g  )*132 + kp0 + tig];
                ah[ms][1] = Ah[(r0+g+8)*132 + kp0 + tig];
                ah[ms][2] = Ah[(r0+g  )*132 + kp0 + tig + 4];
                ah[ms][3] = Ah[(r0+g+8)*132 + kp0 + tig + 4];
            }
            #pragma unroll
            for (int nt = 0; nt < 8; nt++){
                int n0 = nh*64 + nt*8;
                unsigned b0 = Bh[(n0+g)*36 + kb + tig];
                unsigned b1 = Bh[(n0+g)*36 + kb + tig + 4];
                mma16h(acc2[0][nt], ah[0], b0, b1);
                mma16h(acc2[1][nt], ah[1], b0, b1);
            }
        }
        __syncthreads();
    }

    // ---- epilogue2: maskh *= silu(D2 + b2) (fp16 RMW via half2) ----
    #pragma unroll
    for (int ms = 0; ms < 2; ms++){
        #pragma unroll
        for (int nt = 0; nt < 8; nt++){
            int n0 = nh*64 + nt*8;
            int c0 = n0 + 2*tig;
            int e0 = m0 + ms*16 + g;
            size_t base0 = ((size_t)(bi0*64 + e0))*128 + c0;
            __half2* p0 = (__half2*)&g_maskh[base0];
            float2 mv = __half22float2(*p0);
            mv.x *= silu_f(acc2[ms][nt][0] + b2s[c0]);
            mv.y *= silu_f(acc2[ms][nt][1] + b2s[c0+1]);
            *p0 = __float22half2_rn(mv);
            __half2* p1 = (__half2*)&g_maskh[base0 + 8*128];
            float2 mw = __half22float2(*p1);
            mw.x *= silu_f(acc2[ms][nt][2] + b2s[c0]);
            mw.y *= silu_f(acc2[ms][nt][3] + b2s[c0+1]);
            *p1 = __float22half2_rn(mw);
        }
    }
}

// ---------------- K7: readout ----------------
__global__ void k_out(const int* __restrict__ z, const float* __restrict__ Wo,
                      const float* __restrict__ bo, float* __restrict__ out){
    int b = blockIdx.x, h = threadIdx.x;
    __shared__ float red[4];
    float acc = 0.f;
    for (int i = 0; i < NN; i++)
        if (z[b*NN + i] != 0) acc += g_s[(b*NN + i)*HH + h];
    float part = acc * Wo[h];
    float tot = blkred128(part, red);
    if (h == 0) out[b] = tot + bo[0];
}

// ---------------- launch ----------------
extern "C" void kernel_launch(void* const* d_in, const int* in_sizes, int n_in,
                              void* d_out, int out_size){
    const int*   z      = (const int*)  d_in[0];
    const float* pos    = (const float*)d_in[1];
    const float* emb_w  = (const float*)d_in[2];
    const float* emb2_w = (const float*)d_in[3];
    const float* Wef    = (const float*)d_in[4];
    const float* bef    = (const float*)d_in[5];
    const float* Ws2v   = (const float*)d_in[6];
    const float* bs2v   = (const float*)d_in[7];
    const float* Wq     = (const float*)d_in[8];
    const float* Wk     = (const float*)d_in[9];
    const float* Wd1    = (const float*)d_in[10];
    const float* bd1    = (const float*)d_in[11];
    const float* Wd2    = (const float*)d_in[12];
    const float* bd2    = (const float*)d_in[13];
    const float* Wint   = (const float*)d_in[14];
    const float* bint   = (const float*)d_in[15];
    const float* Wo     = (const float*)d_in[16];
    const float* bo     = (const float*)d_in[17];
    float* out = (float*)d_out;

    cudaFuncSetAttribute(k_dir, cudaFuncAttributeMaxDynamicSharedMemorySize, SMEM_DIR_BYTES);

    k_whalf<<<384, 128>>>(Wd1, Wd2);
    k_geom <<<BB*NN, 128>>>(z, pos, Wef, bef);
    k_embed<<<BB*NN, 128>>>(z, emb_w, emb2_w);
    k_gather<<<BB*NN/8, 256>>>(0);               // s += mask @ sn
    k_lin  <<<BB*NN/4, 128>>>(Ws2v, bs2v, 0);    // t = silu(LN(s@Ws2v+b))
    k_v    <<<BB*NN/4, 128>>>();
    k_vqk  <<<BB*NN*3/8, 128>>>(Wq, Wk);
    k_p    <<<BB*NN, 256>>>(Wd1);
    k_dir  <<<BB*NN/2, 256, SMEM_DIR_BYTES>>>(bd1, bd2);
    for (int l = 0; l < 3; l++){
        k_lin   <<<BB*NN/4, 128>>>(Wint + l*HH*HH, bint + l*HH, 1);  // sl
        k_gather<<<BB*NN/8, 256>>>(1);                                // s += mask @ sl
    }
    k_out<<<BB, 128>>>(z, Wo, bo, out);
}

// round 9
// speedup vs baseline: 2.5783x; 1.0758x over previous
#include <cuda_runtime.h>
#include <cuda_fp16.h>
#include <math.h>
#include <stdint.h>

#define BB 64
#define NN 64
#define HH 128
#define EFD 32
#define LN_EPS 1e-5f
#define CUT 10.0f

// ---------------- device scratch (no runtime allocation) ----------------
static __device__ __half g_maskh[BB*NN*NN*HH]; // 64 MB fp16 mask
static __device__ float g_ea  [BB*NN*NN];
static __device__ float g_ev  [BB*NN*NN*3];
static __device__ float g_s   [BB*NN*HH];
static __device__ float g_sn  [BB*NN*HH];
static __device__ float g_t   [BB*NN*HH];
static __device__ float g_v   [BB*NN*3*HH];
static __device__ float g_vq  [BB*NN*3*HH];
static __device__ float g_vk  [BB*NN*3*HH];
static __device__ float g_sl  [BB*NN*HH];
static __device__ float g_P   [BB*NN*3*256];   // P_i = V_i @ Wd1[0:128]
static __device__ unsigned gW1h3[256*64];      // Wd1 dir3 rows packed fp16 (x64)
static __device__ unsigned gW2h [128*128];

// ---- MUFU-free fast exp2 / silu ----
__device__ __forceinline__ float exp2_poly(float f){
    float p = 1.3333558e-3f;
    p = fmaf(p, f, 9.6181291e-3f);
    p = fmaf(p, f, 5.5504109e-2f);
    p = fmaf(p, f, 2.4022651e-1f);
    p = fmaf(p, f, 6.9314718e-1f);
    p = fmaf(p, f, 1.0f);
    return p;
}
__device__ __forceinline__ float exp2n_f(float t){
    t = fmaxf(t, -126.0f);
    float fn = t + 12582912.0f;
    float n  = fn - 12582912.0f;
    float f  = t - n;
    int ni = __float_as_int(fn) - 0x4B400000;
    float scale = __int_as_float((ni + 127) << 23);
    return exp2_poly(f) * scale;
}
__device__ __forceinline__ float silu_f(float x){
    float t = x * (-1.442695041f);
    t = fminf(fmaxf(t, -126.0f), 126.0f);
    float fn = t + 12582912.0f;
    float n  = fn - 12582912.0f;
    float f  = t - n;
    int ni = __float_as_int(fn) - 0x4B400000;
    float scale = __int_as_float((ni + 127) << 23);
    float e = exp2_poly(f) * scale;
    float d = 1.0f + e;
    int id = 0x7EF311C3 - __float_as_int(d);
    float y = __int_as_float(id);
    y = y * fmaf(-d, y, 2.0f);
    y = y * fmaf(-d, y, 2.0f);
    y = y * fmaf(-d, y, 2.0f);
    return x * y;
}

// ---- fp16 pack: {low16 = f16(f0), high16 = f16(f1)} ----
__device__ __forceinline__ unsigned half_pack(float f0, float f1){
    unsigned p;
    asm("cvt.rn.f16x2.f32 %0, %1, %2;" : "=r"(p) : "f"(f1), "f"(f0));
    return p;
}

// ---- mma.sync fp16 m16n8k16, fp32 accumulate ----
__device__ __forceinline__ void mma16h(float* c, const unsigned* a, unsigned b0, unsigned b1){
    asm("mma.sync.aligned.m16n8k16.row.col.f32.f16.f16.f32 "
        "{%0,%1,%2,%3},{%4,%5,%6,%7},{%8,%9},{%0,%1,%2,%3};"
        : "+f"(c[0]), "+f"(c[1]), "+f"(c[2]), "+f"(c[3])
        : "r"(a[0]), "r"(a[1]), "r"(a[2]), "r"(a[3]), "r"(b0), "r"(b1));
}

// block reduction for 128 threads (4 warps)
__device__ __forceinline__ float blkred128(float v, volatile float* red){
    #pragma unroll
    for (int o = 16; o > 0; o >>= 1) v += __shfl_xor_sync(0xffffffffu, v, o);
    if ((threadIdx.x & 31) == 0) red[threadIdx.x >> 5] = v;
    __syncthreads();
    v = red[0] + red[1] + red[2] + red[3];
    __syncthreads();
    return v;
}

// ---------------- K0: convert weights to packed fp16 ----------------
__global__ void k_whalf(const float* __restrict__ Wd1, const float* __restrict__ Wd2){
    int n = blockIdx.x, kp = threadIdx.x;
    if (n < 256){
        if (kp < 64){
            float f0 = Wd1[(128 + 2*kp    )*256 + n] * 64.0f;
            float f1 = Wd1[(128 + 2*kp + 1)*256 + n] * 64.0f;
            gW1h3[n*64 + kp] = half_pack(f0, f1);
        }
    } else {
        int n2 = n - 256;
        float f0 = Wd2[(2*kp  )*128 + n2];
        float f1 = Wd2[(2*kp+1)*128 + n2];
        gW2h[n2*128 + kp] = half_pack(f0, f1);
    }
}

// ---------------- K0b: P_i = V_i @ Wd1[0:128]  (3 x 256 per atom, fp32) ----------------
__global__ void k_p(const float* __restrict__ Wd1){
    int bi = blockIdx.x, n = threadIdx.x;
    __shared__ float vs[3*HH];
    for (int r = n; r < 3*HH; r += 256) vs[r] = g_v[bi*3*HH + r];
    __syncthreads();
    float p0 = 0.f, p1 = 0.f, p2 = 0.f;
    #pragma unroll 4
    for (int k = 0; k < HH; k++){
        float w = Wd1[k*256 + n];
        p0 = fmaf(vs[k],        w, p0);
        p1 = fmaf(vs[HH + k],   w, p1);
        p2 = fmaf(vs[2*HH + k], w, p2);
    }
    g_P[bi*768 + n]       = p0;
    g_P[bi*768 + 256 + n] = p1;
    g_P[bi*768 + 512 + n] = p2;
}

// ---------------- K1: geometry + RBF filter mask (half2-vectorized writes) ----------------
__global__ void k_geom(const int* __restrict__ z, const float* __restrict__ pos,
                       const float* __restrict__ Wef, const float* __restrict__ bef){
    int blk = blockIdx.x;
    int b = blk >> 6, i = blk & 63;
    int t = threadIdx.x;

    __shared__ float pos_s[NN][3];
    __shared__ int   z_s[NN];
    __shared__ float d_s[NN], ea_s[NN];
    __shared__ float ef_s[NN][EFD];
    __shared__ float Wef_s[EFD*HH];
    __shared__ float bef_s[HH];

    for (int r = t; r < EFD*HH; r += 128) Wef_s[r] = Wef[r];
    bef_s[t] = bef[t];
    if (t < NN){
        z_s[t] = z[b*NN + t];
        pos_s[t][0] = pos[(b*NN + t)*3 + 0];
        pos_s[t][1] = pos[(b*NN + t)*3 + 1];
        pos_s[t][2] = pos[(b*NN + t)*3 + 2];
    }
    __syncthreads();

    if (t < NN){
        int j = t;
        float dx = pos_s[j][0] - pos_s[i][0];
        float dy = pos_s[j][1] - pos_s[i][1];
        float dz = pos_s[j][2] - pos_s[i][2];
        float d2 = dx*dx + dy*dy + dz*dz;
        float d  = sqrtf(fmaxf(d2, 1e-12f));
        d_s[j] = d;
        bool pair = (z_s[i] != 0) && (z_s[j] != 0) && (j != i);
        float ea = (pair && d < CUT) ? 0.5f*(cosf(3.14159265358979323846f * d / CUT) + 1.0f) : 0.0f;
        ea_s[j] = ea;
        g_ea[blk*NN + j] = ea;
        float inv = 1.0f / d;
        g_ev[(blk*NN + j)*3 + 0] = pair ? dx*inv : 0.0f;
        g_ev[(blk*NN + j)*3 + 1] = pair ? dy*inv : 0.0f;
        g_ev[(blk*NN + j)*3 + 2] = pair ? dz*inv : 0.0f;
    }
    __syncthreads();

    const float step = CUT / (float)(EFD - 1);
    for (int r = t; r < NN*EFD; r += 128){
        int j = r >> 5, k = r & 31;
        float dd = d_s[j] - step*(float)k;
        ef_s[j][k] = exp2n_f(-14.4269504089f * dd * dd);
    }
    __syncthreads();

    // thread t: h pair (2*(t&63), +1), j range (t>>6)*32 ..
    int hp = t & 63, jh = t >> 6;
    int h0 = 2*hp;
    __half2* mrow = (__half2*)(g_maskh + (size_t)blk*NN*HH);
    for (int jj = 0; jj < 32; jj++){
        int j = jh*32 + jj;
        float a0 = bef_s[h0], a1 = bef_s[h0+1];
        #pragma unroll
        for (int k = 0; k < EFD; k++){
            float e = ef_s[j][k];
            a0 = fmaf(e, Wef_s[k*HH + h0],     a0);
            a1 = fmaf(e, Wef_s[k*HH + h0 + 1], a1);
        }
        float ea = ea_s[j];
        float2 m; m.x = silu_f(a0) * ea; m.y = silu_f(a1) * ea;
        mrow[j*64 + hp] = __float22half2_rn(m);
    }
}

// ---------------- K2a: s = emb[z];  sn = LN(emb2[z]) ----------------
__global__ void k_embed(const int* __restrict__ z, const float* __restrict__ emb_w,
                        const float* __restrict__ emb2_w){
    int a = blockIdx.x, h = threadIdx.x;
    __shared__ float red[4];
    int zi = z[a];
    g_s[a*HH + h] = emb_w[zi*HH + h];
    float x = emb2_w[zi*HH + h];
    float s1 = blkred128(x, red);
    float s2 = blkred128(x*x, red);
    float m = s1 * (1.0f/HH);
    float var = fmaxf(s2 * (1.0f/HH) - m*m, 0.0f);
    g_sn[a*HH + h] = (x - m) * rsqrtf(var + LN_EPS);
}

// ---------------- K2b / K6b: s += mask @ src (8 i-rows/block, half2 loads) ----------------
__global__ void k_gather(int sel){
    int blk = blockIdx.x;              // (b, i-group of 8)
    int b  = blk >> 3;
    int i0 = (blk & 7) * 8;
    int t  = threadIdx.x;              // 256
    int h2 = t & 63;                   // half2 column (h = 2*h2)
    int rg = t >> 6;                   // 0..3 -> rows rg*2, rg*2+1
    const float* src = sel ? g_sl : g_sn;
    __shared__ float srcs[NN*HH];
    const float* sb = src + b*NN*HH;
    for (int r = t; r < NN*HH; r += 256) srcs[r] = sb[r];
    __syncthreads();
    const __half2* m0 = (const __half2*)(g_maskh + (size_t)((b*NN + i0 + rg*2)*NN)*HH);
    float2 a0 = make_float2(0.f, 0.f), a1 = make_float2(0.f, 0.f);
    #pragma unroll 4
    for (int j = 0; j < NN; j++){
        float2 sv = *(const float2*)&srcs[j*HH + 2*h2];
        float2 q0 = __half22float2(m0[j*64 + h2]);
        float2 q1 = __half22float2(m0[4096 + j*64 + h2]);
        a0.x = fmaf(q0.x, sv.x, a0.x); a0.y = fmaf(q0.y, sv.y, a0.y);
        a1.x = fmaf(q1.x, sv.x, a1.x); a1.y = fmaf(q1.y, sv.y, a1.y);
    }
    int base = b*NN + i0 + rg*2;
    float2* sp0 = (float2*)&g_s[(base + 0)*HH + 2*h2];
    float2 s0 = *sp0; s0.x += a0.x; s0.y += a0.y; *sp0 = s0;
    float2* sp1 = (float2*)&g_s[(base + 1)*HH + 2*h2];
    float2 s1 = *sp1; s1.x += a1.x; s1.y += a1.y; *sp1 = s1;
}

// ---------------- K3 / K6a: dst = silu(LN(s @ W + bias)), 8 atoms per block ----------------
__global__ void k_lin(const float* __restrict__ W, const float* __restrict__ bias,
                      int dst_sel){
    int blk = blockIdx.x;
    int h = threadIdx.x;               // 128
    __shared__ float xs[8][HH];
    __shared__ float ys[8][HH];
    __shared__ float mm[8], rr[8];
    for (int r = h; r < 8*HH; r += 128) ((float*)xs)[r] = g_s[blk*8*HH + r];
    __syncthreads();
    float bh = bias[h];
    float acc[8];
    #pragma unroll
    for (int a = 0; a < 8; a++) acc[a] = bh;
    #pragma unroll 4
    for (int k = 0; k < HH; k++){
        float w = W[k*HH + h];
        #pragma unroll
        for (int a = 0; a < 8; a++) acc[a] = fmaf(xs[a][k], w, acc[a]);
    }
    #pragma unroll
    for (int a = 0; a < 8; a++) ys[a][h] = acc[a];
    __syncthreads();
    {
        int w = h >> 5, l = h & 31;
        #pragma unroll
        for (int aa = 0; aa < 2; aa++){
            int a = w + aa*4;
            float s1 = 0.f, s2 = 0.f;
            #pragma unroll
            for (int c = l; c < HH; c += 32){ float v = ys[a][c]; s1 += v; s2 += v*v; }
            #pragma unroll
            for (int o = 16; o > 0; o >>= 1){
                s1 += __shfl_xor_sync(0xffffffffu, s1, o);
                s2 += __shfl_xor_sync(0xffffffffu, s2, o);
            }
            if (l == 0){
                float m = s1 * (1.0f/HH);
                float var = fmaxf(s2 * (1.0f/HH) - m*m, 0.0f);
                mm[a] = m; rr[a] = rsqrtf(var + LN_EPS);
            }
        }
    }
    __syncthreads();
    float* dst = dst_sel ? g_sl : g_t;
    #pragma unroll
    for (int a = 0; a < 8; a++)
        dst[(blk*8 + a)*HH + h] = silu_f((ys[a][h] - mm[a]) * rr[a]);
}

// ---------------- K4a: v = sum_j mask*t*ev (4 i-rows/block, half2 loads) ----------------
__global__ void k_v(){
    int blk = blockIdx.x;
    int b  = blk >> 4;
    int i0 = (blk & 15) * 4;
    int t  = threadIdx.x;              // 256
    int h2 = t & 63;                   // h = 2*h2
    int rg = t >> 6;                   // i-row rg (one of 4)
    __shared__ float ts[NN*HH];
    __shared__ float evl[4][NN*3];
    const float* tb = g_t + b*NN*HH;
    for (int r = t; r < NN*HH; r += 256) ts[r] = tb[r];
    for (int r = t; r < 4*NN*3; r += 256) ((float*)evl)[r] = g_ev[(b*NN + i0)*NN*3 + r];
    __syncthreads();
    const __half2* m0 = (const __half2*)(g_maskh + (size_t)((b*NN + i0 + rg)*NN)*HH);
    float a00 = 0.f, a01 = 0.f, a10 = 0.f, a11 = 0.f, a20 = 0.f, a21 = 0.f;
    #pragma unroll 4
    for (int j = 0; j < NN; j++){
        float2 tv = *(const float2*)&ts[j*HH + 2*h2];
        float2 mq = __half22float2(m0[j*64 + h2]);
        float m0v = mq.x * tv.x, m1v = mq.y * tv.y;
        float e0 = evl[rg][j*3+0], e1 = evl[rg][j*3+1], e2 = evl[rg][j*3+2];
        a00 = fmaf(m0v, e0, a00); a01 = fmaf(m1v, e0, a01);
        a10 = fmaf(m0v, e1, a10); a11 = fmaf(m1v, e1, a11);
        a20 = fmaf(m0v, e2, a20); a21 = fmaf(m1v, e2, a21);
    }
    int base = (b*NN + i0 + rg)*3;
    *(float2*)&g_v[(base + 0)*HH + 2*h2] = make_float2(a00, a01);
    *(float2*)&g_v[(base + 1)*HH + 2*h2] = make_float2(a10, a11);
    *(float2*)&g_v[(base + 2)*HH + 2*h2] = make_float2(a20, a21);
}

// ---------------- K4b: vq = v@Wq, vk = v@Wk (8 rows per block) ----------------
__global__ void k_vqk(const float* __restrict__ Wq, const float* __restrict__ Wk){
    int blk = blockIdx.x;
    int h = threadIdx.x;
    __shared__ float vs[8][HH];
    for (int r = h; r < 8*HH; r += 128) ((float*)vs)[r] = g_v[blk*8*HH + r];
    __syncthreads();
    float aq[8], ak[8];
    #pragma unroll
    for (int r = 0; r < 8; r++){ aq[r] = 0.f; ak[r] = 0.f; }
    #pragma unroll 4
    for (int k = 0; k < HH; k++){
        float wq = Wq[k*HH + h];
        float wk = Wk[k*HH + h];
        #pragma unroll
        for (int r = 0; r < 8; r++){
            float v = vs[r][k];
            aq[r] = fmaf(v, wq, aq[r]);
            ak[r] = fmaf(v, wk, ak[r]);
        }
    }
    #pragma unroll
    for (int r = 0; r < 8; r++){
        g_vq[(blk*8 + r)*HH + h] = aq[r];
        g_vk[(blk*8 + r)*HH + h] = ak[r];
    }
}

// ---------------- K5: directional MLP (unchanged from R8) ----------------
#define SMEM_DIR_BYTES (26496*4)
__global__ void __launch_bounds__(256) k_dir(const float* __restrict__ bd1,
                                             const float* __restrict__ bd2){
    extern __shared__ unsigned smu[];
    unsigned* Ah = smu;                          // [e][kp], stride 132
    unsigned* Bh = smu + 16896;                  // staging [n][kp'], stride 36
    float* b1s = (float*)(smu + 26112);
    float* b2s = (float*)(smu + 26368);
    float* eas = (float*)(Bh);
    float* evs = (float*)(Bh + 128);
    float* vks = (float*)(Bh + 512);
    float* Ps  = (float*)(Bh + 1280);

    int t = threadIdx.x, lane = t & 31, wid = t >> 5;
    int g = lane >> 2, tig = lane & 3;
    int bi0 = blockIdx.x * 2, bbase = bi0 & ~63;

    b1s[t] = bd1[t];
    if (t < 128) b2s[t] = bd2[t];
    if (t < 128) eas[t] = g_ea[bi0*64 + t];
    for (int r = t; r < 384;  r += 256) evs[r] = g_ev[bi0*192 + r];
    for (int r = t; r < 768;  r += 256) vks[r] = g_vk[bi0*384 + r];
    for (int r = t; r < 1536; r += 256) Ps [r] = g_P [bi0*768 + r];
    __syncthreads();

    // build dir3 (scaled 1/64) -> Ah kp 0..63
    {
        int kp3 = t & 63, eh = t >> 6;
        int i  = eh & 1, jh = eh >> 1;
        int kk = 2*kp3;
        float u0 = vks[i*384 + kk],     u1 = vks[i*384 + 128 + kk], u2 = vks[i*384 + 256 + kk];
        float w0 = vks[i*384 + kk + 1], w1 = vks[i*384 + 129 + kk], w2 = vks[i*384 + 257 + kk];
        for (int jj = 0; jj < 32; jj++){
            int j = jh*32 + jj;
            int e = i*64 + j;
            float ea = eas[e] * 0.015625f;
            const float* vq = g_vq + (bbase + j)*384 + kk;
            float2 q0 = *(const float2*)vq;
            float2 q1 = *(const float2*)(vq + 128);
            float2 q2 = *(const float2*)(vq + 256);
            float f0 = (q0.x*u0 + q1.x*u1 + q2.x*u2) * ea;
            float f1 = (q0.y*w0 + q1.y*w1 + q2.y*w2) * ea;
            Ah[e*132 + kp3] = half_pack(f0, f1);
        }
    }

    int m0 = (wid & 3) * 32;
    int nh = wid >> 2;

    // init acc1 with dir2 low-rank contribution
    float acc1[2][16][4];
    #pragma unroll
    for (int ms = 0; ms < 2; ms++){
        int ea_r = m0 + ms*16 + g;
        int eb_r = ea_r + 8;
        int ia = ea_r >> 6, ib = eb_r >> 6;
        float ca0 = evs[ea_r*3], ca1 = evs[ea_r*3+1], ca2 = evs[ea_r*3+2];
        float cb0 = evs[eb_r*3], cb1 = evs[eb_r*3+1], cb2 = evs[eb_r*3+2];
        float wa = eas[ea_r], wb = eas[eb_r];
        const float* Pa = Ps + ia*768;
        const float* Pb = Ps + ib*768;
        #pragma unroll
        for (int nt = 0; nt < 16; nt++){
            int c0 = nh*128 + nt*8 + 2*tig;
            acc1[ms][nt][0] = wa * (ca0*Pa[c0]   + ca1*Pa[256+c0]   + ca2*Pa[512+c0]);
            acc1[ms][nt][1] = wa * (ca0*Pa[c0+1] + ca1*Pa[256+c0+1] + ca2*Pa[512+c0+1]);
            acc1[ms][nt][2] = wb * (cb0*Pb[c0]   + cb1*Pb[256+c0]   + cb2*Pb[512+c0]);
            acc1[ms][nt][3] = wb * (cb0*Pb[c0+1] + cb1*Pb[256+c0+1] + cb2*Pb[512+c0+1]);
        }
    }
    __syncthreads();

    // GEMM1 (dir3 half): K=128
    for (int c = 0; c < 2; c++){
        for (int r = t; r < 2048; r += 256){
            int n = r >> 3, q = r & 7;
            *(uint4*)&Bh[n*36 + q*4] = *(const uint4*)&gW1h3[n*64 + c*32 + q*4];
        }
        __syncthreads();
        #pragma unroll
        for (int ksl = 0; ksl < 4; ksl++){
            int kp0 = c*32 + ksl*8;
            int kb  = ksl*8;
            unsigned ah[2][4];
            #pragma unroll
            for (int ms = 0; ms < 2; ms++){
                int r0 = m0 + ms*16;
                ah[ms][0] = Ah[(r0+g  )*132 + kp0 + tig];
                ah[ms][1] = Ah[(r0+g+8)*132 + kp0 + tig];
                ah[ms][2] = Ah[(r0+g  )*132 + kp0 + tig + 4];
                ah[ms][3] = Ah[(r0+g+8)*132 + kp0 + tig + 4];
            }
            #pragma unroll
            for (int nt = 0; nt < 16; nt++){
                int n0 = nh*128 + nt*8;
                unsigned b0 = Bh[(n0+g)*36 + kb + tig];
                unsigned b1 = Bh[(n0+g)*36 + kb + tig + 4];
                mma16h(acc1[0][nt], ah[0], b0, b1);
                mma16h(acc1[1][nt], ah[1], b0, b1);
            }
        }
        __syncthreads();
    }

    // epilogue1: h1 = silu(D1 + b1) packed back into Ah
    #pragma unroll
    for (int ms = 0; ms < 2; ms++){
        #pragma unroll
        for (int nt = 0; nt < 16; nt++){
            int n0 = nh*128 + nt*8;
            int c0 = n0 + 2*tig;
            int kph = c0 >> 1;
            int r0 = m0 + ms*16 + g;
            float y0 = silu_f(acc1[ms][nt][0] + b1s[c0]);
            float y1 = silu_f(acc1[ms][nt][1] + b1s[c0+1]);
            Ah[r0*132 + kph] = half_pack(y0, y1);
            float y2 = silu_f(acc1[ms][nt][2] + b1s[c0]);
            float y3 = silu_f(acc1[ms][nt][3] + b1s[c0+1]);
            Ah[(r0+8)*132 + kph] = half_pack(y2, y3);
        }
    }
    __syncthreads();

    // GEMM2: K=256
    float acc2[2][8][4];
    #pragma unroll
    for (int ms = 0; ms < 2; ms++)
        #pragma unroll
        for (int nt = 0; nt < 8; nt++)
            #pragma unroll
            for (int q = 0; q < 4; q++) acc2[ms][nt][q] = 0.f;

    for (int c = 0; c < 4; c++){
        for (int r = t; r < 1024; r += 256){
            int n = r >> 3, q = r & 7;
            *(uint4*)&Bh[n*36 + q*4] = *(const uint4*)&gW2h[n*128 + c*32 + q*4];
        }
        __syncthreads();
        #pragma unroll
        for (int ksl = 0; ksl < 4; ksl++){
            int kp0 = c*32 + ksl*8;
            int kb  = ksl*8;
            unsigned ah[2][4];
            #pragma unroll
            for (int ms = 0; ms < 2; ms++){
                int r0 = m0 + ms*16;
                ah[ms][0] = Ah[(r0+g  )*132 + kp0 + tig];
                ah[ms][1] = Ah[(r0+g+8)*132 + kp0 + tig];
                ah[ms][2] = Ah[(r0+g  )*132 + kp0 + tig + 4];
                ah[ms][3] = Ah[(r0+g+8)*132 + kp0 + tig + 4];
            }
            #pragma unroll
            for (int nt = 0; nt < 8; nt++){
                int n0 = nh*64 + nt*8;
                unsigned b0 = Bh[(n0+g)*36 + kb + tig];
                unsigned b1 = Bh[(n0+g)*36 + kb + tig + 4];
                mma16h(acc2[0][nt], ah[0], b0, b1);
                mma16h(acc2[1][nt], ah[1], b0, b1);
            }
        }
        __syncthreads();
    }

    // epilogue2: maskh *= silu(D2 + b2)
    #pragma unroll
    for (int ms = 0; ms < 2; ms++){
        #pragma unroll
        for (int nt = 0; nt < 8; nt++){
            int n0 = nh*64 + nt*8;
            int c0 = n0 + 2*tig;
            int e0 = m0 + ms*16 + g;
            size_t base0 = ((size_t)(bi0*64 + e0))*128 + c0;
            __half2* p0 = (__half2*)&g_maskh[base0];
            float2 mv = __half22float2(*p0);
            mv.x *= silu_f(acc2[ms][nt][0] + b2s[c0]);
            mv.y *= silu_f(acc2[ms][nt][1] + b2s[c0+1]);
            *p0 = __float22half2_rn(mv);
            __half2* p1 = (__half2*)&g_maskh[base0 + 8*128];
            float2 mw = __half22float2(*p1);
            mw.x *= silu_f(acc2[ms][nt][2] + b2s[c0]);
            mw.y *= silu_f(acc2[ms][nt][3] + b2s[c0+1]);
            *p1 = __float22half2_rn(mw);
        }
    }
}

// ---------------- K7: readout ----------------
__global__ void k_out(const int* __restrict__ z, const float* __restrict__ Wo,
                      const float* __restrict__ bo, float* __restrict__ out){
    int b = blockIdx.x, h = threadIdx.x;
    __shared__ float red[4];
    float acc = 0.f;
    for (int i = 0; i < NN; i++)
        if (z[b*NN + i] != 0) acc += g_s[(b*NN + i)*HH + h];
    float part = acc * Wo[h];
    float tot = blkred128(part, red);
    if (h == 0) out[b] = tot + bo[0];
}

// ---------------- launch ----------------
extern "C" void kernel_launch(void* const* d_in, const int* in_sizes, int n_in,
                              void* d_out, int out_size){
    const int*   z      = (const int*)  d_in[0];
    const float* pos    = (const float*)d_in[1];
    const float* emb_w  = (const float*)d_in[2];
    const float* emb2_w = (const float*)d_in[3];
    const float* Wef    = (const float*)d_in[4];
    const float* bef    = (const float*)d_in[5];
    const float* Ws2v   = (const float*)d_in[6];
    const float* bs2v   = (const float*)d_in[7];
    const float* Wq     = (const float*)d_in[8];
    const float* Wk     = (const float*)d_in[9];
    const float* Wd1    = (const float*)d_in[10];
    const float* bd1    = (const float*)d_in[11];
    const float* Wd2    = (const float*)d_in[12];
    const float* bd2    = (const float*)d_in[13];
    const float* Wint   = (const float*)d_in[14];
    const float* bint   = (const float*)d_in[15];
    const float* Wo     = (const float*)d_in[16];
    const float* bo     = (const float*)d_in[17];
    float* out = (float*)d_out;

    cudaFuncSetAttribute(k_dir, cudaFuncAttributeMaxDynamicSharedMemorySize, SMEM_DIR_BYTES);

    k_whalf<<<384, 128>>>(Wd1, Wd2);
    k_geom <<<BB*NN, 128>>>(z, pos, Wef, bef);
    k_embed<<<BB*NN, 128>>>(z, emb_w, emb2_w);
    k_gather<<<BB*NN/8, 256>>>(0);               // s += mask @ sn
    k_lin  <<<BB*NN/8, 128>>>(Ws2v, bs2v, 0);    // t = silu(LN(s@Ws2v+b))
    k_v    <<<BB*NN/4, 256>>>();
    k_vqk  <<<BB*NN*3/8, 128>>>(Wq, Wk);
    k_p    <<<BB*NN, 256>>>(Wd1);
    k_dir  <<<BB*NN/2, 256, SMEM_DIR_BYTES>>>(bd1, bd2);
    for (int l = 0; l < 3; l++){
        k_lin   <<<BB*NN/8, 128>>>(Wint + l*HH*HH, bint + l*HH, 1);  // sl
        k_gather<<<BB*NN/8, 256>>>(1);                                // s += mask @ sl
    }
    k_out<<<BB, 128>>>(z, Wo, bo, out);
}

// round 11
// speedup vs baseline: 2.6272x; 1.0190x over previous
#include <cuda_runtime.h>
#include <cuda_fp16.h>
#include <math.h>
#include <stdint.h>

#define BB 64
#define NN 64
#define HH 128
#define EFD 32
#define LN_EPS 1e-5f
#define CUT 10.0f

// ---------------- device scratch (no runtime allocation) ----------------
static __device__ __half g_maskh[BB*NN*NN*HH]; // 64 MB fp16 mask
static __device__ float g_ea  [BB*NN*NN];
static __device__ float g_ev  [BB*NN*NN*3];
static __device__ float g_s   [BB*NN*HH];
static __device__ float g_sn  [BB*NN*HH];
static __device__ float g_t   [BB*NN*HH];
static __device__ float g_v   [BB*NN*3*HH];
static __device__ float g_vq  [BB*NN*3*HH];
static __device__ float g_vk  [BB*NN*3*HH];
static __device__ float g_sl  [BB*NN*HH];
static __device__ float g_P   [BB*NN*3*256];   // P_i = V_i @ Wd1[0:128]
static __device__ unsigned gW1h3[256*64];      // Wd1 dir3 rows packed fp16 (x64)
static __device__ unsigned gW2h [128*128];

// ---- fast exp2 poly ----
__device__ __forceinline__ float exp2_poly(float f){
    float p = 1.3333558e-3f;
    p = fmaf(p, f, 9.6181291e-3f);
    p = fmaf(p, f, 5.5504109e-2f);
    p = fmaf(p, f, 2.4022651e-1f);
    p = fmaf(p, f, 6.9314718e-1f);
    p = fmaf(p, f, 1.0f);
    return p;
}
__device__ __forceinline__ float exp2n_f(float t){
    t = fmaxf(t, -126.0f);
    float fn = t + 12582912.0f;
    float n  = fn - 12582912.0f;
    float f  = t - n;
    int ni = __float_as_int(fn) - 0x4B400000;
    float scale = __int_as_float((ni + 127) << 23);
    return exp2_poly(f) * scale;
}
// silu: poly exp2 on FMA pipe + MUFU rcp (pipes overlap)
__device__ __forceinline__ float silu_f(float x){
    float t = x * (-1.442695041f);
    t = fminf(fmaxf(t, -126.0f), 126.0f);
    float fn = t + 12582912.0f;
    float n  = fn - 12582912.0f;
    float f  = t - n;
    int ni = __float_as_int(fn) - 0x4B400000;
    float scale = __int_as_float((ni + 127) << 23);
    float e = exp2_poly(f) * scale;   // e^{-x}
    float d = 1.0f + e;
    float y;
    asm("rcp.approx.f32 %0, %1;" : "=f"(y) : "f"(d));
    return x * y;
}

// ---- fp16 pack: {low16 = f16(f0), high16 = f16(f1)} ----
__device__ __forceinline__ unsigned half_pack(float f0, float f1){
    unsigned p;
    asm("cvt.rn.f16x2.f32 %0, %1, %2;" : "=r"(p) : "f"(f1), "f"(f0));
    return p;
}

// ---- mma.sync fp16 m16n8k16, fp32 accumulate ----
__device__ __forceinline__ void mma16h(float* c, const unsigned* a, unsigned b0, unsigned b1){
    asm("mma.sync.aligned.m16n8k16.row.col.f32.f16.f16.f32 "
        "{%0,%1,%2,%3},{%4,%5,%6,%7},{%8,%9},{%0,%1,%2,%3};"
        : "+f"(c[0]), "+f"(c[1]), "+f"(c[2]), "+f"(c[3])
        : "r"(a[0]), "r"(a[1]), "r"(a[2]), "r"(a[3]), "r"(b0), "r"(b1));
}

// block reduction for 128 threads (4 warps)
__device__ __forceinline__ float blkred128(float v, volatile float* red){
    #pragma unroll
    for (int o = 16; o > 0; o >>= 1) v += __shfl_xor_sync(0xffffffffu, v, o);
    if ((threadIdx.x & 31) == 0) red[threadIdx.x >> 5] = v;
    __syncthreads();
    v = red[0] + red[1] + red[2] + red[3];
    __syncthreads();
    return v;
}

// ---------------- K0: convert weights to packed fp16 ----------------
__global__ void k_whalf(const float* __restrict__ Wd1, const float* __restrict__ Wd2){
    int n = blockIdx.x, kp = threadIdx.x;
    if (n < 256){
        if (kp < 64){
            float f0 = Wd1[(128 + 2*kp    )*256 + n] * 64.0f;
            float f1 = Wd1[(128 + 2*kp + 1)*256 + n] * 64.0f;
            gW1h3[n*64 + kp] = half_pack(f0, f1);
        }
    } else {
        int n2 = n - 256;
        float f0 = Wd2[(2*kp  )*128 + n2];
        float f1 = Wd2[(2*kp+1)*128 + n2];
        gW2h[n2*128 + kp] = half_pack(f0, f1);
    }
}

// ---------------- K0b: P_i = V_i @ Wd1[0:128]  (3 x 256 per atom, fp32) ----------------
__global__ void k_p(const float* __restrict__ Wd1){
    int bi = blockIdx.x, n = threadIdx.x;
    __shared__ float vs[3*HH];
    for (int r = n; r < 3*HH; r += 256) vs[r] = g_v[bi*3*HH + r];
    __syncthreads();
    float p0 = 0.f, p1 = 0.f, p2 = 0.f;
    #pragma unroll 4
    for (int k = 0; k < HH; k++){
        float w = Wd1[k*256 + n];
        p0 = fmaf(vs[k],        w, p0);
        p1 = fmaf(vs[HH + k],   w, p1);
        p2 = fmaf(vs[2*HH + k], w, p2);
    }
    g_P[bi*768 + n]       = p0;
    g_P[bi*768 + 256 + n] = p1;
    g_P[bi*768 + 512 + n] = p2;
}

// ---------------- K1: geometry + RBF filter mask (256 threads) ----------------
__global__ void k_geom(const int* __restrict__ z, const float* __restrict__ pos,
                       const float* __restrict__ Wef, const float* __restrict__ bef){
    int blk = blockIdx.x;
    int b = blk >> 6, i = blk & 63;
    int t = threadIdx.x;               // 256

    __shared__ float pos_s[NN][3];
    __shared__ int   z_s[NN];
    __shared__ float d_s[NN], ea_s[NN];
    __shared__ float ef_s[NN][EFD];
    __shared__ float Wef_s[EFD*HH];
    __shared__ float bef_s[HH];

    for (int r = t; r < EFD*HH; r += 256) Wef_s[r] = Wef[r];
    if (t < HH) bef_s[t] = bef[t];
    if (t < NN){
        z_s[t] = z[b*NN + t];
        pos_s[t][0] = pos[(b*NN + t)*3 + 0];
        pos_s[t][1] = pos[(b*NN + t)*3 + 1];
        pos_s[t][2] = pos[(b*NN + t)*3 + 2];
    }
    __syncthreads();

    if (t < NN){
        int j = t;
        float dx = pos_s[j][0] - pos_s[i][0];
        float dy = pos_s[j][1] - pos_s[i][1];
        float dz = pos_s[j][2] - pos_s[i][2];
        float d2 = dx*dx + dy*dy + dz*dz;
        float d  = sqrtf(fmaxf(d2, 1e-12f));
        d_s[j] = d;
        bool pair = (z_s[i] != 0) && (z_s[j] != 0) && (j != i);
        float ea = (pair && d < CUT) ? 0.5f*(cosf(3.14159265358979323846f * d / CUT) + 1.0f) : 0.0f;
        ea_s[j] = ea;
        g_ea[blk*NN + j] = ea;
        float inv = 1.0f / d;
        g_ev[(blk*NN + j)*3 + 0] = pair ? dx*inv : 0.0f;
        g_ev[(blk*NN + j)*3 + 1] = pair ? dy*inv : 0.0f;
        g_ev[(blk*NN + j)*3 + 2] = pair ? dz*inv : 0.0f;
    }
    __syncthreads();

    const float step = CUT / (float)(EFD - 1);
    for (int r = t; r < NN*EFD; r += 256){
        int j = r >> 5, k = r & 31;
        float dd = d_s[j] - step*(float)k;
        ef_s[j][k] = exp2n_f(-14.4269504089f * dd * dd);
    }
    __syncthreads();

    // thread t: h pair 2*(t&63), j range (t>>6)*16 ..
    int hp = t & 63, jh = t >> 6;
    int h0 = 2*hp;
    __half2* mrow = (__half2*)(g_maskh + (size_t)blk*NN*HH);
    for (int jj = 0; jj < 16; jj++){
        int j = jh*16 + jj;
        float a0 = bef_s[h0], a1 = bef_s[h0+1];
        #pragma unroll
        for (int k = 0; k < EFD; k++){
            float e = ef_s[j][k];
            a0 = fmaf(e, Wef_s[k*HH + h0],     a0);
            a1 = fmaf(e, Wef_s[k*HH + h0 + 1], a1);
        }
        float ea = ea_s[j];
        float2 m; m.x = silu_f(a0) * ea; m.y = silu_f(a1) * ea;
        mrow[j*64 + hp] = __float22half2_rn(m);
    }
}

// ---------------- K2a: s = emb[z];  sn = LN(emb2[z]) ----------------
__global__ void k_embed(const int* __restrict__ z, const float* __restrict__ emb_w,
                        const float* __restrict__ emb2_w){
    int a = blockIdx.x, h = threadIdx.x;
    __shared__ float red[4];
    int zi = z[a];
    g_s[a*HH + h] = emb_w[zi*HH + h];
    float x = emb2_w[zi*HH + h];
    float s1 = blkred128(x, red);
    float s2 = blkred128(x*x, red);
    float m = s1 * (1.0f/HH);
    float var = fmaxf(s2 * (1.0f/HH) - m*m, 0.0f);
    g_sn[a*HH + h] = (x - m) * rsqrtf(var + LN_EPS);
}

// ---------------- K2b / K6b: s += mask @ src (4 i-rows/block, half2 loads) ----------------
__global__ void k_gather(int sel){
    int blk = blockIdx.x;              // (b, i-group of 4)
    int b  = blk >> 4;
    int i0 = (blk & 15) * 4;
    int t  = threadIdx.x;              // 256
    int h2 = t & 63;
    int rg = t >> 6;                   // one i-row per group
    const float* src = sel ? g_sl : g_sn;
    __shared__ float srcs[NN*HH];
    const float* sb = src + b*NN*HH;
    for (int r = t; r < NN*HH; r += 256) srcs[r] = sb[r];
    __syncthreads();
    const __half2* m0 = (const __half2*)(g_maskh + (size_t)((b*NN + i0 + rg)*NN)*HH);
    float2 a0 = make_float2(0.f, 0.f);
    #pragma unroll 8
    for (int j = 0; j < NN; j++){
        float2 sv = *(const float2*)&srcs[j*HH + 2*h2];
        float2 q0 = __half22float2(m0[j*64 + h2]);
        a0.x = fmaf(q0.x, sv.x, a0.x); a0.y = fmaf(q0.y, sv.y, a0.y);
    }
    float2* sp0 = (float2*)&g_s[(b*NN + i0 + rg)*HH + 2*h2];
    float2 s0 = *sp0; s0.x += a0.x; s0.y += a0.y; *sp0 = s0;
}

// ---------------- K3 / K6a: dst = silu(LN(s @ W + bias)), 8 atoms per block ----------------
__global__ void k_lin(const float* __restrict__ W, const float* __restrict__ bias,
                      int dst_sel){
    int blk = blockIdx.x;
    int h = threadIdx.x;               // 128
    __shared__ float xs[8][HH];
    __shared__ float ys[8][HH];
    __shared__ float mm[8], rr[8];
    for (int r = h; r < 8*HH; r += 128) ((float*)xs)[r] = g_s[blk*8*HH + r];
    __syncthreads();
    float bh = bias[h];
    float acc[8];
    #pragma unroll
    for (int a = 0; a < 8; a++) acc[a] = bh;
    #pragma unroll 4
    for (int k = 0; k < HH; k++){
        float w = W[k*HH + h];
        #pragma unroll
        for (int a = 0; a < 8; a++) acc[a] = fmaf(xs[a][k], w, acc[a]);
    }
    #pragma unroll
    for (int a = 0; a < 8; a++) ys[a][h] = acc[a];
    __syncthreads();
    {
        int w = h >> 5, l = h & 31;
        #pragma unroll
        for (int aa = 0; aa < 2; aa++){
            int a = w + aa*4;
            float s1 = 0.f, s2 = 0.f;
            #pragma unroll
            for (int c = l; c < HH; c += 32){ float v = ys[a][c]; s1 += v; s2 += v*v; }
            #pragma unroll
            for (int o = 16; o > 0; o >>= 1){
                s1 += __shfl_xor_sync(0xffffffffu, s1, o);
                s2 += __shfl_xor_sync(0xffffffffu, s2, o);
            }
            if (l == 0){
                float m = s1 * (1.0f/HH);
                float var = fmaxf(s2 * (1.0f/HH) - m*m, 0.0f);
                mm[a] = m; rr[a] = rsqrtf(var + LN_EPS);
            }
        }
    }
    __syncthreads();
    float* dst = dst_sel ? g_sl : g_t;
    #pragma unroll
    for (int a = 0; a < 8; a++)
        dst[(blk*8 + a)*HH + h] = silu_f((ys[a][h] - mm[a]) * rr[a]);
}

// ---------------- K4a: v = sum_j mask*t*ev (4 i-rows/block, half2 loads) ----------------
__global__ void k_v(){
    int blk = blockIdx.x;
    int b  = blk >> 4;
    int i0 = (blk & 15) * 4;
    int t  = threadIdx.x;              // 256
    int h2 = t & 63;
    int rg = t >> 6;
    __shared__ float ts[NN*HH];
    __shared__ float evl[4][NN*3];
    const float* tb = g_t + b*NN*HH;
    for (int r = t; r < NN*HH; r += 256) ts[r] = tb[r];
    for (int r = t; r < 4*NN*3; r += 256) ((float*)evl)[r] = g_ev[(b*NN + i0)*NN*3 + r];
    __syncthreads();
    const __half2* m0 = (const __half2*)(g_maskh + (size_t)((b*NN + i0 + rg)*NN)*HH);
    float a00 = 0.f, a01 = 0.f, a10 = 0.f, a11 = 0.f, a20 = 0.f, a21 = 0.f;
    #pragma unroll 4
    for (int j = 0; j < NN; j++){
        float2 tv = *(const float2*)&ts[j*HH + 2*h2];
        float2 mq = __half22float2(m0[j*64 + h2]);
        float m0v = mq.x * tv.x, m1v = mq.y * tv.y;
        float e0 = evl[rg][j*3+0], e1 = evl[rg][j*3+1], e2 = evl[rg][j*3+2];
        a00 = fmaf(m0v, e0, a00); a01 = fmaf(m1v, e0, a01);
        a10 = fmaf(m0v, e1, a10); a11 = fmaf(m1v, e1, a11);
        a20 = fmaf(m0v, e2, a20); a21 = fmaf(m1v, e2, a21);
    }
    int base = (b*NN + i0 + rg)*3;
    *(float2*)&g_v[(base + 0)*HH + 2*h2] = make_float2(a00, a01);
    *(float2*)&g_v[(base + 1)*HH + 2*h2] = make_float2(a10, a11);
    *(float2*)&g_v[(base + 2)*HH + 2*h2] = make_float2(a20, a21);
}

// ---------------- K4b: vq = v@Wq, vk = v@Wk (8 rows per block) ----------------
__global__ void k_vqk(const float* __restrict__ Wq, const float* __restrict__ Wk){
    int blk = blockIdx.x;
    int h = threadIdx.x;
    __shared__ float vs[8][HH];
    for (int r = h; r < 8*HH; r += 128) ((float*)vs)[r] = g_v[blk*8*HH + r];
    __syncthreads();
    float aq[8], ak[8];
    #pragma unroll
    for (int r = 0; r < 8; r++){ aq[r] = 0.f; ak[r] = 0.f; }
    #pragma unroll 4
    for (int k = 0; k < HH; k++){
        float wq = Wq[k*HH + h];
        float wk = Wk[k*HH + h];
        #pragma unroll
        for (int r = 0; r < 8; r++){
            float v = vs[r][k];
            aq[r] = fmaf(v, wq, aq[r]);
            ak[r] = fmaf(v, wk, ak[r]);
        }
    }
    #pragma unroll
    for (int r = 0; r < 8; r++){
        g_vq[(blk*8 + r)*HH + h] = aq[r];
        g_vk[(blk*8 + r)*HH + h] = ak[r];
    }
}

// ---------------- K5: directional MLP (double-buffered staging) ----------------
// smem words: Ah 16896 | Bh0 9216 | Bh1 9216 | b1s 256 | b2s 128  = 35712
#define SMEM_DIR_BYTES (35712*4)
__global__ void __launch_bounds__(256) k_dir(const float* __restrict__ bd1,
                                             const float* __restrict__ bd2){
    extern __shared__ unsigned smu[];
    unsigned* Ah  = smu;                         // [e][kp], stride 132
    unsigned* BhA = smu + 16896;                 // staging buf 0
    unsigned* BhB = smu + 16896 + 9216;          // staging buf 1
    float* b1s = (float*)(smu + 35328);
    float* b2s = (float*)(smu + 35584);
    // pre-GEMM scratch overlaps BhA (dead before first staging store)
    float* eas = (float*)(BhA);
    float* evs = (float*)(BhA + 128);
    float* vks = (float*)(BhA + 512);
    float* Ps  = (float*)(BhA + 1280);

    int t = threadIdx.x, lane = t & 31, wid = t >> 5;
    int g = lane >> 2, tig = lane & 3;
    int bi0 = blockIdx.x * 2, bbase = bi0 & ~63;

    b1s[t] = bd1[t];
    if (t < 128) b2s[t] = bd2[t];
    if (t < 128) eas[t] = g_ea[bi0*64 + t];
    for (int r = t; r < 384;  r += 256) evs[r] = g_ev[bi0*192 + r];
    for (int r = t; r < 768;  r += 256) vks[r] = g_vk[bi0*384 + r];
    for (int r = t; r < 1536; r += 256) Ps [r] = g_P [bi0*768 + r];
    __syncthreads();

    // build dir3 (scaled 1/64) -> Ah kp 0..63
    {
        int kp3 = t & 63, eh = t >> 6;
        int i  = eh & 1, jh = eh >> 1;
        int kk = 2*kp3;
        float u0 = vks[i*384 + kk],     u1 = vks[i*384 + 128 + kk], u2 = vks[i*384 + 256 + kk];
        float w0 = vks[i*384 + kk + 1], w1 = vks[i*384 + 129 + kk], w2 = vks[i*384 + 257 + kk];
        for (int jj = 0; jj < 32; jj++){
            int j = jh*32 + jj;
            int e = i*64 + j;
            float ea = eas[e] * 0.015625f;
            const float* vq = g_vq + (bbase + j)*384 + kk;
            float2 q0 = *(const float2*)vq;
            float2 q1 = *(const float2*)(vq + 128);
            float2 q2 = *(const float2*)(vq + 256);
            float f0 = (q0.x*u0 + q1.x*u1 + q2.x*u2) * ea;
            float f1 = (q0.y*w0 + q1.y*w1 + q2.y*w2) * ea;
            Ah[e*132 + kp3] = half_pack(f0, f1);
        }
    }
    __syncthreads();

    int m0 = (wid & 3) * 32;
    int nh = wid >> 2;

    // init acc1 with dir2 low-rank contribution (reads eas/evs/Ps in BhA)
    float acc1[2][16][4];
    #pragma unroll
    for (int ms = 0; ms < 2; ms++){
        int ea_r = m0 + ms*16 + g;
        int eb_r = ea_r + 8;
        int ia = ea_r >> 6, ib = eb_r >> 6;
        float ca0 = evs[ea_r*3], ca1 = evs[ea_r*3+1], ca2 = evs[ea_r*3+2];
        float cb0 = evs[eb_r*3], cb1 = evs[eb_r*3+1], cb2 = evs[eb_r*3+2];
        float wa = eas[ea_r], wb = eas[eb_r];
        const float* Pa = Ps + ia*768;
        const float* Pb = Ps + ib*768;
        #pragma unroll
        for (int nt = 0; nt < 16; nt++){
            int c0 = nh*128 + nt*8 + 2*tig;
            acc1[ms][nt][0] = wa * (ca0*Pa[c0]   + ca1*Pa[256+c0]   + ca2*Pa[512+c0]);
            acc1[ms][nt][1] = wa * (ca0*Pa[c0+1] + ca1*Pa[256+c0+1] + ca2*Pa[512+c0+1]);
            acc1[ms][nt][2] = wb * (cb0*Pb[c0]   + cb1*Pb[256+c0]   + cb2*Pb[512+c0]);
            acc1[ms][nt][3] = wb * (cb0*Pb[c0+1] + cb1*Pb[256+c0+1] + cb2*Pb[512+c0+1]);
        }
    }

    // ===== GEMM1 (dir3 half): K=128, 2 chunks, double-buffered =====
    {
        uint4 pf[8];
        #pragma unroll
        for (int q = 0; q < 8; q++){
            int r = t + q*256;
            pf[q] = *(const uint4*)&gW1h3[(r>>3)*64 + (r&7)*4];
        }
        __syncthreads();                 // all scratch reads (init acc1) done
        #pragma unroll
        for (int q = 0; q < 8; q++){
            int r = t + q*256;
            *(uint4*)&BhA[(r>>3)*36 + (r&7)*4] = pf[q];
        }
        __syncthreads();
        for (int c = 0; c < 2; c++){
            unsigned* Bcur = (c & 1) ? BhB : BhA;
            if (c == 0){
                #pragma unroll
                for (int q = 0; q < 8; q++){
                    int r = t + q*256;
                    pf[q] = *(const uint4*)&gW1h3[(r>>3)*64 + 32 + (r&7)*4];
                }
            }
            #pragma unroll
            for (int ksl = 0; ksl < 4; ksl++){
                int kp0 = c*32 + ksl*8;
                int kb  = ksl*8;
                unsigned ah[2][4];
                #pragma unroll
                for (int ms = 0; ms < 2; ms++){
                    int r0 = m0 + ms*16;
                    ah[ms][0] = Ah[(r0+g  )*132 + kp0 + tig];
                    ah[ms][1] = Ah[(r0+g+8)*132 + kp0 + tig];
                    ah[ms][2] = Ah[(r0+g  )*132 + kp0 + tig + 4];
                    ah[ms][3] = Ah[(r0+g+8)*132 + kp0 + tig + 4];
                }
                #pragma unroll
                for (int nt = 0; nt < 16; nt++){
                    int n0 = nh*128 + nt*8;
                    unsigned b0 = Bcur[(n0+g)*36 + kb + tig];
                    unsigned b1 = Bcur[(n0+g)*36 + kb + tig + 4];
                    mma16h(acc1[0][nt], ah[0], b0, b1);
                    mma16h(acc1[1][nt], ah[1], b0, b1);
                }
            }
            if (c == 0){
                #pragma unroll
                for (int q = 0; q < 8; q++){
                    int r = t + q*256;
                    *(uint4*)&BhB[(r>>3)*36 + (r&7)*4] = pf[q];
                }
            }
            __syncthreads();
        }
    }

    // epilogue1: h1 = silu(D1 + b1) packed back into Ah
    #pragma unroll
    for (int ms = 0; ms < 2; ms++){
        #pragma unroll
        for (int nt = 0; nt < 16; nt++){
            int n0 = nh*128 + nt*8;
            int c0 = n0 + 2*tig;
            int kph = c0 >> 1;
            int r0 = m0 + ms*16 + g;
            float y0 = silu_f(acc1[ms][nt][0] + b1s[c0]);
            float y1 = silu_f(acc1[ms][nt][1] + b1s[c0+1]);
            Ah[r0*132 + kph] = half_pack(y0, y1);
            float y2 = silu_f(acc1[ms][nt][2] + b1s[c0]);
            float y3 = silu_f(acc1[ms][nt][3] + b1s[c0+1]);
            Ah[(r0+8)*132 + kph] = half_pack(y2, y3);
        }
    }

    // ===== GEMM2: K=256, 4 chunks, double-buffered =====
    float acc2[2][8][4];
    #pragma unroll
    for (int ms = 0; ms < 2; ms++)
        #pragma unroll
        for (int nt = 0; nt < 8; nt++)
            #pragma unroll
            for (int q = 0; q < 4; q++) acc2[ms][nt][q] = 0.f;

    {
        uint4 pf[4];
        #pragma unroll
        for (int q = 0; q < 4; q++){
            int r = t + q*256;
            pf[q] = *(const uint4*)&gW2h[(r>>3)*128 + (r&7)*4];
        }
        __syncthreads();                 // epilogue1 Ah writes complete; Bh free
        #pragma unroll
        for (int q = 0; q < 4; q++){
            int r = t + q*256;
            *(uint4*)&BhA[(r>>3)*36 + (r&7)*4] = pf[q];
        }
        __syncthreads();
        for (int c = 0; c < 4; c++){
            unsigned* Bcur = (c & 1) ? BhB : BhA;
            unsigned* Bnxt = (c & 1) ? BhA : BhB;
            if (c + 1 < 4){
                #pragma unroll
                for (int q = 0; q < 4; q++){
                    int r = t + q*256;
                    pf[q] = *(const uint4*)&gW2h[(r>>3)*128 + (c+1)*32 + (r&7)*4];
                }
            }
            #pragma unroll
            for (int ksl = 0; ksl < 4; ksl++){
                int kp0 = c*32 + ksl*8;
                int kb  = ksl*8;
                unsigned ah[2][4];
                #pragma unroll
                for (int ms = 0; ms < 2; ms++){
                    int r0 = m0 + ms*16;
                    ah[ms][0] = Ah[(r0+g  )*132 + kp0 + tig];
                    ah[ms][1] = Ah[(r0+g+8)*132 + kp0 + tig];
                    ah[ms][2] = Ah[(r0+g  )*132 + kp0 + tig + 4];
                    ah[ms][3] = Ah[(r0+g+8)*132 + kp0 + tig + 4];
                }
                #pragma unroll
                for (int nt = 0; nt < 8; nt++){
                    int n0 = nh*64 + nt*8;
                    unsigned b0 = Bcur[(n0+g)*36 + kb + tig];
                    unsigned b1 = Bcur[(n0+g)*36 + kb + tig + 4];
                    mma16h(acc2[0][nt], ah[0], b0, b1);
                    mma16h(acc2[1][nt], ah[1], b0, b1);
                }
            }
            if (c + 1 < 4){
                #pragma unroll
                for (int q = 0; q < 4; q++){
                    int r = t + q*256;
                    *(uint4*)&Bnxt[(r>>3)*36 + (r&7)*4] = pf[q];
                }
            }
            __syncthreads();
        }
    }

    // epilogue2: maskh *= silu(D2 + b2)
    #pragma unroll
    for (int ms = 0; ms < 2; ms++){
        #pragma unroll
        for (int nt = 0; nt < 8; nt++){
            int n0 = nh*64 + nt*8;
            int c0 = n0 + 2*tig;
            int e0 = m0 + ms*16 + g;
            size_t base0 = ((size_t)(bi0*64 + e0))*128 + c0;
            __half2* p0 = (__half2*)&g_maskh[base0];
            float2 mv = __half22float2(*p0);
            mv.x *= silu_f(acc2[ms][nt][0] + b2s[c0]);
            mv.y *= silu_f(acc2[ms][nt][1] + b2s[c0+1]);
            *p0 = __float22half2_rn(mv);
            __half2* p1 = (__half2*)&g_maskh[base0 + 8*128];
            float2 mw = __half22float2(*p1);
            mw.x *= silu_f(acc2[ms][nt][2] + b2s[c0]);
            mw.y *= silu_f(acc2[ms][nt][3] + b2s[c0+1]);
            *p1 = __float22half2_rn(mw);
        }
    }
}

// ---------------- K7: readout ----------------
__global__ void k_out(const int* __restrict__ z, const float* __restrict__ Wo,
                      const float* __restrict__ bo, float* __restrict__ out){
    int b = blockIdx.x, h = threadIdx.x;
    __shared__ float red[4];
    float acc = 0.f;
    for (int i = 0; i < NN; i++)
        if (z[b*NN + i] != 0) acc += g_s[(b*NN + i)*HH + h];
    float part = acc * Wo[h];
    float tot = blkred128(part, red);
    if (h == 0) out[b] = tot + bo[0];
}

// ---------------- launch ----------------
extern "C" void kernel_launch(void* const* d_in, const int* in_sizes, int n_in,
                              void* d_out, int out_size){
    const int*   z      = (const int*)  d_in[0];
    const float* pos    = (const float*)d_in[1];
    const float* emb_w  = (const float*)d_in[2];
    const float* emb2_w = (const float*)d_in[3];
    const float* Wef    = (const float*)d_in[4];
    const float* bef    = (const float*)d_in[5];
    const float* Ws2v   = (const float*)d_in[6];
    const float* bs2v   = (const float*)d_in[7];
    const float* Wq     = (const float*)d_in[8];
    const float* Wk     = (const float*)d_in[9];
    const float* Wd1    = (const float*)d_in[10];
    const float* bd1    = (const float*)d_in[11];
    const float* Wd2    = (const float*)d_in[12];
    const float* bd2    = (const float*)d_in[13];
    const float* Wint   = (const float*)d_in[14];
    const float* bint   = (const float*)d_in[15];
    const float* Wo     = (const float*)d_in[16];
    const float* bo     = (const float*)d_in[17];
    float* out = (float*)d_out;

    cudaFuncSetAttribute(k_dir, cudaFuncAttributeMaxDynamicSharedMemorySize, SMEM_DIR_BYTES);

    k_whalf<<<384, 128>>>(Wd1, Wd2);
    k_geom <<<BB*NN, 256>>>(z, pos, Wef, bef);
    k_embed<<<BB*NN, 128>>>(z, emb_w, emb2_w);
    k_gather<<<BB*NN/4, 256>>>(0);               // s += mask @ sn
    k_lin  <<<BB*NN/8, 128>>>(Ws2v, bs2v, 0);    // t = silu(LN(s@Ws2v+b))
    k_v    <<<BB*NN/4, 256>>>();
    k_vqk  <<<BB*NN*3/8, 128>>>(Wq, Wk);
    k_p    <<<BB*NN, 256>>>(Wd1);
    k_dir  <<<BB*NN/2, 256, SMEM_DIR_BYTES>>>(bd1, bd2);
    for (int l = 0; l < 3; l++){
        k_lin   <<<BB*NN/8, 128>>>(Wint + l*HH*HH, bint + l*HH, 1);  // sl
        k_gather<<<BB*NN/4, 256>>>(1);                                // s += mask @ sl
    }
    k_out<<<BB, 128>>>(z, Wo, bo, out);
}

// round 12
// speedup vs baseline: 2.9720x; 1.1312x over previous
#include <cuda_runtime.h>
#include <cuda_fp16.h>
#include <math.h>
#include <stdint.h>

#define BB 64
#define NN 64
#define HH 128
#define EFD 32
#define LN_EPS 1e-5f
#define CUT 10.0f

// ---------------- device scratch (no runtime allocation) ----------------
static __device__ __half g_maskh[BB*NN*NN*HH]; // 64 MB fp16 mask
static __device__ float g_ea  [BB*NN*NN];
static __device__ float g_ev  [BB*NN*NN*3];
static __device__ float g_s   [BB*NN*HH];
static __device__ float g_sn  [BB*NN*HH];
static __device__ float g_t   [BB*NN*HH];
static __device__ float g_v   [BB*NN*3*HH];
static __device__ float g_vq  [BB*NN*3*HH];
static __device__ float g_vk  [BB*NN*3*HH];
static __device__ float g_sl  [BB*NN*HH];
static __device__ float g_P   [BB*NN*3*256];   // P_i = V_i @ Wd1[0:128]
static __device__ unsigned gW1h3[256*64];      // Wd1 dir3 rows packed fp16 (x64)
static __device__ unsigned gW2h [128*128];

// ---- fast exp2 poly ----
__device__ __forceinline__ float exp2_poly(float f){
    float p = 1.3333558e-3f;
    p = fmaf(p, f, 9.6181291e-3f);
    p = fmaf(p, f, 5.5504109e-2f);
    p = fmaf(p, f, 2.4022651e-1f);
    p = fmaf(p, f, 6.9314718e-1f);
    p = fmaf(p, f, 1.0f);
    return p;
}
__device__ __forceinline__ float exp2n_f(float t){
    t = fmaxf(t, -126.0f);
    float fn = t + 12582912.0f;
    float n  = fn - 12582912.0f;
    float f  = t - n;
    int ni = __float_as_int(fn) - 0x4B400000;
    float scale = __int_as_float((ni + 127) << 23);
    return exp2_poly(f) * scale;
}
// silu: poly exp2 on FMA pipe + MUFU rcp (pipes overlap)
__device__ __forceinline__ float silu_f(float x){
    float t = x * (-1.442695041f);
    t = fminf(fmaxf(t, -126.0f), 126.0f);
    float fn = t + 12582912.0f;
    float n  = fn - 12582912.0f;
    float f  = t - n;
    int ni = __float_as_int(fn) - 0x4B400000;
    float scale = __int_as_float((ni + 127) << 23);
    float e = exp2_poly(f) * scale;   // e^{-x}
    float d = 1.0f + e;
    float y;
    asm("rcp.approx.f32 %0, %1;" : "=f"(y) : "f"(d));
    return x * y;
}

// ---- fp16 pack: {low16 = f16(f0), high16 = f16(f1)} ----
__device__ __forceinline__ unsigned half_pack(float f0, float f1){
    unsigned p;
    asm("cvt.rn.f16x2.f32 %0, %1, %2;" : "=r"(p) : "f"(f1), "f"(f0));
    return p;
}

// ---- mma.sync fp16 m16n8k16, fp32 accumulate ----
__device__ __forceinline__ void mma16h(float* c, const unsigned* a, unsigned b0, unsigned b1){
    asm("mma.sync.aligned.m16n8k16.row.col.f32.f16.f16.f32 "
        "{%0,%1,%2,%3},{%4,%5,%6,%7},{%8,%9},{%0,%1,%2,%3};"
        : "+f"(c[0]), "+f"(c[1]), "+f"(c[2]), "+f"(c[3])
        : "r"(a[0]), "r"(a[1]), "r"(a[2]), "r"(a[3]), "r"(b0), "r"(b1));
}

// block reduction for 128 threads (4 warps)
__device__ __forceinline__ float blkred128(float v, volatile float* red){
    #pragma unroll
    for (int o = 16; o > 0; o >>= 1) v += __shfl_xor_sync(0xffffffffu, v, o);
    if ((threadIdx.x & 31) == 0) red[threadIdx.x >> 5] = v;
    __syncthreads();
    v = red[0] + red[1] + red[2] + red[3];
    __syncthreads();
    return v;
}

// ---------------- K0: convert weights to packed fp16 ----------------
__global__ void k_whalf(const float* __restrict__ Wd1, const float* __restrict__ Wd2){
    int n = blockIdx.x, kp = threadIdx.x;
    if (n < 256){
        if (kp < 64){
            float f0 = Wd1[(128 + 2*kp    )*256 + n] * 64.0f;
            float f1 = Wd1[(128 + 2*kp + 1)*256 + n] * 64.0f;
            gW1h3[n*64 + kp] = half_pack(f0, f1);
        }
    } else {
        int n2 = n - 256;
        float f0 = Wd2[(2*kp  )*128 + n2];
        float f1 = Wd2[(2*kp+1)*128 + n2];
        gW2h[n2*128 + kp] = half_pack(f0, f1);
    }
}

// ---------------- K0b: P_i = V_i @ Wd1[0:128]  (3 x 256 per atom, fp32) ----------------
__global__ void k_p(const float* __restrict__ Wd1){
    int bi = blockIdx.x, n = threadIdx.x;
    __shared__ float vs[3*HH];
    for (int r = n; r < 3*HH; r += 256) vs[r] = g_v[bi*3*HH + r];
    __syncthreads();
    float p0 = 0.f, p1 = 0.f, p2 = 0.f;
    #pragma unroll 4
    for (int k = 0; k < HH; k++){
        float w = Wd1[k*256 + n];
        p0 = fmaf(vs[k],        w, p0);
        p1 = fmaf(vs[HH + k],   w, p1);
        p2 = fmaf(vs[2*HH + k], w, p2);
    }
    g_P[bi*768 + n]       = p0;
    g_P[bi*768 + 256 + n] = p1;
    g_P[bi*768 + 512 + n] = p2;
}

// ---------------- K1: geometry + RBF filter mask (256 threads) ----------------
__global__ void k_geom(const int* __restrict__ z, const float* __restrict__ pos,
                       const float* __restrict__ Wef, const float* __restrict__ bef){
    int blk = blockIdx.x;
    int b = blk >> 6, i = blk & 63;
    int t = threadIdx.x;               // 256

    __shared__ float pos_s[NN][3];
    __shared__ int   z_s[NN];
    __shared__ float d_s[NN], ea_s[NN];
    __shared__ float ef_s[NN][EFD];
    __shared__ float Wef_s[EFD*HH];
    __shared__ float bef_s[HH];

    for (int r = t; r < EFD*HH; r += 256) Wef_s[r] = Wef[r];
    if (t < HH) bef_s[t] = bef[t];
    if (t < NN){
        z_s[t] = z[b*NN + t];
        pos_s[t][0] = pos[(b*NN + t)*3 + 0];
        pos_s[t][1] = pos[(b*NN + t)*3 + 1];
        pos_s[t][2] = pos[(b*NN + t)*3 + 2];
    }
    __syncthreads();

    if (t < NN){
        int j = t;
        float dx = pos_s[j][0] - pos_s[i][0];
        float dy = pos_s[j][1] - pos_s[i][1];
        float dz = pos_s[j][2] - pos_s[i][2];
        float d2 = dx*dx + dy*dy + dz*dz;
        float d  = sqrtf(fmaxf(d2, 1e-12f));
        d_s[j] = d;
        bool pair = (z_s[i] != 0) && (z_s[j] != 0) && (j != i);
        float ea = (pair && d < CUT) ? 0.5f*(cosf(3.14159265358979323846f * d / CUT) + 1.0f) : 0.0f;
        ea_s[j] = ea;
        g_ea[blk*NN + j] = ea;
        float inv = 1.0f / d;
        g_ev[(blk*NN + j)*3 + 0] = pair ? dx*inv : 0.0f;
        g_ev[(blk*NN + j)*3 + 1] = pair ? dy*inv : 0.0f;
        g_ev[(blk*NN + j)*3 + 2] = pair ? dz*inv : 0.0f;
    }
    __syncthreads();

    const float step = CUT / (float)(EFD - 1);
    for (int r = t; r < NN*EFD; r += 256){
        int j = r >> 5, k = r & 31;
        float dd = d_s[j] - step*(float)k;
        ef_s[j][k] = exp2n_f(-14.4269504089f * dd * dd);
    }
    __syncthreads();

    int hp = t & 63, jh = t >> 6;
    int h0 = 2*hp;
    __half2* mrow = (__half2*)(g_maskh + (size_t)blk*NN*HH);
    for (int jj = 0; jj < 16; jj++){
        int j = jh*16 + jj;
        float a0 = bef_s[h0], a1 = bef_s[h0+1];
        #pragma unroll
        for (int k = 0; k < EFD; k++){
            float e = ef_s[j][k];
            a0 = fmaf(e, Wef_s[k*HH + h0],     a0);
            a1 = fmaf(e, Wef_s[k*HH + h0 + 1], a1);
        }
        float ea = ea_s[j];
        float2 m; m.x = silu_f(a0) * ea; m.y = silu_f(a1) * ea;
        mrow[j*64 + hp] = __float22half2_rn(m);
    }
}

// ---------------- K2a: s = emb[z];  sn = LN(emb2[z]) ----------------
__global__ void k_embed(const int* __restrict__ z, const float* __restrict__ emb_w,
                        const float* __restrict__ emb2_w){
    int a = blockIdx.x, h = threadIdx.x;
    __shared__ float red[4];
    int zi = z[a];
    g_s[a*HH + h] = emb_w[zi*HH + h];
    float x = emb2_w[zi*HH + h];
    float s1 = blkred128(x, red);
    float s2 = blkred128(x*x, red);
    float m = s1 * (1.0f/HH);
    float var = fmaxf(s2 * (1.0f/HH) - m*m, 0.0f);
    g_sn[a*HH + h] = (x - m) * rsqrtf(var + LN_EPS);
}

// ---------------- K2b / K6b: s += mask @ src (8 i-rows/block, half2 loads) ----------------
__global__ void k_gather(int sel){
    int blk = blockIdx.x;              // (b, i-group of 8)
    int b  = blk >> 3;
    int i0 = (blk & 7) * 8;
    int t  = threadIdx.x;              // 256
    int h2 = t & 63;
    int rg = t >> 6;                   // 0..3 -> rows rg*2, rg*2+1
    const float* src = sel ? g_sl : g_sn;
    __shared__ float srcs[NN*HH];
    const float* sb = src + b*NN*HH;
    for (int r = t; r < NN*HH; r += 256) srcs[r] = sb[r];
    __syncthreads();
    const __half2* m0 = (const __half2*)(g_maskh + (size_t)((b*NN + i0 + rg*2)*NN)*HH);
    float2 a0 = make_float2(0.f, 0.f), a1 = make_float2(0.f, 0.f);
    #pragma unroll 4
    for (int j = 0; j < NN; j++){
        float2 sv = *(const float2*)&srcs[j*HH + 2*h2];
        float2 q0 = __half22float2(m0[j*64 + h2]);
        float2 q1 = __half22float2(m0[4096 + j*64 + h2]);
        a0.x = fmaf(q0.x, sv.x, a0.x); a0.y = fmaf(q0.y, sv.y, a0.y);
        a1.x = fmaf(q1.x, sv.x, a1.x); a1.y = fmaf(q1.y, sv.y, a1.y);
    }
    int base = b*NN + i0 + rg*2;
    float2* sp0 = (float2*)&g_s[(base + 0)*HH + 2*h2];
    float2 s0 = *sp0; s0.x += a0.x; s0.y += a0.y; *sp0 = s0;
    float2* sp1 = (float2*)&g_s[(base + 1)*HH + 2*h2];
    float2 s1 = *sp1; s1.x += a1.x; s1.y += a1.y; *sp1 = s1;
}

// ---------------- K3 / K6a: dst = silu(LN(s @ W + bias)), 8 atoms per block ----------------
__global__ void k_lin(const float* __restrict__ W, const float* __restrict__ bias,
                      int dst_sel){
    int blk = blockIdx.x;
    int h = threadIdx.x;               // 128
    __shared__ float xs[8][HH];
    __shared__ float ys[8][HH];
    __shared__ float mm[8], rr[8];
    for (int r = h; r < 8*HH; r += 128) ((float*)xs)[r] = g_s[blk*8*HH + r];
    __syncthreads();
    float bh = bias[h];
    float acc[8];
    #pragma unroll
    for (int a = 0; a < 8; a++) acc[a] = bh;
    #pragma unroll 4
    for (int k = 0; k < HH; k++){
        float w = W[k*HH + h];
        #pragma unroll
        for (int a = 0; a < 8; a++) acc[a] = fmaf(xs[a][k], w, acc[a]);
    }
    #pragma unroll
    for (int a = 0; a < 8; a++) ys[a][h] = acc[a];
    __syncthreads();
    {
        int w = h >> 5, l = h & 31;
        #pragma unroll
        for (int aa = 0; aa < 2; aa++){
            int a = w + aa*4;
            float s1 = 0.f, s2 = 0.f;
            #pragma unroll
            for (int c = l; c < HH; c += 32){ float v = ys[a][c]; s1 += v; s2 += v*v; }
            #pragma unroll
            for (int o = 16; o > 0; o >>= 1){
                s1 += __shfl_xor_sync(0xffffffffu, s1, o);
                s2 += __shfl_xor_sync(0xffffffffu, s2, o);
            }
            if (l == 0){
                float m = s1 * (1.0f/HH);
                float var = fmaxf(s2 * (1.0f/HH) - m*m, 0.0f);
                mm[a] = m; rr[a] = rsqrtf(var + LN_EPS);
            }
        }
    }
    __syncthreads();
    float* dst = dst_sel ? g_sl : g_t;
    #pragma unroll
    for (int a = 0; a < 8; a++)
        dst[(blk*8 + a)*HH + h] = silu_f((ys[a][h] - mm[a]) * rr[a]);
}

// ---------------- K4a: v = sum_j mask*t*ev (4 i-rows/block, half2 loads) ----------------
__global__ void k_v(){
    int blk = blockIdx.x;
    int b  = blk >> 4;
    int i0 = (blk & 15) * 4;
    int t  = threadIdx.x;              // 256
    int h2 = t & 63;
    int rg = t >> 6;
    __shared__ float ts[NN*HH];
    __shared__ float evl[4][NN*3];
    const float* tb = g_t + b*NN*HH;
    for (int r = t; r < NN*HH; r += 256) ts[r] = tb[r];
    for (int r = t; r < 4*NN*3; r += 256) ((float*)evl)[r] = g_ev[(b*NN + i0)*NN*3 + r];
    __syncthreads();
    const __half2* m0 = (const __half2*)(g_maskh + (size_t)((b*NN + i0 + rg)*NN)*HH);
    float a00 = 0.f, a01 = 0.f, a10 = 0.f, a11 = 0.f, a20 = 0.f, a21 = 0.f;
    #pragma unroll 4
    for (int j = 0; j < NN; j++){
        float2 tv = *(const float2*)&ts[j*HH + 2*h2];
        float2 mq = __half22float2(m0[j*64 + h2]);
        float m0v = mq.x * tv.x, m1v = mq.y * tv.y;
        float e0 = evl[rg][j*3+0], e1 = evl[rg][j*3+1], e2 = evl[rg][j*3+2];
        a00 = fmaf(m0v, e0, a00); a01 = fmaf(m1v, e0, a01);
        a10 = fmaf(m0v, e1, a10); a11 = fmaf(m1v, e1, a11);
        a20 = fmaf(m0v, e2, a20); a21 = fmaf(m1v, e2, a21);
    }
    int base = (b*NN + i0 + rg)*3;
    *(float2*)&g_v[(base + 0)*HH + 2*h2] = make_float2(a00, a01);
    *(float2*)&g_v[(base + 1)*HH + 2*h2] = make_float2(a10, a11);
    *(float2*)&g_v[(base + 2)*HH + 2*h2] = make_float2(a20, a21);
}

// ---------------- K4b: vq = v@Wq, vk = v@Wk (8 rows per block) ----------------
__global__ void k_vqk(const float* __restrict__ Wq, const float* __restrict__ Wk){
    int blk = blockIdx.x;
    int h = threadIdx.x;
    __shared__ float vs[8][HH];
    for (int r = h; r < 8*HH; r += 128) ((float*)vs)[r] = g_v[blk*8*HH + r];
    __syncthreads();
    float aq[8], ak[8];
    #pragma unroll
    for (int r = 0; r < 8; r++){ aq[r] = 0.f; ak[r] = 0.f; }
    #pragma unroll 4
    for (int k = 0; k < HH; k++){
        float wq = Wq[k*HH + h];
        float wk = Wk[k*HH + h];
        #pragma unroll
        for (int r = 0; r < 8; r++){
            float v = vs[r][k];
            aq[r] = fmaf(v, wq, aq[r]);
            ak[r] = fmaf(v, wk, ak[r]);
        }
    }
    #pragma unroll
    for (int r = 0; r < 8; r++){
        g_vq[(blk*8 + r)*HH + h] = aq[r];
        g_vk[(blk*8 + r)*HH + h] = ak[r];
    }
}

// ---------------- K5: directional MLP (512 threads, 16 warps 4m x 4n) ----------------
// smem words: Ah 16896 | Bh 9216 | b1s 256 | b2s 128 = 26496 (105984 B)
#define SMEM_DIR_BYTES (26496*4)
__global__ void __launch_bounds__(512) k_dir(const float* __restrict__ bd1,
                                             const float* __restrict__ bd2){
    extern __shared__ unsigned smu[];
    unsigned* Ah = smu;                          // [e][kp], stride 132
    unsigned* Bh = smu + 16896;                  // staging [n][kp'], stride 36
    float* b1s = (float*)(smu + 26112);
    float* b2s = (float*)(smu + 26368);
    // pre-GEMM scratch overlaps Bh (dead before first staging store)
    float* eas = (float*)(Bh);                   // 128
    float* evs = (float*)(Bh + 128);             // 384
    float* vks = (float*)(Bh + 512);             // 768
    float* Ps  = (float*)(Bh + 1280);            // 1536

    int t = threadIdx.x, lane = t & 31, wid = t >> 5;
    int g = lane >> 2, tig = lane & 3;
    int bi0 = blockIdx.x * 2, bbase = bi0 & ~63;

    if (t < 256) b1s[t] = bd1[t];
    if (t < 128) b2s[t] = bd2[t];
    if (t < 128) eas[t] = g_ea[bi0*64 + t];
    for (int r = t; r < 384;  r += 512) evs[r] = g_ev[bi0*192 + r];
    for (int r = t; r < 768;  r += 512) vks[r] = g_vk[bi0*384 + r];
    for (int r = t; r < 1536; r += 512) Ps [r] = g_P [bi0*768 + r];
    __syncthreads();

    // build dir3 (scaled 1/64) -> Ah kp 0..63; 8 groups of (i, j-quarter)
    {
        int kp3 = t & 63, grp = t >> 6;          // grp 0..7
        int i  = grp & 1, jq = grp >> 1;         // jq 0..3: 16 j each
        int kk = 2*kp3;
        float u0 = vks[i*384 + kk],     u1 = vks[i*384 + 128 + kk], u2 = vks[i*384 + 256 + kk];
        float w0 = vks[i*384 + kk + 1], w1 = vks[i*384 + 129 + kk], w2 = vks[i*384 + 257 + kk];
        for (int jj = 0; jj < 16; jj++){
            int j = jq*16 + jj;
            int e = i*64 + j;
            float ea = eas[e] * 0.015625f;
            const float* vq = g_vq + (bbase + j)*384 + kk;
            float2 q0 = *(const float2*)vq;
            float2 q1 = *(const float2*)(vq + 128);
            float2 q2 = *(const float2*)(vq + 256);
            float f0 = (q0.x*u0 + q1.x*u1 + q2.x*u2) * ea;
            float f1 = (q0.y*w0 + q1.y*w1 + q2.y*w2) * ea;
            Ah[e*132 + kp3] = half_pack(f0, f1);
        }
    }

    int m0 = (wid & 3) * 32;                     // 4 m-groups x 32 rows
    int nh = wid >> 2;                           // 4 n-groups

    // init acc1 with dir2 low-rank contribution (GEMM1 cols nh*64 .. +63)
    float acc1[2][8][4];
    #pragma unroll
    for (int ms = 0; ms < 2; ms++){
        int ea_r = m0 + ms*16 + g;
        int eb_r = ea_r + 8;
        int ia = ea_r >> 6, ib = eb_r >> 6;
        float ca0 = evs[ea_r*3], ca1 = evs[ea_r*3+1], ca2 = evs[ea_r*3+2];
        float cb0 = evs[eb_r*3], cb1 = evs[eb_r*3+1], cb2 = evs[eb_r*3+2];
        float wa = eas[ea_r], wb = eas[eb_r];
        const float* Pa = Ps + ia*768;
        const float* Pb = Ps + ib*768;
        #pragma unroll
        for (int nt = 0; nt < 8; nt++){
            int c0 = nh*64 + nt*8 + 2*tig;
            acc1[ms][nt][0] = wa * (ca0*Pa[c0]   + ca1*Pa[256+c0]   + ca2*Pa[512+c0]);
            acc1[ms][nt][1] = wa * (ca0*Pa[c0+1] + ca1*Pa[256+c0+1] + ca2*Pa[512+c0+1]);
            acc1[ms][nt][2] = wb * (cb0*Pb[c0]   + cb1*Pb[256+c0]   + cb2*Pb[512+c0]);
            acc1[ms][nt][3] = wb * (cb0*Pb[c0+1] + cb1*Pb[256+c0+1] + cb2*Pb[512+c0+1]);
        }
    }

    // ===== GEMM1 (dir3 half): K=128, 2 chunks, single buffer + reg prefetch =====
    {
        uint4 pf[4];
        #pragma unroll
        for (int q = 0; q < 4; q++){
            int r = t + q*512;
            pf[q] = *(const uint4*)&gW1h3[(r>>3)*64 + (r&7)*4];
        }
        __syncthreads();                 // scratch reads (build + init acc1) done
        #pragma unroll
        for (int q = 0; q < 4; q++){
            int r = t + q*512;
            *(uint4*)&Bh[(r>>3)*36 + (r&7)*4] = pf[q];
        }
        __syncthreads();
        for (int c = 0; c < 2; c++){
            if (c == 0){
                #pragma unroll
                for (int q = 0; q < 4; q++){
                    int r = t + q*512;
                    pf[q] = *(const uint4*)&gW1h3[(r>>3)*64 + 32 + (r&7)*4];
                }
            }
            #pragma unroll
            for (int ksl = 0; ksl < 4; ksl++){
                int kp0 = c*32 + ksl*8;
                int kb  = ksl*8;
                unsigned ah[2][4];
                #pragma unroll
                for (int ms = 0; ms < 2; ms++){
                    int r0 = m0 + ms*16;
                    ah[ms][0] = Ah[(r0+g  )*132 + kp0 + tig];
                    ah[ms][1] = Ah[(r0+g+8)*132 + kp0 + tig];
                    ah[ms][2] = Ah[(r0+g  )*132 + kp0 + tig + 4];
                    ah[ms][3] = Ah[(r0+g+8)*132 + kp0 + tig + 4];
                }
                #pragma unroll
                for (int nt = 0; nt < 8; nt++){
                    int n0 = nh*64 + nt*8;
                    unsigned b0 = Bh[(n0+g)*36 + kb + tig];
                    unsigned b1 = Bh[(n0+g)*36 + kb + tig + 4];
                    mma16h(acc1[0][nt], ah[0], b0, b1);
                    mma16h(acc1[1][nt], ah[1], b0, b1);
                }
            }
            __syncthreads();
            if (c == 0){
                #pragma unroll
                for (int q = 0; q < 4; q++){
                    int r = t + q*512;
                    *(uint4*)&Bh[(r>>3)*36 + (r&7)*4] = pf[q];
                }
                __syncthreads();
            }
        }
    }

    // epilogue1: h1 = silu(D1 + b1) packed back into Ah (cols nh*64..+63)
    #pragma unroll
    for (int ms = 0; ms < 2; ms++){
        #pragma unroll
        for (int nt = 0; nt < 8; nt++){
            int c0 = nh*64 + nt*8 + 2*tig;
            int kph = c0 >> 1;
            int r0 = m0 + ms*16 + g;
            float y0 = silu_f(acc1[ms][nt][0] + b1s[c0]);
            float y1 = silu_f(acc1[ms][nt][1] + b1s[c0+1]);
            Ah[r0*132 + kph] = half_pack(y0, y1);
            float y2 = silu_f(acc1[ms][nt][2] + b1s[c0]);
            float y3 = silu_f(acc1[ms][nt][3] + b1s[c0+1]);
            Ah[(r0+8)*132 + kph] = half_pack(y2, y3);
        }
    }

    // ===== GEMM2: K=256, 4 chunks, single buffer + reg prefetch =====
    float acc2[2][4][4];
    #pragma unroll
    for (int ms = 0; ms < 2; ms++)
        #pragma unroll
        for (int nt = 0; nt < 4; nt++)
            #pragma unroll
            for (int q = 0; q < 4; q++) acc2[ms][nt][q] = 0.f;

    {
        uint4 pf[2];
        #pragma unroll
        for (int q = 0; q < 2; q++){
            int r = t + q*512;
            pf[q] = *(const uint4*)&gW2h[(r>>3)*128 + (r&7)*4];
        }
        __syncthreads();                 // epilogue1 Ah writes done; last GEMM1 Bh reads done
        #pragma unroll
        for (int q = 0; q < 2; q++){
            int r = t + q*512;
            *(uint4*)&Bh[(r>>3)*36 + (r&7)*4] = pf[q];
        }
        __syncthreads();
        for (int c = 0; c < 4; c++){
            if (c + 1 < 4){
                #pragma unroll
                for (int q = 0; q < 2; q++){
                    int r = t + q*512;
                    pf[q] = *(const uint4*)&gW2h[(r>>3)*128 + (c+1)*32 + (r&7)*4];
                }
            }
            #pragma unroll
            for (int ksl = 0; ksl < 4; ksl++){
                int kp0 = c*32 + ksl*8;
                int kb  = ksl*8;
                unsigned ah[2][4];
                #pragma unroll
                for (int ms = 0; ms < 2; ms++){
                    int r0 = m0 + ms*16;
                    ah[ms][0] = Ah[(r0+g  )*132 + kp0 + tig];
                    ah[ms][1] = Ah[(r0+g+8)*132 + kp0 + tig];
                    ah[ms][2] = Ah[(r0+g  )*132 + kp0 + tig + 4];
                    ah[ms][3] = Ah[(r0+g+8)*132 + kp0 + tig + 4];
                }
                #pragma unroll
                for (int nt = 0; nt < 4; nt++){
                    int n0 = nh*32 + nt*8;
                    unsigned b0 = Bh[(n0+g)*36 + kb + tig];
                    unsigned b1 = Bh[(n0+g)*36 + kb + tig + 4];
                    mma16h(acc2[0][nt], ah[0], b0, b1);
                    mma16h(acc2[1][nt], ah[1], b0, b1);
                }
            }
            __syncthreads();
            if (c + 1 < 4){
                #pragma unroll
                for (int q = 0; q < 2; q++){
                    int r = t + q*512;
                    *(uint4*)&Bh[(r>>3)*36 + (r&7)*4] = pf[q];
                }
                __syncthreads();
            }
        }
    }

    // epilogue2: maskh *= silu(D2 + b2)  (cols nh*32..+31)
    #pragma unroll
    for (int ms = 0; ms < 2; ms++){
        #pragma unroll
        for (int nt = 0; nt < 4; nt++){
            int c0 = nh*32 + nt*8 + 2*tig;
            int e0 = m0 + ms*16 + g;
            size_t base0 = ((size_t)(bi0*64 + e0))*128 + c0;
            __half2* p0 = (__half2*)&g_maskh[base0];
            float2 mv = __half22float2(*p0);
            mv.x *= silu_f(acc2[ms][nt][0] + b2s[c0]);
            mv.y *= silu_f(acc2[ms][nt][1] + b2s[c0+1]);
            *p0 = __float22half2_rn(mv);
            __half2* p1 = (__half2*)&g_maskh[base0 + 8*128];
            float2 mw = __half22float2(*p1);
            mw.x *= silu_f(acc2[ms][nt][2] + b2s[c0]);
            mw.y *= silu_f(acc2[ms][nt][3] + b2s[c0+1]);
            *p1 = __float22half2_rn(mw);
        }
    }
}

// ---------------- K7: readout ----------------
__global__ void k_out(const int* __restrict__ z, const float* __restrict__ Wo,
                      const float* __restrict__ bo, float* __restrict__ out){
    int b = blockIdx.x, h = threadIdx.x;
    __shared__ float red[4];
    float acc = 0.f;
    for (int i = 0; i < NN; i++)
        if (z[b*NN + i] != 0) acc += g_s[(b*NN + i)*HH + h];
    float part = acc * Wo[h];
    float tot = blkred128(part, red);
    if (h == 0) out[b] = tot + bo[0];
}

// ---------------- launch ----------------
extern "C" void kernel_launch(void* const* d_in, const int* in_sizes, int n_in,
                              void* d_out, int out_size){
    const int*   z      = (const int*)  d_in[0];
    const float* pos    = (const float*)d_in[1];
    const float* emb_w  = (const float*)d_in[2];
    const float* emb2_w = (const float*)d_in[3];
    const float* Wef    = (const float*)d_in[4];
    const float* bef    = (const float*)d_in[5];
    const float* Ws2v   = (const float*)d_in[6];
    const float* bs2v   = (const float*)d_in[7];
    const float* Wq     = (const float*)d_in[8];
    const float* Wk     = (const float*)d_in[9];
    const float* Wd1    = (const float*)d_in[10];
    const float* bd1    = (const float*)d_in[11];
    const float* Wd2    = (const float*)d_in[12];
    const float* bd2    = (const float*)d_in[13];
    const float* Wint   = (const float*)d_in[14];
    const float* bint   = (const float*)d_in[15];
    const float* Wo     = (const float*)d_in[16];
    const float* bo     = (const float*)d_in[17];
    float* out = (float*)d_out;

    cudaFuncSetAttribute(k_dir, cudaFuncAttributeMaxDynamicSharedMemorySize, SMEM_DIR_BYTES);

    k_whalf<<<384, 128>>>(Wd1, Wd2);
    k_geom <<<BB*NN, 256>>>(z, pos, Wef, bef);
    k_embed<<<BB*NN, 128>>>(z, emb_w, emb2_w);
    k_gather<<<BB*NN/8, 256>>>(0);               // s += mask @ sn
    k_lin  <<<BB*NN/8, 128>>>(Ws2v, bs2v, 0);    // t = silu(LN(s@Ws2v+b))
    k_v    <<<BB*NN/4, 256>>>();
    k_vqk  <<<BB*NN*3/8, 128>>>(Wq, Wk);
    k_p    <<<BB*NN, 256>>>(Wd1);
    k_dir  <<<BB*NN/2, 512, SMEM_DIR_BYTES>>>(bd1, bd2);
    for (int l = 0; l < 3; l++){
        k_lin   <<<BB*NN/8, 128>>>(Wint + l*HH*HH, bint + l*HH, 1);  // sl
        k_gather<<<BB*NN/8, 256>>>(1);                                // s += mask @ sl
    }
    k_out<<<BB, 128>>>(z, Wo, bo, out);
}